// round 1
// baseline (speedup 1.0000x reference)
#include <cuda_runtime.h>
#include <math.h>
#include <stdint.h>

// ---------------------------------------------------------------------------
// Problem constants
// ---------------------------------------------------------------------------
constexpr int cV  = 32000;
constexpr int cD  = 768;
constexpr int cH  = 12;
constexpr int cL  = 8;
constexpr int cT  = 1024;
constexpr int cB  = 4;
constexpr int cHD = cD / cH;          // 64
constexpr int cM  = cB * cT;          // 4096 rows
constexpr int cD3 = 3 * cD;           // 2304
constexpr int cDF = 4 * cD;           // 3072

// ---------------------------------------------------------------------------
// Scratch (device globals — no allocation allowed)
// ---------------------------------------------------------------------------
__device__ float g_x  [cM * cD];      // residual stream
__device__ float g_ln [cM * cD];      // layernorm output
__device__ float g_qkv[cM * cD3];     // fused qkv
__device__ float g_y  [cM * cD];      // attention output
__device__ float g_fc [cM * cDF];     // mlp hidden
__device__ float g_nll[cM];           // per-row nll

// ---------------------------------------------------------------------------
// Block reductions (blockDim.x == 256)
// ---------------------------------------------------------------------------
__device__ __forceinline__ float blockReduceSum(float v) {
    __shared__ float sh[8];
    #pragma unroll
    for (int o = 16; o; o >>= 1) v += __shfl_xor_sync(0xffffffffu, v, o);
    int w = threadIdx.x >> 5, l = threadIdx.x & 31;
    __syncthreads();                    // protect sh across repeated calls
    if (l == 0) sh[w] = v;
    __syncthreads();
    if (w == 0) {
        v = (l < 8) ? sh[l] : 0.0f;
        #pragma unroll
        for (int o = 16; o; o >>= 1) v += __shfl_xor_sync(0xffffffffu, v, o);
        if (l == 0) sh[0] = v;
    }
    __syncthreads();
    return sh[0];
}

__device__ __forceinline__ float blockReduceMax(float v) {
    __shared__ float sh[8];
    #pragma unroll
    for (int o = 16; o; o >>= 1) v = fmaxf(v, __shfl_xor_sync(0xffffffffu, v, o));
    int w = threadIdx.x >> 5, l = threadIdx.x & 31;
    __syncthreads();
    if (l == 0) sh[w] = v;
    __syncthreads();
    if (w == 0) {
        v = (l < 8) ? sh[l] : -INFINITY;
        #pragma unroll
        for (int o = 16; o; o >>= 1) v = fmaxf(v, __shfl_xor_sync(0xffffffffu, v, o));
        if (l == 0) sh[0] = v;
    }
    __syncthreads();
    return sh[0];
}

// ---------------------------------------------------------------------------
// Embedding: x = wte[idx] + wpe[t]
// ---------------------------------------------------------------------------
__global__ void embed_kernel(const int* __restrict__ idx,
                             const float* __restrict__ wte,
                             const float* __restrict__ wpe,
                             float* __restrict__ x) {
    int i = blockIdx.x * blockDim.x + threadIdx.x;  // over cM*cD
    int row = i / cD;
    int d   = i - row * cD;
    int t   = row & (cT - 1);
    int tok = idx[row];
    x[i] = wte[(size_t)tok * cD + d] + wpe[(size_t)t * cD + d];
}

// ---------------------------------------------------------------------------
// LayerNorm: one block (256 threads) per row; D = 768 = 3*256
// ---------------------------------------------------------------------------
__global__ void __launch_bounds__(256) ln_kernel(const float* __restrict__ x,
                                                 const float* __restrict__ g,
                                                 const float* __restrict__ b,
                                                 float* __restrict__ out) {
    const int row = blockIdx.x;
    const float* xr = x + (size_t)row * cD;
    const int t = threadIdx.x;
    float v0 = xr[t], v1 = xr[t + 256], v2 = xr[t + 512];
    float s  = blockReduceSum(v0 + v1 + v2);
    float s2 = blockReduceSum(v0 * v0 + v1 * v1 + v2 * v2);
    const float inv = 1.0f / cD;
    float mu  = s * inv;
    float var = s2 * inv - mu * mu;
    float rs  = rsqrtf(var + 1e-5f);
    float* orow = out + (size_t)row * cD;
    orow[t]       = (v0 - mu) * rs * g[t]       + b[t];
    orow[t + 256] = (v1 - mu) * rs * g[t + 256] + b[t + 256];
    orow[t + 512] = (v2 - mu) * rs * g[t + 512] + b[t + 512];
}

// ---------------------------------------------------------------------------
// SGEMM: C[M,N] = A[M,K] @ B[K,N] (+bias)(->gelu)(+residual)
// Tile 128x64x16, 256 threads, 8x4 microtile. All dims divide tiles exactly.
// ---------------------------------------------------------------------------
__device__ __forceinline__ float gelu_exact(float x) {
    return 0.5f * x * (1.0f + erff(x * 0.70710678118654752f));
}

template<bool BIAS, bool RES, bool GELU>
__global__ void __launch_bounds__(256) sgemm_kernel(
    const float* __restrict__ A, const float* __restrict__ Bw,
    const float* __restrict__ bias, const float* __restrict__ Rres,
    float* __restrict__ C, int N, int K) {

    __shared__ float As[16][128];
    __shared__ float Bs[16][64];

    const int tid = threadIdx.x;
    const int tx = tid & 15;       // col group (4 cols)
    const int ty = tid >> 4;       // row group (8 rows)
    const int m0 = blockIdx.y * 128;
    const int n0 = blockIdx.x * 64;

    const int ar = tid >> 1;       // 0..127 tile row for A load
    const int ac = (tid & 1) * 8;  // 0 or 8
    const int br = tid >> 4;       // 0..15  tile row for B load
    const int bc = (tid & 15) * 4; // 0..60

    float acc[8][4];
    #pragma unroll
    for (int i = 0; i < 8; i++)
        #pragma unroll
        for (int j = 0; j < 4; j++) acc[i][j] = 0.0f;

    const float* Aptr = A  + (size_t)(m0 + ar) * K + ac;
    const float* Bptr = Bw + (size_t)br * N + n0 + bc;

    for (int k0 = 0; k0 < K; k0 += 16) {
        float4 a0 = *(const float4*)(Aptr + k0);
        float4 a1 = *(const float4*)(Aptr + k0 + 4);
        float4 b4 = *(const float4*)(Bptr + (size_t)k0 * N);
        As[ac + 0][ar] = a0.x; As[ac + 1][ar] = a0.y;
        As[ac + 2][ar] = a0.z; As[ac + 3][ar] = a0.w;
        As[ac + 4][ar] = a1.x; As[ac + 5][ar] = a1.y;
        As[ac + 6][ar] = a1.z; As[ac + 7][ar] = a1.w;
        *(float4*)&Bs[br][bc] = b4;
        __syncthreads();
        #pragma unroll
        for (int kk = 0; kk < 16; kk++) {
            float a8[8], b4r[4];
            *(float4*)&a8[0] = *(const float4*)&As[kk][ty * 8];
            *(float4*)&a8[4] = *(const float4*)&As[kk][ty * 8 + 4];
            *(float4*)&b4r[0] = *(const float4*)&Bs[kk][tx * 4];
            #pragma unroll
            for (int i = 0; i < 8; i++)
                #pragma unroll
                for (int j = 0; j < 4; j++)
                    acc[i][j] = fmaf(a8[i], b4r[j], acc[i][j]);
        }
        __syncthreads();
    }

    float4 bv = make_float4(0.f, 0.f, 0.f, 0.f);
    if (BIAS) bv = *(const float4*)(bias + n0 + tx * 4);

    #pragma unroll
    for (int i = 0; i < 8; i++) {
        size_t off = (size_t)(m0 + ty * 8 + i) * N + n0 + tx * 4;
        float4 v = make_float4(acc[i][0], acc[i][1], acc[i][2], acc[i][3]);
        if (BIAS) { v.x += bv.x; v.y += bv.y; v.z += bv.z; v.w += bv.w; }
        if (GELU) {
            v.x = gelu_exact(v.x); v.y = gelu_exact(v.y);
            v.z = gelu_exact(v.z); v.w = gelu_exact(v.w);
        }
        if (RES) {
            float4 r = *(const float4*)(Rres + off);
            v.x += r.x; v.y += r.y; v.z += r.z; v.w += r.w;
        }
        *(float4*)(C + off) = v;
    }
}

// ---------------------------------------------------------------------------
// Fused causal attention, online softmax. One warp per (b,h,q).
// qkv layout: [B,T,3D], q at +h*64, k at +D+h*64, v at +2D+h*64.
// ---------------------------------------------------------------------------
__global__ void __launch_bounds__(128) attn_kernel(const float* __restrict__ qkv,
                                                   float* __restrict__ y) {
    const int b = blockIdx.z;
    const int h = blockIdx.y;
    const int q = blockIdx.x * 4 + (threadIdx.x >> 5);
    const int lane = threadIdx.x & 31;

    const size_t rowstride = (size_t)cD3;
    const float* qrow = qkv + ((size_t)(b * cT + q)) * rowstride + h * cHD;
    float2 qv = *(const float2*)(qrow + lane * 2);
    const float scale = 0.125f;  // 1/sqrt(64)
    qv.x *= scale; qv.y *= scale;

    float m = -INFINITY, lsum = 0.0f;
    float2 acc = make_float2(0.0f, 0.0f);

    const float* kbase = qkv + (size_t)b * cT * rowstride + cD  + h * cHD + lane * 2;
    const float* vbase = qkv + (size_t)b * cT * rowstride + 2*cD + h * cHD + lane * 2;

    for (int k = 0; k <= q; k++) {
        float2 kv = *(const float2*)(kbase + (size_t)k * rowstride);
        float s = qv.x * kv.x + qv.y * kv.y;
        #pragma unroll
        for (int o = 16; o; o >>= 1) s += __shfl_xor_sync(0xffffffffu, s, o);
        float newm = fmaxf(m, s);
        float corr = __expf(m - newm);     // exp(-inf)=0 on first iter
        float p    = __expf(s - newm);
        lsum = lsum * corr + p;
        float2 vv = *(const float2*)(vbase + (size_t)k * rowstride);
        acc.x = acc.x * corr + p * vv.x;
        acc.y = acc.y * corr + p * vv.y;
        m = newm;
    }
    float inv = 1.0f / lsum;
    float* orow = y + ((size_t)(b * cT + q)) * cD + h * cHD + lane * 2;
    orow[0] = acc.x * inv;
    orow[1] = acc.y * inv;
}

// ---------------------------------------------------------------------------
// Loss: per-row log-softmax NLL, then deterministic mean reduction
// ---------------------------------------------------------------------------
__global__ void __launch_bounds__(256) loss_row_kernel(const float* __restrict__ logits,
                                                       const int* __restrict__ tgt,
                                                       float* __restrict__ nll) {
    const int r = blockIdx.x;
    const float* lr = logits + (size_t)r * cV;
    float mx = -INFINITY;
    for (int i = threadIdx.x; i < cV; i += 256) mx = fmaxf(mx, lr[i]);
    mx = blockReduceMax(mx);
    float s = 0.0f;
    for (int i = threadIdx.x; i < cV; i += 256) s += __expf(lr[i] - mx);
    s = blockReduceSum(s);
    if (threadIdx.x == 0)
        nll[r] = -(lr[tgt[r]] - mx - logf(s));
}

__global__ void __launch_bounds__(256) loss_reduce_kernel(const float* __restrict__ nll,
                                                          float* __restrict__ out) {
    float s = 0.0f;
    for (int i = threadIdx.x; i < cM; i += 256) s += nll[i];
    s = blockReduceSum(s);
    if (threadIdx.x == 0) *out = s / (float)cM;
}

// ---------------------------------------------------------------------------
// Launch
// ---------------------------------------------------------------------------
extern "C" void kernel_launch(void* const* d_in, const int* in_sizes, int n_in,
                              void* d_out, int out_size) {
    const int*   idx    = (const int*)  d_in[0];
    const int*   tgt    = (const int*)  d_in[1];
    const float* wte    = (const float*)d_in[2];
    const float* wpe    = (const float*)d_in[3];
    const float* ln1_g  = (const float*)d_in[4];
    const float* ln1_b  = (const float*)d_in[5];
    const float* w_attn = (const float*)d_in[6];
    const float* w_proj = (const float*)d_in[7];
    const float* ln2_g  = (const float*)d_in[8];
    const float* ln2_b  = (const float*)d_in[9];
    const float* w_fc   = (const float*)d_in[10];
    const float* b_fc   = (const float*)d_in[11];
    const float* w_out  = (const float*)d_in[12];
    const float* b_out  = (const float*)d_in[13];
    const float* lnf_g  = (const float*)d_in[14];
    const float* lnf_b  = (const float*)d_in[15];
    const float* w_head = (const float*)d_in[16];
    float* logits = (float*)d_out;

    void *px, *pln, *pqkv, *py, *pfc, *pnll;
    cudaGetSymbolAddress(&px,   g_x);
    cudaGetSymbolAddress(&pln,  g_ln);
    cudaGetSymbolAddress(&pqkv, g_qkv);
    cudaGetSymbolAddress(&py,   g_y);
    cudaGetSymbolAddress(&pfc,  g_fc);
    cudaGetSymbolAddress(&pnll, g_nll);
    float* x   = (float*)px;
    float* ln  = (float*)pln;
    float* qkv = (float*)pqkv;
    float* y   = (float*)py;
    float* fc  = (float*)pfc;
    float* nll = (float*)pnll;

    embed_kernel<<<(cM * cD) / 256, 256>>>(idx, wte, wpe, x);

    for (int l = 0; l < cL; l++) {
        ln_kernel<<<cM, 256>>>(x, ln1_g + l * cD, ln1_b + l * cD, ln);
        sgemm_kernel<false, false, false><<<dim3(cD3 / 64, cM / 128), 256>>>(
            ln, w_attn + (size_t)l * cD * cD3, nullptr, nullptr, qkv, cD3, cD);
        attn_kernel<<<dim3(cT / 4, cH, cB), 128>>>(qkv, y);
        sgemm_kernel<false, true, false><<<dim3(cD / 64, cM / 128), 256>>>(
            y, w_proj + (size_t)l * cD * cD, nullptr, x, x, cD, cD);
        ln_kernel<<<cM, 256>>>(x, ln2_g + l * cD, ln2_b + l * cD, ln);
        sgemm_kernel<true, false, true><<<dim3(cDF / 64, cM / 128), 256>>>(
            ln, w_fc + (size_t)l * cD * cDF, b_fc + l * cDF, nullptr, fc, cDF, cD);
        sgemm_kernel<true, true, false><<<dim3(cD / 64, cM / 128), 256>>>(
            fc, w_out + (size_t)l * cDF * cD, b_out + l * cD, x, x, cD, cDF);
    }

    ln_kernel<<<cM, 256>>>(x, lnf_g, lnf_b, ln);
    sgemm_kernel<false, false, false><<<dim3(cV / 64, cM / 128), 256>>>(
        ln, w_head, nullptr, nullptr, logits, cV, cD);

    if (out_size >= cM * cV + 1) {
        loss_row_kernel<<<cM, 256>>>(logits, tgt, nll);
        loss_reduce_kernel<<<1, 256>>>(nll, logits + (size_t)cM * cV);
    }
}

// round 3
// speedup vs baseline: 1.0934x; 1.0934x over previous
#include <cuda_runtime.h>
#include <math.h>
#include <stdint.h>

// ---------------------------------------------------------------------------
// Problem constants
// ---------------------------------------------------------------------------
constexpr int cV  = 32000;
constexpr int cD  = 768;
constexpr int cH  = 12;
constexpr int cL  = 8;
constexpr int cT  = 1024;
constexpr int cB  = 4;
constexpr int cHD = cD / cH;          // 64
constexpr int cM  = cB * cT;          // 4096 rows
constexpr int cD3 = 3 * cD;           // 2304
constexpr int cDF = 4 * cD;           // 3072

// ---------------------------------------------------------------------------
// Scratch (device globals — no allocation allowed)
// ---------------------------------------------------------------------------
__device__ float g_x  [cM * cD];
__device__ float g_ln [cM * cD];
__device__ float g_qkv[cM * cD3];
__device__ float g_y  [cM * cD];
__device__ float g_fc [cM * cDF];
__device__ float g_nll[cM];

// ---------------------------------------------------------------------------
// mma.sync tf32 GEMM (sm_80+ path — works under compute_103 virtual target)
// Block tile 128x128x32, 256 threads, warp tile 32x64, cp.async double buffer.
// ---------------------------------------------------------------------------
__device__ __forceinline__ uint32_t cvt_tf32(float f) {
    uint32_t r;
    asm("cvt.rna.tf32.f32 %0, %1;" : "=r"(r) : "f"(f));
    return r;
}

__device__ __forceinline__ void mma_tf32(float* d, const uint32_t* a,
                                         uint32_t b0, uint32_t b1) {
    asm volatile(
        "mma.sync.aligned.m16n8k8.row.col.f32.tf32.tf32.f32 "
        "{%0,%1,%2,%3}, {%4,%5,%6,%7}, {%8,%9}, {%0,%1,%2,%3};"
        : "+f"(d[0]), "+f"(d[1]), "+f"(d[2]), "+f"(d[3])
        : "r"(a[0]), "r"(a[1]), "r"(a[2]), "r"(a[3]), "r"(b0), "r"(b1));
}

__device__ __forceinline__ void cp_async16(uint32_t saddr, const void* gptr) {
    asm volatile("cp.async.cg.shared.global [%0], [%1], 16;"
                 :: "r"(saddr), "l"(gptr));
}
#define CP_COMMIT() asm volatile("cp.async.commit_group;" ::: "memory")
#define CP_WAIT1()  asm volatile("cp.async.wait_group 1;" ::: "memory")

__device__ __forceinline__ float gelu_exact(float x) {
    return 0.5f * x * (1.0f + erff(x * 0.70710678118654752f));
}

// smem layout (floats): A stride 36, B stride 136 (both conflict-free + 16B aligned)
constexpr int SA = 36;                 // A row stride (floats)
constexpr int SB = 136;                // B row stride (floats)
constexpr int A_BUF = 128 * SA;        // 4608 floats
constexpr int B_BUF = 32 * SB;         // 4352 floats
constexpr int OFF_A0 = 0;
constexpr int OFF_A1 = A_BUF;
constexpr int OFF_B0 = 2 * A_BUF;
constexpr int OFF_B1 = 2 * A_BUF + B_BUF;
constexpr int GEMM_SMEM_BYTES = (2 * A_BUF + 2 * B_BUF) * 4;  // 71680

template<bool BIAS, bool RES, bool GELU>
__global__ void __launch_bounds__(256, 2) gemm_mma(
    const float* __restrict__ A, const float* __restrict__ W,
    const float* __restrict__ bias, const float* __restrict__ Rres,
    float* __restrict__ C, int N, int K) {

    extern __shared__ float sm[];
    const int tid  = threadIdx.x;
    const int lane = tid & 31;
    const int wid  = tid >> 5;
    const int gr   = lane >> 2;        // group id 0..7
    const int tg   = lane & 3;         // thread-in-group 0..3
    const int mw   = (wid & 3) * 32;   // warp m offset in tile
    const int nw   = (wid >> 2) * 64;  // warp n offset in tile
    const int m0   = blockIdx.y * 128;
    const int n0   = blockIdx.x * 128;

    float* As[2] = { sm + OFF_A0, sm + OFF_A1 };
    float* Bs[2] = { sm + OFF_B0, sm + OFF_B1 };
    uint32_t sbase = (uint32_t)__cvta_generic_to_shared(sm);
    uint32_t aS[2] = { sbase + OFF_A0 * 4, sbase + OFF_A1 * 4 };
    uint32_t bS[2] = { sbase + OFF_B0 * 4, sbase + OFF_B1 * 4 };

    float acc[2][8][4];
    #pragma unroll
    for (int mi = 0; mi < 2; mi++)
        #pragma unroll
        for (int nt = 0; nt < 8; nt++)
            #pragma unroll
            for (int q = 0; q < 4; q++) acc[mi][nt][q] = 0.0f;

    const int NK = K >> 5;

    // prefetch lambda-equivalent
    #define PREFETCH(ib, buf) do {                                              \
        const int _k0 = (ib) << 5;                                              \
        _Pragma("unroll")                                                       \
        for (int j = 0; j < 4; j++) {                                           \
            int c = tid + 256 * j;                                              \
            int row = c >> 3, kc = c & 7;                                       \
            cp_async16(aS[buf] + (uint32_t)(row * SA + kc * 4) * 4,             \
                       A + (size_t)(m0 + row) * K + _k0 + kc * 4);              \
        }                                                                       \
        _Pragma("unroll")                                                       \
        for (int j = 0; j < 4; j++) {                                           \
            int c = tid + 256 * j;                                              \
            int kr = c >> 5, nc = c & 31;                                       \
            cp_async16(bS[buf] + (uint32_t)(kr * SB + nc * 4) * 4,              \
                       W + (size_t)(_k0 + kr) * N + n0 + nc * 4);               \
        }                                                                       \
    } while (0)

    PREFETCH(0, 0);
    CP_COMMIT();
    if (NK > 1) PREFETCH(1, 1);
    CP_COMMIT();

    for (int ib = 0; ib < NK; ib++) {
        const int buf = ib & 1;
        CP_WAIT1();
        __syncthreads();

        const float* Ab = As[buf];
        const float* Bb = Bs[buf];
        #pragma unroll
        for (int ks = 0; ks < 4; ks++) {
            const int k = ks * 8;
            uint32_t af[2][4];
            #pragma unroll
            for (int mi = 0; mi < 2; mi++) {
                const float* ap = Ab + (mw + mi * 16 + gr) * SA + k + tg;
                af[mi][0] = cvt_tf32(ap[0]);
                af[mi][1] = cvt_tf32(ap[8 * SA]);
                af[mi][2] = cvt_tf32(ap[4]);
                af[mi][3] = cvt_tf32(ap[8 * SA + 4]);
            }
            #pragma unroll
            for (int nt = 0; nt < 8; nt++) {
                const float* bp = Bb + (k + tg) * SB + nw + nt * 8 + gr;
                uint32_t b0 = cvt_tf32(bp[0]);
                uint32_t b1 = cvt_tf32(bp[4 * SB]);
                mma_tf32(acc[0][nt], af[0], b0, b1);
                mma_tf32(acc[1][nt], af[1], b0, b1);
            }
        }
        __syncthreads();
        if (ib + 2 < NK) PREFETCH(ib + 2, buf);
        CP_COMMIT();
    }
    #undef PREFETCH

    // epilogue
    #pragma unroll
    for (int mi = 0; mi < 2; mi++) {
        const int r0 = m0 + mw + mi * 16 + gr;
        #pragma unroll
        for (int nt = 0; nt < 8; nt++) {
            const int c0 = n0 + nw + nt * 8 + tg * 2;
            float2 v0 = make_float2(acc[mi][nt][0], acc[mi][nt][1]);
            float2 v1 = make_float2(acc[mi][nt][2], acc[mi][nt][3]);
            if (BIAS) {
                float2 bv = *(const float2*)(bias + c0);
                v0.x += bv.x; v0.y += bv.y;
                v1.x += bv.x; v1.y += bv.y;
            }
            if (GELU) {
                v0.x = gelu_exact(v0.x); v0.y = gelu_exact(v0.y);
                v1.x = gelu_exact(v1.x); v1.y = gelu_exact(v1.y);
            }
            if (RES) {
                float2 r0v = *(const float2*)(Rres + (size_t)r0 * N + c0);
                float2 r1v = *(const float2*)(Rres + (size_t)(r0 + 8) * N + c0);
                v0.x += r0v.x; v0.y += r0v.y;
                v1.x += r1v.x; v1.y += r1v.y;
            }
            *(float2*)(C + (size_t)r0 * N + c0)       = v0;
            *(float2*)(C + (size_t)(r0 + 8) * N + c0) = v1;
        }
    }
}

// ---------------------------------------------------------------------------
// Block reductions (blockDim.x == 256)
// ---------------------------------------------------------------------------
__device__ __forceinline__ float blockReduceSum(float v) {
    __shared__ float sh[8];
    #pragma unroll
    for (int o = 16; o; o >>= 1) v += __shfl_xor_sync(0xffffffffu, v, o);
    int w = threadIdx.x >> 5, l = threadIdx.x & 31;
    __syncthreads();
    if (l == 0) sh[w] = v;
    __syncthreads();
    if (w == 0) {
        v = (l < 8) ? sh[l] : 0.0f;
        #pragma unroll
        for (int o = 16; o; o >>= 1) v += __shfl_xor_sync(0xffffffffu, v, o);
        if (l == 0) sh[0] = v;
    }
    __syncthreads();
    return sh[0];
}

__device__ __forceinline__ float blockReduceMax(float v) {
    __shared__ float sh[8];
    #pragma unroll
    for (int o = 16; o; o >>= 1) v = fmaxf(v, __shfl_xor_sync(0xffffffffu, v, o));
    int w = threadIdx.x >> 5, l = threadIdx.x & 31;
    __syncthreads();
    if (l == 0) sh[w] = v;
    __syncthreads();
    if (w == 0) {
        v = (l < 8) ? sh[l] : -INFINITY;
        #pragma unroll
        for (int o = 16; o; o >>= 1) v = fmaxf(v, __shfl_xor_sync(0xffffffffu, v, o));
        if (l == 0) sh[0] = v;
    }
    __syncthreads();
    return sh[0];
}

// ---------------------------------------------------------------------------
// Embedding
// ---------------------------------------------------------------------------
__global__ void embed_kernel(const int* __restrict__ idx,
                             const float* __restrict__ wte,
                             const float* __restrict__ wpe,
                             float* __restrict__ x) {
    int i = blockIdx.x * blockDim.x + threadIdx.x;
    int row = i / cD;
    int d   = i - row * cD;
    int t   = row & (cT - 1);
    int tok = idx[row];
    x[i] = wte[(size_t)tok * cD + d] + wpe[(size_t)t * cD + d];
}

// ---------------------------------------------------------------------------
// LayerNorm
// ---------------------------------------------------------------------------
__global__ void __launch_bounds__(256) ln_kernel(const float* __restrict__ x,
                                                 const float* __restrict__ g,
                                                 const float* __restrict__ b,
                                                 float* __restrict__ out) {
    const int row = blockIdx.x;
    const float* xr = x + (size_t)row * cD;
    const int t = threadIdx.x;
    float v0 = xr[t], v1 = xr[t + 256], v2 = xr[t + 512];
    float s  = blockReduceSum(v0 + v1 + v2);
    float s2 = blockReduceSum(v0 * v0 + v1 * v1 + v2 * v2);
    const float inv = 1.0f / cD;
    float mu  = s * inv;
    float var = s2 * inv - mu * mu;
    float rs  = rsqrtf(var + 1e-5f);
    float* orow = out + (size_t)row * cD;
    orow[t]       = (v0 - mu) * rs * g[t]       + b[t];
    orow[t + 256] = (v1 - mu) * rs * g[t + 256] + b[t + 256];
    orow[t + 512] = (v2 - mu) * rs * g[t + 512] + b[t + 512];
}

// ---------------------------------------------------------------------------
// Fused causal attention (fp32, one warp per query)
// ---------------------------------------------------------------------------
__global__ void __launch_bounds__(128) attn_kernel(const float* __restrict__ qkv,
                                                   float* __restrict__ y) {
    const int b = blockIdx.z;
    const int h = blockIdx.y;
    const int q = blockIdx.x * 4 + (threadIdx.x >> 5);
    const int lane = threadIdx.x & 31;

    const size_t rowstride = (size_t)cD3;
    const float* qrow = qkv + ((size_t)(b * cT + q)) * rowstride + h * cHD;
    float2 qv = *(const float2*)(qrow + lane * 2);
    const float scale = 0.125f;
    qv.x *= scale; qv.y *= scale;

    float m = -INFINITY, lsum = 0.0f;
    float2 acc = make_float2(0.0f, 0.0f);

    const float* kbase = qkv + (size_t)b * cT * rowstride + cD   + h * cHD + lane * 2;
    const float* vbase = qkv + (size_t)b * cT * rowstride + 2*cD + h * cHD + lane * 2;

    for (int k = 0; k <= q; k++) {
        float2 kv = *(const float2*)(kbase + (size_t)k * rowstride);
        float s = qv.x * kv.x + qv.y * kv.y;
        #pragma unroll
        for (int o = 16; o; o >>= 1) s += __shfl_xor_sync(0xffffffffu, s, o);
        float newm = fmaxf(m, s);
        float corr = __expf(m - newm);
        float p    = __expf(s - newm);
        lsum = lsum * corr + p;
        float2 vv = *(const float2*)(vbase + (size_t)k * rowstride);
        acc.x = acc.x * corr + p * vv.x;
        acc.y = acc.y * corr + p * vv.y;
        m = newm;
    }
    float inv = 1.0f / lsum;
    float* orow = y + ((size_t)(b * cT + q)) * cD + h * cHD + lane * 2;
    orow[0] = acc.x * inv;
    orow[1] = acc.y * inv;
}

// ---------------------------------------------------------------------------
// Loss
// ---------------------------------------------------------------------------
__global__ void __launch_bounds__(256) loss_row_kernel(const float* __restrict__ logits,
                                                       const int* __restrict__ tgt,
                                                       float* __restrict__ nll) {
    const int r = blockIdx.x;
    const float* lr = logits + (size_t)r * cV;
    float mx = -INFINITY;
    for (int i = threadIdx.x; i < cV; i += 256) mx = fmaxf(mx, lr[i]);
    mx = blockReduceMax(mx);
    float s = 0.0f;
    for (int i = threadIdx.x; i < cV; i += 256) s += __expf(lr[i] - mx);
    s = blockReduceSum(s);
    if (threadIdx.x == 0)
        nll[r] = -(lr[tgt[r]] - mx - logf(s));
}

__global__ void __launch_bounds__(256) loss_reduce_kernel(const float* __restrict__ nll,
                                                          float* __restrict__ out) {
    float s = 0.0f;
    for (int i = threadIdx.x; i < cM; i += 256) s += nll[i];
    s = blockReduceSum(s);
    if (threadIdx.x == 0) *out = s / (float)cM;
}

// ---------------------------------------------------------------------------
// Launch
// ---------------------------------------------------------------------------
extern "C" void kernel_launch(void* const* d_in, const int* in_sizes, int n_in,
                              void* d_out, int out_size) {
    const int*   idx    = (const int*)  d_in[0];
    const int*   tgt    = (const int*)  d_in[1];
    const float* wte    = (const float*)d_in[2];
    const float* wpe    = (const float*)d_in[3];
    const float* ln1_g  = (const float*)d_in[4];
    const float* ln1_b  = (const float*)d_in[5];
    const float* w_attn = (const float*)d_in[6];
    const float* w_proj = (const float*)d_in[7];
    const float* ln2_g  = (const float*)d_in[8];
    const float* ln2_b  = (const float*)d_in[9];
    const float* w_fc   = (const float*)d_in[10];
    const float* b_fc   = (const float*)d_in[11];
    const float* w_out  = (const float*)d_in[12];
    const float* b_out  = (const float*)d_in[13];
    const float* lnf_g  = (const float*)d_in[14];
    const float* lnf_b  = (const float*)d_in[15];
    const float* w_head = (const float*)d_in[16];
    float* logits = (float*)d_out;

    void *px, *pln, *pqkv, *py, *pfc, *pnll;
    cudaGetSymbolAddress(&px,   g_x);
    cudaGetSymbolAddress(&pln,  g_ln);
    cudaGetSymbolAddress(&pqkv, g_qkv);
    cudaGetSymbolAddress(&py,   g_y);
    cudaGetSymbolAddress(&pfc,  g_fc);
    cudaGetSymbolAddress(&pnll, g_nll);
    float* x   = (float*)px;
    float* ln  = (float*)pln;
    float* qkv = (float*)pqkv;
    float* y   = (float*)py;
    float* fc  = (float*)pfc;
    float* nll = (float*)pnll;

    cudaFuncSetAttribute((const void*)gemm_mma<false, false, false>,
                         cudaFuncAttributeMaxDynamicSharedMemorySize, GEMM_SMEM_BYTES);
    cudaFuncSetAttribute((const void*)gemm_mma<false, true, false>,
                         cudaFuncAttributeMaxDynamicSharedMemorySize, GEMM_SMEM_BYTES);
    cudaFuncSetAttribute((const void*)gemm_mma<true, false, true>,
                         cudaFuncAttributeMaxDynamicSharedMemorySize, GEMM_SMEM_BYTES);
    cudaFuncSetAttribute((const void*)gemm_mma<true, true, false>,
                         cudaFuncAttributeMaxDynamicSharedMemorySize, GEMM_SMEM_BYTES);

    embed_kernel<<<(cM * cD) / 256, 256>>>(idx, wte, wpe, x);

    for (int l = 0; l < cL; l++) {
        ln_kernel<<<cM, 256>>>(x, ln1_g + l * cD, ln1_b + l * cD, ln);
        gemm_mma<false, false, false><<<dim3(cD3 / 128, cM / 128), 256, GEMM_SMEM_BYTES>>>(
            ln, w_attn + (size_t)l * cD * cD3, nullptr, nullptr, qkv, cD3, cD);
        attn_kernel<<<dim3(cT / 4, cH, cB), 128>>>(qkv, y);
        gemm_mma<false, true, false><<<dim3(cD / 128, cM / 128), 256, GEMM_SMEM_BYTES>>>(
            y, w_proj + (size_t)l * cD * cD, nullptr, x, x, cD, cD);
        ln_kernel<<<cM, 256>>>(x, ln2_g + l * cD, ln2_b + l * cD, ln);
        gemm_mma<true, false, true><<<dim3(cDF / 128, cM / 128), 256, GEMM_SMEM_BYTES>>>(
            ln, w_fc + (size_t)l * cD * cDF, b_fc + l * cDF, nullptr, fc, cDF, cD);
        gemm_mma<true, true, false><<<dim3(cD / 128, cM / 128), 256, GEMM_SMEM_BYTES>>>(
            fc, w_out + (size_t)l * cDF * cD, b_out + l * cD, x, x, cD, cDF);
    }

    ln_kernel<<<cM, 256>>>(x, lnf_g, lnf_b, ln);
    gemm_mma<false, false, false><<<dim3(cV / 128, cM / 128), 256, GEMM_SMEM_BYTES>>>(
        ln, w_head, nullptr, nullptr, logits, cV, cD);

    if (out_size >= cM * cV + 1) {
        loss_row_kernel<<<cM, 256>>>(logits, tgt, nll);
        loss_reduce_kernel<<<1, 256>>>(nll, logits + (size_t)cM * cV);
    }
}

// round 4
// speedup vs baseline: 1.6880x; 1.5438x over previous
#include <cuda_runtime.h>
#include <cuda_bf16.h>
#include <math.h>
#include <stdint.h>

// ---------------------------------------------------------------------------
// Problem constants
// ---------------------------------------------------------------------------
constexpr int cV  = 32000;
constexpr int cD  = 768;
constexpr int cH  = 12;
constexpr int cL  = 8;
constexpr int cT  = 1024;
constexpr int cB  = 4;
constexpr int cHD = cD / cH;          // 64
constexpr int cM  = cB * cT;          // 4096
constexpr int cD3 = 3 * cD;           // 2304
constexpr int cDF = 4 * cD;           // 3072

// ---------------------------------------------------------------------------
// Scratch (device globals — no allocation allowed)
// ---------------------------------------------------------------------------
__device__ float g_x  [cM * cD];      // residual stream (fp32)
__device__ float g_qkv[cM * cD3];     // qkv (fp32, for attention)
__device__ float g_nll[cM];

// bf16 hi/lo planes for GEMM operands
__device__ __nv_bfloat16 g_ln_h[cM * cD],  g_ln_l[cM * cD];
__device__ __nv_bfloat16 g_y_h [cM * cD],  g_y_l [cM * cD];
__device__ __nv_bfloat16 g_fc_h[cM * cDF], g_fc_l[cM * cDF];
__device__ __nv_bfloat16 g_wa_h[cL * cD * cD3], g_wa_l[cL * cD * cD3];
__device__ __nv_bfloat16 g_wp_h[cL * cD * cD],  g_wp_l[cL * cD * cD];
__device__ __nv_bfloat16 g_wf_h[cL * cD * cDF], g_wf_l[cL * cD * cDF];
__device__ __nv_bfloat16 g_wo_h[cL * cDF * cD], g_wo_l[cL * cDF * cD];
__device__ __nv_bfloat16 g_wh_h[cD * cV],       g_wh_l[cD * cV];

// ---------------------------------------------------------------------------
// PTX helpers
// ---------------------------------------------------------------------------
__device__ __forceinline__ void cp_async16(uint32_t saddr, const void* gptr) {
    asm volatile("cp.async.cg.shared.global [%0], [%1], 16;"
                 :: "r"(saddr), "l"(gptr));
}
#define CP_COMMIT() asm volatile("cp.async.commit_group;" ::: "memory")
#define CP_WAIT1()  asm volatile("cp.async.wait_group 1;" ::: "memory")

__device__ __forceinline__ void ldsm_x4(uint32_t* r, uint32_t addr) {
    asm volatile("ldmatrix.sync.aligned.m8n8.x4.shared.b16 {%0,%1,%2,%3}, [%4];"
        : "=r"(r[0]), "=r"(r[1]), "=r"(r[2]), "=r"(r[3]) : "r"(addr));
}
__device__ __forceinline__ void ldsm_x4_t(uint32_t* r, uint32_t addr) {
    asm volatile("ldmatrix.sync.aligned.m8n8.x4.trans.shared.b16 {%0,%1,%2,%3}, [%4];"
        : "=r"(r[0]), "=r"(r[1]), "=r"(r[2]), "=r"(r[3]) : "r"(addr));
}
__device__ __forceinline__ void mma_bf16(float* d, const uint32_t* a,
                                         uint32_t b0, uint32_t b1) {
    asm volatile(
        "mma.sync.aligned.m16n8k16.row.col.f32.bf16.bf16.f32 "
        "{%0,%1,%2,%3},{%4,%5,%6,%7},{%8,%9},{%0,%1,%2,%3};"
        : "+f"(d[0]), "+f"(d[1]), "+f"(d[2]), "+f"(d[3])
        : "r"(a[0]), "r"(a[1]), "r"(a[2]), "r"(a[3]), "r"(b0), "r"(b1));
}

// pack(lo_elem, hi_elem): u32 with lo in bits[0:16), hi in [16:32)
__device__ __forceinline__ uint32_t pack_bf16x2(float lo, float hi) {
    uint32_t d;
    asm("cvt.rn.bf16x2.f32 %0, %1, %2;" : "=r"(d) : "f"(hi), "f"(lo));
    return d;
}
// split two fp32 into hi-pair and lo-pair (bf16x2 each)
__device__ __forceinline__ void split2(float v0, float v1,
                                       uint32_t& hp, uint32_t& lp) {
    hp = pack_bf16x2(v0, v1);
    float h0 = __uint_as_float(hp << 16);
    float h1 = __uint_as_float(hp & 0xffff0000u);
    lp = pack_bf16x2(v0 - h0, v1 - h1);
}

__device__ __forceinline__ float gelu_exact(float x) {
    return 0.5f * x * (1.0f + erff(x * 0.70710678118654752f));
}

// ---------------------------------------------------------------------------
// Weight / activation splitter: fp32 -> bf16 hi + bf16 lo
// ---------------------------------------------------------------------------
__global__ void __launch_bounds__(256) split_kernel(const float* __restrict__ src,
                                                    __nv_bfloat16* __restrict__ hi,
                                                    __nv_bfloat16* __restrict__ lo,
                                                    int npairs) {
    int i = blockIdx.x * blockDim.x + threadIdx.x;
    if (i >= npairs) return;
    float2 v = *(const float2*)(src + (size_t)i * 2);
    uint32_t hp, lp;
    split2(v.x, v.y, hp, lp);
    ((uint32_t*)hi)[i] = hp;
    ((uint32_t*)lo)[i] = lp;
}

// ---------------------------------------------------------------------------
// split-bf16 GEMM: C[M,N] = A[M,K] @ W[K,N]  via AhWh + AhWl + AlWh
// Block tile 128x128x32, 8 warps (4x2), warp tile 32x64.
// smem: bf16 planes, A row stride 80B, B row stride 272B (LDSM conflict-free).
// ---------------------------------------------------------------------------
constexpr int SM_AH  = 0;
constexpr int SM_AL  = 10240;          // 128*80
constexpr int SM_BH  = 20480;
constexpr int SM_BL  = 29184;          // +32*272
constexpr int SM_BUF = 37888;
constexpr int GEMM_SMEM = 2 * SM_BUF;  // 75776

template<bool BIAS, bool RES, bool GELU, bool WC, bool WPL>
__global__ void __launch_bounds__(256, 2) gemm_bf3(
    const __nv_bfloat16* __restrict__ Ah, const __nv_bfloat16* __restrict__ Al,
    const __nv_bfloat16* __restrict__ Wh, const __nv_bfloat16* __restrict__ Wl,
    const float* __restrict__ bias, const float* __restrict__ Rres,
    float* __restrict__ C,
    __nv_bfloat16* __restrict__ Ch, __nv_bfloat16* __restrict__ Cl,
    int N, int K) {

    extern __shared__ char smem[];
    const uint32_t sb = (uint32_t)__cvta_generic_to_shared(smem);
    const int tid  = threadIdx.x;
    const int lane = tid & 31;
    const int wid  = tid >> 5;
    const int gr   = lane >> 2;
    const int tg   = lane & 3;
    const int mw   = (wid & 3) * 32;
    const int nw   = (wid >> 2) * 64;
    const int m0   = blockIdx.y * 128;
    const int n0   = blockIdx.x * 128;

    // ldmatrix lane addressing
    const int lr = lane & 7, lt = lane >> 3;
    const uint32_t aoff = (uint32_t)((mw + (lt & 1) * 8 + lr) * 80 + (lt >> 1) * 16);
    const uint32_t boff = (uint32_t)(((lt & 1) * 8 + lr) * 272 + (nw + (lt >> 1) * 8) * 2);

    float acc[2][8][4];
    #pragma unroll
    for (int mi = 0; mi < 2; mi++)
        #pragma unroll
        for (int nt = 0; nt < 8; nt++)
            #pragma unroll
            for (int q = 0; q < 4; q++) acc[mi][nt][q] = 0.0f;

    const int NK = K >> 5;

    #define PREFETCH(ib, buf) do {                                               \
        const int _k0 = (ib) << 5;                                               \
        const uint32_t _bb = sb + (buf) * SM_BUF;                                \
        _Pragma("unroll")                                                        \
        for (int j = 0; j < 2; j++) {                                            \
            int c = tid + 256 * j;                                               \
            int row = c >> 2, seg = c & 3;                                       \
            uint32_t d = _bb + SM_AH + (uint32_t)(row * 80 + seg * 16);          \
            size_t s = (size_t)(m0 + row) * K + _k0 + seg * 8;                   \
            cp_async16(d, Ah + s);                                               \
            cp_async16(d + (SM_AL - SM_AH), Al + s);                             \
        }                                                                        \
        _Pragma("unroll")                                                        \
        for (int j = 0; j < 2; j++) {                                            \
            int c = tid + 256 * j;                                               \
            int kr = c >> 4, seg = c & 15;                                       \
            uint32_t d = _bb + SM_BH + (uint32_t)(kr * 272 + seg * 16);          \
            size_t s = (size_t)(_k0 + kr) * N + n0 + seg * 8;                    \
            cp_async16(d, Wh + s);                                               \
            cp_async16(d + (SM_BL - SM_BH), Wl + s);                             \
        }                                                                        \
    } while (0)

    PREFETCH(0, 0);
    CP_COMMIT();
    PREFETCH(1, 1);
    CP_COMMIT();

    for (int ib = 0; ib < NK; ib++) {
        const int buf = ib & 1;
        CP_WAIT1();
        __syncthreads();

        const uint32_t base = sb + buf * SM_BUF;
        const uint32_t aHb = base + SM_AH + aoff;
        const uint32_t aLb = base + SM_AL + aoff;
        const uint32_t bHb = base + SM_BH + boff;
        const uint32_t bLb = base + SM_BL + boff;

        #pragma unroll
        for (int ks = 0; ks < 2; ks++) {
            uint32_t ahi[2][4], alo[2][4];
            ldsm_x4(ahi[0], aHb + ks * 32);
            ldsm_x4(ahi[1], aHb + 1280 + ks * 32);   // mi=1: +16 rows * 80B
            ldsm_x4(alo[0], aLb + ks * 32);
            ldsm_x4(alo[1], aLb + 1280 + ks * 32);
            #pragma unroll
            for (int g = 0; g < 4; g++) {
                uint32_t bh[4], bl[4];
                ldsm_x4_t(bh, bHb + ks * 4352 + g * 32);  // ks: +16 k-rows * 272B
                ldsm_x4_t(bl, bLb + ks * 4352 + g * 32);
                #pragma unroll
                for (int mi = 0; mi < 2; mi++) {
                    const int nt = g * 2;
                    mma_bf16(acc[mi][nt],     ahi[mi], bh[0], bh[1]);
                    mma_bf16(acc[mi][nt],     ahi[mi], bl[0], bl[1]);
                    mma_bf16(acc[mi][nt],     alo[mi], bh[0], bh[1]);
                    mma_bf16(acc[mi][nt + 1], ahi[mi], bh[2], bh[3]);
                    mma_bf16(acc[mi][nt + 1], ahi[mi], bl[2], bl[3]);
                    mma_bf16(acc[mi][nt + 1], alo[mi], bh[2], bh[3]);
                }
            }
        }
        __syncthreads();
        if (ib + 2 < NK) PREFETCH(ib + 2, buf);
        CP_COMMIT();
    }
    #undef PREFETCH

    // epilogue: acc[mi][nt] = {(r0,c0),(r0,c0+1),(r0+8,c0),(r0+8,c0+1)}
    #pragma unroll
    for (int mi = 0; mi < 2; mi++) {
        const int r0 = m0 + mw + mi * 16 + gr;
        #pragma unroll
        for (int nt = 0; nt < 8; nt++) {
            const int c0 = n0 + nw + nt * 8 + tg * 2;
            float2 v0 = make_float2(acc[mi][nt][0], acc[mi][nt][1]);
            float2 v1 = make_float2(acc[mi][nt][2], acc[mi][nt][3]);
            if (BIAS) {
                float2 bv = *(const float2*)(bias + c0);
                v0.x += bv.x; v0.y += bv.y;
                v1.x += bv.x; v1.y += bv.y;
            }
            if (GELU) {
                v0.x = gelu_exact(v0.x); v0.y = gelu_exact(v0.y);
                v1.x = gelu_exact(v1.x); v1.y = gelu_exact(v1.y);
            }
            if (RES) {
                float2 a0 = *(const float2*)(Rres + (size_t)r0 * N + c0);
                float2 a1 = *(const float2*)(Rres + (size_t)(r0 + 8) * N + c0);
                v0.x += a0.x; v0.y += a0.y;
                v1.x += a1.x; v1.y += a1.y;
            }
            if (WC) {
                *(float2*)(C + (size_t)r0 * N + c0)       = v0;
                *(float2*)(C + (size_t)(r0 + 8) * N + c0) = v1;
            }
            if (WPL) {
                uint32_t hp, lp;
                split2(v0.x, v0.y, hp, lp);
                ((uint32_t*)Ch)[((size_t)r0 * N + c0) >> 1] = hp;
                ((uint32_t*)Cl)[((size_t)r0 * N + c0) >> 1] = lp;
                split2(v1.x, v1.y, hp, lp);
                ((uint32_t*)Ch)[((size_t)(r0 + 8) * N + c0) >> 1] = hp;
                ((uint32_t*)Cl)[((size_t)(r0 + 8) * N + c0) >> 1] = lp;
            }
        }
    }
}

// ---------------------------------------------------------------------------
// Block reductions (blockDim.x == 256)
// ---------------------------------------------------------------------------
__device__ __forceinline__ float blockReduceSum(float v) {
    __shared__ float sh[8];
    #pragma unroll
    for (int o = 16; o; o >>= 1) v += __shfl_xor_sync(0xffffffffu, v, o);
    int w = threadIdx.x >> 5, l = threadIdx.x & 31;
    __syncthreads();
    if (l == 0) sh[w] = v;
    __syncthreads();
    if (w == 0) {
        v = (l < 8) ? sh[l] : 0.0f;
        #pragma unroll
        for (int o = 16; o; o >>= 1) v += __shfl_xor_sync(0xffffffffu, v, o);
        if (l == 0) sh[0] = v;
    }
    __syncthreads();
    return sh[0];
}

__device__ __forceinline__ float blockReduceMax(float v) {
    __shared__ float sh[8];
    #pragma unroll
    for (int o = 16; o; o >>= 1) v = fmaxf(v, __shfl_xor_sync(0xffffffffu, v, o));
    int w = threadIdx.x >> 5, l = threadIdx.x & 31;
    __syncthreads();
    if (l == 0) sh[w] = v;
    __syncthreads();
    if (w == 0) {
        v = (l < 8) ? sh[l] : -INFINITY;
        #pragma unroll
        for (int o = 16; o; o >>= 1) v = fmaxf(v, __shfl_xor_sync(0xffffffffu, v, o));
        if (l == 0) sh[0] = v;
    }
    __syncthreads();
    return sh[0];
}

// ---------------------------------------------------------------------------
// Embedding
// ---------------------------------------------------------------------------
__global__ void embed_kernel(const int* __restrict__ idx,
                             const float* __restrict__ wte,
                             const float* __restrict__ wpe,
                             float* __restrict__ x) {
    int i = blockIdx.x * blockDim.x + threadIdx.x;
    int row = i / cD;
    int d   = i - row * cD;
    int t   = row & (cT - 1);
    int tok = idx[row];
    x[i] = wte[(size_t)tok * cD + d] + wpe[(size_t)t * cD + d];
}

// ---------------------------------------------------------------------------
// LayerNorm -> bf16 hi/lo planes
// ---------------------------------------------------------------------------
__global__ void __launch_bounds__(256) ln_kernel(const float* __restrict__ x,
                                                 const float* __restrict__ g,
                                                 const float* __restrict__ b,
                                                 __nv_bfloat16* __restrict__ oh,
                                                 __nv_bfloat16* __restrict__ ol) {
    const int row = blockIdx.x;
    const float* xr = x + (size_t)row * cD;
    const int t = threadIdx.x;
    float v0 = xr[t], v1 = xr[t + 256], v2 = xr[t + 512];
    float s  = blockReduceSum(v0 + v1 + v2);
    float s2 = blockReduceSum(v0 * v0 + v1 * v1 + v2 * v2);
    const float inv = 1.0f / cD;
    float mu  = s * inv;
    float var = s2 * inv - mu * mu;
    float rs  = rsqrtf(var + 1e-5f);
    #pragma unroll
    for (int j = 0; j < 3; j++) {
        int d = t + j * 256;
        float val = (((j == 0) ? v0 : (j == 1) ? v1 : v2) - mu) * rs * g[d] + b[d];
        __nv_bfloat16 h = __float2bfloat16_rn(val);
        oh[(size_t)row * cD + d] = h;
        ol[(size_t)row * cD + d] = __float2bfloat16_rn(val - __bfloat162float(h));
    }
}

// ---------------------------------------------------------------------------
// Fused causal attention (fp32) -> y bf16 hi/lo planes
// ---------------------------------------------------------------------------
__global__ void __launch_bounds__(128) attn_kernel(const float* __restrict__ qkv,
                                                   __nv_bfloat16* __restrict__ yh,
                                                   __nv_bfloat16* __restrict__ yl) {
    const int b = blockIdx.z;
    const int h = blockIdx.y;
    const int q = blockIdx.x * 4 + (threadIdx.x >> 5);
    const int lane = threadIdx.x & 31;

    const size_t rowstride = (size_t)cD3;
    const float* qrow = qkv + ((size_t)(b * cT + q)) * rowstride + h * cHD;
    float2 qv = *(const float2*)(qrow + lane * 2);
    const float scale = 0.125f;
    qv.x *= scale; qv.y *= scale;

    float m = -INFINITY, lsum = 0.0f;
    float2 acc = make_float2(0.0f, 0.0f);

    const float* kbase = qkv + (size_t)b * cT * rowstride + cD   + h * cHD + lane * 2;
    const float* vbase = qkv + (size_t)b * cT * rowstride + 2*cD + h * cHD + lane * 2;

    for (int k = 0; k <= q; k++) {
        float2 kv = *(const float2*)(kbase + (size_t)k * rowstride);
        float s = qv.x * kv.x + qv.y * kv.y;
        #pragma unroll
        for (int o = 16; o; o >>= 1) s += __shfl_xor_sync(0xffffffffu, s, o);
        float newm = fmaxf(m, s);
        float corr = __expf(m - newm);
        float p    = __expf(s - newm);
        lsum = lsum * corr + p;
        float2 vv = *(const float2*)(vbase + (size_t)k * rowstride);
        acc.x = acc.x * corr + p * vv.x;
        acc.y = acc.y * corr + p * vv.y;
        m = newm;
    }
    float inv = 1.0f / lsum;
    float o0 = acc.x * inv, o1 = acc.y * inv;
    size_t oidx = ((size_t)(b * cT + q)) * cD + h * cHD + lane * 2;
    uint32_t hp, lp;
    split2(o0, o1, hp, lp);
    ((uint32_t*)yh)[oidx >> 1] = hp;
    ((uint32_t*)yl)[oidx >> 1] = lp;
}

// ---------------------------------------------------------------------------
// Loss
// ---------------------------------------------------------------------------
__global__ void __launch_bounds__(256) loss_row_kernel(const float* __restrict__ logits,
                                                       const int* __restrict__ tgt,
                                                       float* __restrict__ nll) {
    const int r = blockIdx.x;
    const float* lr = logits + (size_t)r * cV;
    float mx = -INFINITY;
    for (int i = threadIdx.x; i < cV; i += 256) mx = fmaxf(mx, lr[i]);
    mx = blockReduceMax(mx);
    float s = 0.0f;
    for (int i = threadIdx.x; i < cV; i += 256) s += __expf(lr[i] - mx);
    s = blockReduceSum(s);
    if (threadIdx.x == 0)
        nll[r] = -(lr[tgt[r]] - mx - logf(s));
}

__global__ void __launch_bounds__(256) loss_reduce_kernel(const float* __restrict__ nll,
                                                          float* __restrict__ out) {
    float s = 0.0f;
    for (int i = threadIdx.x; i < cM; i += 256) s += nll[i];
    s = blockReduceSum(s);
    if (threadIdx.x == 0) *out = s / (float)cM;
}

// ---------------------------------------------------------------------------
// Launch
// ---------------------------------------------------------------------------
template<typename T> static T* sym(const void* s) {
    void* p; cudaGetSymbolAddress(&p, s); return (T*)p;
}

extern "C" void kernel_launch(void* const* d_in, const int* in_sizes, int n_in,
                              void* d_out, int out_size) {
    const int*   idx    = (const int*)  d_in[0];
    const int*   tgt    = (const int*)  d_in[1];
    const float* wte    = (const float*)d_in[2];
    const float* wpe    = (const float*)d_in[3];
    const float* ln1_g  = (const float*)d_in[4];
    const float* ln1_b  = (const float*)d_in[5];
    const float* w_attn = (const float*)d_in[6];
    const float* w_proj = (const float*)d_in[7];
    const float* ln2_g  = (const float*)d_in[8];
    const float* ln2_b  = (const float*)d_in[9];
    const float* w_fc   = (const float*)d_in[10];
    const float* b_fc   = (const float*)d_in[11];
    const float* w_out  = (const float*)d_in[12];
    const float* b_out  = (const float*)d_in[13];
    const float* lnf_g  = (const float*)d_in[14];
    const float* lnf_b  = (const float*)d_in[15];
    const float* w_head = (const float*)d_in[16];
    float* logits = (float*)d_out;

    float* x   = sym<float>(g_x);
    float* qkv = sym<float>(g_qkv);
    float* nll = sym<float>(g_nll);
    __nv_bfloat16 *lnh = sym<__nv_bfloat16>(g_ln_h), *lnl = sym<__nv_bfloat16>(g_ln_l);
    __nv_bfloat16 *yh  = sym<__nv_bfloat16>(g_y_h),  *yl  = sym<__nv_bfloat16>(g_y_l);
    __nv_bfloat16 *fch = sym<__nv_bfloat16>(g_fc_h), *fcl = sym<__nv_bfloat16>(g_fc_l);
    __nv_bfloat16 *wah = sym<__nv_bfloat16>(g_wa_h), *wal = sym<__nv_bfloat16>(g_wa_l);
    __nv_bfloat16 *wph = sym<__nv_bfloat16>(g_wp_h), *wpl = sym<__nv_bfloat16>(g_wp_l);
    __nv_bfloat16 *wfh = sym<__nv_bfloat16>(g_wf_h), *wfl = sym<__nv_bfloat16>(g_wf_l);
    __nv_bfloat16 *woh = sym<__nv_bfloat16>(g_wo_h), *wol = sym<__nv_bfloat16>(g_wo_l);
    __nv_bfloat16 *whh = sym<__nv_bfloat16>(g_wh_h), *whl = sym<__nv_bfloat16>(g_wh_l);

    cudaFuncSetAttribute((const void*)gemm_bf3<false,false,false,true,false>,
                         cudaFuncAttributeMaxDynamicSharedMemorySize, GEMM_SMEM);
    cudaFuncSetAttribute((const void*)gemm_bf3<false,true,false,true,false>,
                         cudaFuncAttributeMaxDynamicSharedMemorySize, GEMM_SMEM);
    cudaFuncSetAttribute((const void*)gemm_bf3<true,false,true,false,true>,
                         cudaFuncAttributeMaxDynamicSharedMemorySize, GEMM_SMEM);
    cudaFuncSetAttribute((const void*)gemm_bf3<true,true,false,true,false>,
                         cudaFuncAttributeMaxDynamicSharedMemorySize, GEMM_SMEM);

    // split weights (each count is divisible by 512)
    split_kernel<<<cL * cD * cD3 / 512, 256>>>(w_attn, wah, wal, cL * cD * cD3 / 2);
    split_kernel<<<cL * cD * cD  / 512, 256>>>(w_proj, wph, wpl, cL * cD * cD  / 2);
    split_kernel<<<cL * cD * cDF / 512, 256>>>(w_fc,   wfh, wfl, cL * cD * cDF / 2);
    split_kernel<<<cL * cDF * cD / 512, 256>>>(w_out,  woh, wol, cL * cDF * cD / 2);
    split_kernel<<<cD * cV       / 512, 256>>>(w_head, whh, whl, cD * cV       / 2);

    embed_kernel<<<(cM * cD) / 256, 256>>>(idx, wte, wpe, x);

    for (int l = 0; l < cL; l++) {
        ln_kernel<<<cM, 256>>>(x, ln1_g + l * cD, ln1_b + l * cD, lnh, lnl);
        gemm_bf3<false,false,false,true,false><<<dim3(cD3/128, cM/128), 256, GEMM_SMEM>>>(
            lnh, lnl, wah + (size_t)l * cD * cD3, wal + (size_t)l * cD * cD3,
            nullptr, nullptr, qkv, nullptr, nullptr, cD3, cD);
        attn_kernel<<<dim3(cT / 4, cH, cB), 128>>>(qkv, yh, yl);
        gemm_bf3<false,true,false,true,false><<<dim3(cD/128, cM/128), 256, GEMM_SMEM>>>(
            yh, yl, wph + (size_t)l * cD * cD, wpl + (size_t)l * cD * cD,
            nullptr, x, x, nullptr, nullptr, cD, cD);
        ln_kernel<<<cM, 256>>>(x, ln2_g + l * cD, ln2_b + l * cD, lnh, lnl);
        gemm_bf3<true,false,true,false,true><<<dim3(cDF/128, cM/128), 256, GEMM_SMEM>>>(
            lnh, lnl, wfh + (size_t)l * cD * cDF, wfl + (size_t)l * cD * cDF,
            b_fc + l * cDF, nullptr, nullptr, fch, fcl, cDF, cD);
        gemm_bf3<true,true,false,true,false><<<dim3(cD/128, cM/128), 256, GEMM_SMEM>>>(
            fch, fcl, woh + (size_t)l * cDF * cD, wol + (size_t)l * cDF * cD,
            b_out + l * cD, x, x, nullptr, nullptr, cD, cDF);
    }

    ln_kernel<<<cM, 256>>>(x, lnf_g, lnf_b, lnh, lnl);
    gemm_bf3<false,false,false,true,false><<<dim3(cV/128, cM/128), 256, GEMM_SMEM>>>(
        lnh, lnl, whh, whl, nullptr, nullptr, logits, nullptr, nullptr, cV, cD);

    if (out_size >= cM * cV + 1) {
        loss_row_kernel<<<cM, 256>>>(logits, tgt, nll);
        loss_reduce_kernel<<<1, 256>>>(nll, logits + (size_t)cM * cV);
    }
}

// round 5
// speedup vs baseline: 2.9849x; 1.7684x over previous
#include <cuda_runtime.h>
#include <cuda_bf16.h>
#include <math.h>
#include <stdint.h>

// ---------------------------------------------------------------------------
// Problem constants
// ---------------------------------------------------------------------------
constexpr int cV  = 32000;
constexpr int cD  = 768;
constexpr int cH  = 12;
constexpr int cL  = 8;
constexpr int cT  = 1024;
constexpr int cB  = 4;
constexpr int cHD = cD / cH;          // 64
constexpr int cM  = cB * cT;          // 4096
constexpr int cD3 = 3 * cD;           // 2304
constexpr int cDF = 4 * cD;           // 3072
constexpr int cZ  = cB * cH;          // 48 batched heads
constexpr size_t cSH = (size_t)cT * cT;        // 1048576 per head
constexpr size_t cQH = (size_t)cT * cHD;       // 65536 per head

// ---------------------------------------------------------------------------
// Scratch (device globals — no allocation allowed)
// ---------------------------------------------------------------------------
__device__ float g_x  [cM * cD];
__device__ float g_qkv[cM * cD3];
__device__ float g_nll[cM];
__device__ float g_S  [cZ * cT * cT];           // attention scores (fp32)

__device__ __nv_bfloat16 g_ln_h[cM * cD],  g_ln_l[cM * cD];
__device__ __nv_bfloat16 g_y_h [cM * cD],  g_y_l [cM * cD];
__device__ __nv_bfloat16 g_fc_h[cM * cDF], g_fc_l[cM * cDF];
__device__ __nv_bfloat16 g_P_h [cZ * cT * cT], g_P_l [cZ * cT * cT];
__device__ __nv_bfloat16 g_q_h [cZ * cT * cHD], g_q_l [cZ * cT * cHD];
__device__ __nv_bfloat16 g_k_h [cZ * cT * cHD], g_k_l [cZ * cT * cHD];
__device__ __nv_bfloat16 g_v_h [cZ * cT * cHD], g_v_l [cZ * cT * cHD];
__device__ __nv_bfloat16 g_wa_h[cL * cD * cD3], g_wa_l[cL * cD * cD3];
__device__ __nv_bfloat16 g_wp_h[cL * cD * cD],  g_wp_l[cL * cD * cD];
__device__ __nv_bfloat16 g_wf_h[cL * cD * cDF], g_wf_l[cL * cD * cDF];
__device__ __nv_bfloat16 g_wo_h[cL * cDF * cD], g_wo_l[cL * cDF * cD];
__device__ __nv_bfloat16 g_wh_h[cD * cV],       g_wh_l[cD * cV];

// ---------------------------------------------------------------------------
// PTX helpers
// ---------------------------------------------------------------------------
__device__ __forceinline__ void cp_async16(uint32_t saddr, const void* gptr) {
    asm volatile("cp.async.cg.shared.global [%0], [%1], 16;"
                 :: "r"(saddr), "l"(gptr));
}
#define CP_COMMIT() asm volatile("cp.async.commit_group;" ::: "memory")
#define CP_WAIT1()  asm volatile("cp.async.wait_group 1;" ::: "memory")

__device__ __forceinline__ void ldsm_x4(uint32_t* r, uint32_t addr) {
    asm volatile("ldmatrix.sync.aligned.m8n8.x4.shared.b16 {%0,%1,%2,%3}, [%4];"
        : "=r"(r[0]), "=r"(r[1]), "=r"(r[2]), "=r"(r[3]) : "r"(addr));
}
__device__ __forceinline__ void ldsm_x4_t(uint32_t* r, uint32_t addr) {
    asm volatile("ldmatrix.sync.aligned.m8n8.x4.trans.shared.b16 {%0,%1,%2,%3}, [%4];"
        : "=r"(r[0]), "=r"(r[1]), "=r"(r[2]), "=r"(r[3]) : "r"(addr));
}
__device__ __forceinline__ void mma_bf16(float* d, const uint32_t* a,
                                         uint32_t b0, uint32_t b1) {
    asm volatile(
        "mma.sync.aligned.m16n8k16.row.col.f32.bf16.bf16.f32 "
        "{%0,%1,%2,%3},{%4,%5,%6,%7},{%8,%9},{%0,%1,%2,%3};"
        : "+f"(d[0]), "+f"(d[1]), "+f"(d[2]), "+f"(d[3])
        : "r"(a[0]), "r"(a[1]), "r"(a[2]), "r"(a[3]), "r"(b0), "r"(b1));
}

__device__ __forceinline__ uint32_t pack_bf16x2(float lo, float hi) {
    uint32_t d;
    asm("cvt.rn.bf16x2.f32 %0, %1, %2;" : "=r"(d) : "f"(hi), "f"(lo));
    return d;
}
__device__ __forceinline__ void split2(float v0, float v1,
                                       uint32_t& hp, uint32_t& lp) {
    hp = pack_bf16x2(v0, v1);
    float h0 = __uint_as_float(hp << 16);
    float h1 = __uint_as_float(hp & 0xffff0000u);
    lp = pack_bf16x2(v0 - h0, v1 - h1);
}

__device__ __forceinline__ float gelu_exact(float x) {
    return 0.5f * x * (1.0f + erff(x * 0.70710678118654752f));
}

// ---------------------------------------------------------------------------
// Generalized split-bf16 GEMM (3-mma Markidis): C = A @ W(op)
//   NT     : N block-tile (128 / 96 / 64); M tile fixed 128, K step 32
//   BTRANS : W stored [K][N] (row-major, trans ldsm)  — else W is [N][K]
//            (k-contiguous, non-trans ldsm; "NT gemm")
//   ZMODE  : 0 = C offset z*sC ; 1 = attention-y scatter map
//   CQK    : skip CTAs with n0 > m0 (causal upper triangle)
//   CPV    : truncate K loop at m0+128 (causal PV)
// ---------------------------------------------------------------------------
template<int NT, bool BTRANS>
struct Geom {
    static constexpr int SBb = BTRANS ? (2 * NT + 16) : 80;   // B row stride bytes
    static constexpr int BSZ = BTRANS ? 32 * SBb : NT * 80;   // B plane bytes
    static constexpr int AL  = 10240;                          // A lo plane offset
    static constexpr int BH  = 20480;
    static constexpr int BL  = BH + BSZ;
    static constexpr int BUF = BH + 2 * BSZ;
    static constexpr int SMEM = 2 * BUF;
};

template<int NT, bool BTRANS, bool BIAS, bool RES, bool GELU,
         bool WC, bool WPL, int ZMODE, bool CQK, bool CPV>
__global__ void __launch_bounds__(256, 2) gemm_u(
    const __nv_bfloat16* __restrict__ Ah, const __nv_bfloat16* __restrict__ Al,
    const __nv_bfloat16* __restrict__ Wh, const __nv_bfloat16* __restrict__ Wl,
    const float* __restrict__ bias, const float* __restrict__ Rres,
    float* __restrict__ C,
    __nv_bfloat16* __restrict__ Ch, __nv_bfloat16* __restrict__ Cl,
    int N, int K, int ldc, size_t sA, size_t sW, size_t sC) {

    using G = Geom<NT, BTRANS>;
    extern __shared__ char smem[];
    const uint32_t sb = (uint32_t)__cvta_generic_to_shared(smem);

    const int m0 = blockIdx.y * 128;
    const int n0 = blockIdx.x * NT;
    if (CQK && n0 > m0) return;

    const int z = blockIdx.z;
    Ah += z * sA; Al += z * sA;
    Wh += z * sW; Wl += z * sW;
    size_t cofs;
    if (ZMODE == 1) cofs = (size_t)(z / cH) * (cT * cD) + (size_t)(z % cH) * cHD;
    else            cofs = z * sC;

    const int tid  = threadIdx.x;
    const int lane = tid & 31;
    const int wid  = tid >> 5;
    const int gr   = lane >> 2;
    const int tg   = lane & 3;
    const int mw   = (wid & 3) * 32;
    const int nw   = (wid >> 2) * (NT / 2);
    const int lr   = lane & 7, lt = lane >> 3;

    const uint32_t aoff = (uint32_t)((mw + (lt & 1) * 8 + lr) * 80 + (lt >> 1) * 16);
    uint32_t boff;
    if (BTRANS) boff = (uint32_t)(((lt & 1) * 8 + lr) * G::SBb + (nw + (lt >> 1) * 8) * 2);
    else        boff = (uint32_t)((nw + (lt >> 1) * 8 + lr) * 80 + (lt & 1) * 16);

    constexpr int NTW = NT / 16;
    float acc[2][NTW][4];
    #pragma unroll
    for (int mi = 0; mi < 2; mi++)
        #pragma unroll
        for (int nt = 0; nt < NTW; nt++)
            #pragma unroll
            for (int q = 0; q < 4; q++) acc[mi][nt][q] = 0.0f;

    const int NK = CPV ? ((m0 + 128) >> 5) : (K >> 5);

    auto stage = [&](int ib, int buf) {
        const int k0 = ib << 5;
        const uint32_t bb = sb + buf * G::BUF;
        #pragma unroll
        for (int j = 0; j < 2; j++) {                 // A: 512 chunks
            int c = tid + 256 * j;
            int row = c >> 2, seg = c & 3;
            uint32_t d = bb + (uint32_t)(row * 80 + seg * 16);
            size_t s = (size_t)(m0 + row) * K + k0 + seg * 8;
            cp_async16(d, Ah + s);
            cp_async16(d + G::AL, Al + s);
        }
        if (BTRANS) {
            constexpr int SEGS = NT / 8;
            constexpr int BCH = 32 * SEGS;
            #pragma unroll
            for (int j = 0; j < (BCH + 255) / 256; j++) {
                int c = tid + 256 * j;
                if ((BCH % 256 == 0) || c < BCH) {
                    int kr = c / SEGS, seg = c - kr * SEGS;
                    uint32_t d = bb + G::BH + (uint32_t)(kr * G::SBb + seg * 16);
                    size_t s = (size_t)(k0 + kr) * N + n0 + seg * 8;
                    cp_async16(d, Wh + s);
                    cp_async16(d + G::BSZ, Wl + s);
                }
            }
        } else {
            constexpr int BCH = NT * 4;
            #pragma unroll
            for (int j = 0; j < (BCH + 255) / 256; j++) {
                int c = tid + 256 * j;
                if ((BCH % 256 == 0) || c < BCH) {
                    int row = c >> 2, seg = c & 3;
                    uint32_t d = bb + G::BH + (uint32_t)(row * 80 + seg * 16);
                    size_t s = (size_t)(n0 + row) * K + k0 + seg * 8;
                    cp_async16(d, Wh + s);
                    cp_async16(d + G::BSZ, Wl + s);
                }
            }
        }
    };

    stage(0, 0); CP_COMMIT();
    stage(1, 1); CP_COMMIT();

    for (int ib = 0; ib < NK; ib++) {
        const int buf = ib & 1;
        CP_WAIT1();
        __syncthreads();

        const uint32_t base = sb + buf * G::BUF;
        const uint32_t aHb = base + aoff;
        const uint32_t aLb = base + G::AL + aoff;
        const uint32_t bHb = base + G::BH + boff;
        const uint32_t bLb = base + G::BL + boff;

        #pragma unroll
        for (int ks = 0; ks < 2; ks++) {
            uint32_t ahi[2][4], alo[2][4];
            ldsm_x4(ahi[0], aHb + ks * 32);
            ldsm_x4(ahi[1], aHb + 1280 + ks * 32);
            ldsm_x4(alo[0], aLb + ks * 32);
            ldsm_x4(alo[1], aLb + 1280 + ks * 32);
            #pragma unroll
            for (int g = 0; g < NT / 32; g++) {
                uint32_t bh[4], bl[4];
                if (BTRANS) {
                    ldsm_x4_t(bh, bHb + ks * (16 * G::SBb) + g * 32);
                    ldsm_x4_t(bl, bLb + ks * (16 * G::SBb) + g * 32);
                } else {
                    ldsm_x4(bh, bHb + ks * 32 + g * 1280);
                    ldsm_x4(bl, bLb + ks * 32 + g * 1280);
                }
                #pragma unroll
                for (int mi = 0; mi < 2; mi++) {
                    const int nt = g * 2;
                    mma_bf16(acc[mi][nt],     ahi[mi], bh[0], bh[1]);
                    mma_bf16(acc[mi][nt],     ahi[mi], bl[0], bl[1]);
                    mma_bf16(acc[mi][nt],     alo[mi], bh[0], bh[1]);
                    mma_bf16(acc[mi][nt + 1], ahi[mi], bh[2], bh[3]);
                    mma_bf16(acc[mi][nt + 1], ahi[mi], bl[2], bl[3]);
                    mma_bf16(acc[mi][nt + 1], alo[mi], bh[2], bh[3]);
                }
            }
        }
        __syncthreads();
        if (ib + 2 < NK) stage(ib + 2, buf);
        CP_COMMIT();
    }

    // epilogue
    #pragma unroll
    for (int mi = 0; mi < 2; mi++) {
        const int r0 = m0 + mw + mi * 16 + gr;
        #pragma unroll
        for (int nt = 0; nt < NTW; nt++) {
            const int c0 = n0 + nw + nt * 8 + tg * 2;
            size_t o0 = cofs + (size_t)r0 * ldc + c0;
            size_t o1 = cofs + (size_t)(r0 + 8) * ldc + c0;
            float2 v0 = make_float2(acc[mi][nt][0], acc[mi][nt][1]);
            float2 v1 = make_float2(acc[mi][nt][2], acc[mi][nt][3]);
            if (BIAS) {
                float2 bv = *(const float2*)(bias + c0);
                v0.x += bv.x; v0.y += bv.y;
                v1.x += bv.x; v1.y += bv.y;
            }
            if (GELU) {
                v0.x = gelu_exact(v0.x); v0.y = gelu_exact(v0.y);
                v1.x = gelu_exact(v1.x); v1.y = gelu_exact(v1.y);
            }
            if (RES) {
                float2 a0 = *(const float2*)(Rres + o0);
                float2 a1 = *(const float2*)(Rres + o1);
                v0.x += a0.x; v0.y += a0.y;
                v1.x += a1.x; v1.y += a1.y;
            }
            if (WC) {
                *(float2*)(C + o0) = v0;
                *(float2*)(C + o1) = v1;
            }
            if (WPL) {
                uint32_t hp, lp;
                split2(v0.x, v0.y, hp, lp);
                ((uint32_t*)Ch)[o0 >> 1] = hp;
                ((uint32_t*)Cl)[o0 >> 1] = lp;
                split2(v1.x, v1.y, hp, lp);
                ((uint32_t*)Ch)[o1 >> 1] = hp;
                ((uint32_t*)Cl)[o1 >> 1] = lp;
            }
        }
    }
}

// ---------------------------------------------------------------------------
// Block reductions (blockDim.x == 256)
// ---------------------------------------------------------------------------
__device__ __forceinline__ float blockReduceSum(float v) {
    __shared__ float sh[8];
    #pragma unroll
    for (int o = 16; o; o >>= 1) v += __shfl_xor_sync(0xffffffffu, v, o);
    int w = threadIdx.x >> 5, l = threadIdx.x & 31;
    __syncthreads();
    if (l == 0) sh[w] = v;
    __syncthreads();
    if (w == 0) {
        v = (l < 8) ? sh[l] : 0.0f;
        #pragma unroll
        for (int o = 16; o; o >>= 1) v += __shfl_xor_sync(0xffffffffu, v, o);
        if (l == 0) sh[0] = v;
    }
    __syncthreads();
    return sh[0];
}

__device__ __forceinline__ float blockReduceMax(float v) {
    __shared__ float sh[8];
    #pragma unroll
    for (int o = 16; o; o >>= 1) v = fmaxf(v, __shfl_xor_sync(0xffffffffu, v, o));
    int w = threadIdx.x >> 5, l = threadIdx.x & 31;
    __syncthreads();
    if (l == 0) sh[w] = v;
    __syncthreads();
    if (w == 0) {
        v = (l < 8) ? sh[l] : -INFINITY;
        #pragma unroll
        for (int o = 16; o; o >>= 1) v = fmaxf(v, __shfl_xor_sync(0xffffffffu, v, o));
        if (l == 0) sh[0] = v;
    }
    __syncthreads();
    return sh[0];
}

// ---------------------------------------------------------------------------
// Small kernels
// ---------------------------------------------------------------------------
__global__ void __launch_bounds__(256) split_kernel(const float* __restrict__ src,
                                                    __nv_bfloat16* __restrict__ hi,
                                                    __nv_bfloat16* __restrict__ lo,
                                                    int npairs) {
    int i = blockIdx.x * blockDim.x + threadIdx.x;
    if (i >= npairs) return;
    float2 v = *(const float2*)(src + (size_t)i * 2);
    uint32_t hp, lp;
    split2(v.x, v.y, hp, lp);
    ((uint32_t*)hi)[i] = hp;
    ((uint32_t*)lo)[i] = lp;
}

__global__ void embed_kernel(const int* __restrict__ idx,
                             const float* __restrict__ wte,
                             const float* __restrict__ wpe,
                             float* __restrict__ x) {
    int i = blockIdx.x * blockDim.x + threadIdx.x;
    int row = i / cD;
    int d   = i - row * cD;
    int t   = row & (cT - 1);
    int tok = idx[row];
    x[i] = wte[(size_t)tok * cD + d] + wpe[(size_t)t * cD + d];
}

__global__ void __launch_bounds__(256) ln_kernel(const float* __restrict__ x,
                                                 const float* __restrict__ g,
                                                 const float* __restrict__ b,
                                                 __nv_bfloat16* __restrict__ oh,
                                                 __nv_bfloat16* __restrict__ ol) {
    const int row = blockIdx.x;
    const float* xr = x + (size_t)row * cD;
    const int t = threadIdx.x;
    float v0 = xr[t], v1 = xr[t + 256], v2 = xr[t + 512];
    float s  = blockReduceSum(v0 + v1 + v2);
    float s2 = blockReduceSum(v0 * v0 + v1 * v1 + v2 * v2);
    const float inv = 1.0f / cD;
    float mu  = s * inv;
    float var = s2 * inv - mu * mu;
    float rs  = rsqrtf(var + 1e-5f);
    #pragma unroll
    for (int j = 0; j < 3; j++) {
        int d = t + j * 256;
        float val = (((j == 0) ? v0 : (j == 1) ? v1 : v2) - mu) * rs * g[d] + b[d];
        __nv_bfloat16 h = __float2bfloat16_rn(val);
        oh[(size_t)row * cD + d] = h;
        ol[(size_t)row * cD + d] = __float2bfloat16_rn(val - __bfloat162float(h));
    }
}

// repack qkv fp32 [B,T,3D] -> per-head bf16 hi/lo planes [z][T][64]; q scaled
__global__ void __launch_bounds__(256) repack_qkv(
    const float* __restrict__ qkv,
    __nv_bfloat16* __restrict__ qh, __nv_bfloat16* __restrict__ ql,
    __nv_bfloat16* __restrict__ kh, __nv_bfloat16* __restrict__ kl,
    __nv_bfloat16* __restrict__ vh, __nv_bfloat16* __restrict__ vl) {
    int i = blockIdx.x * 256 + threadIdx.x;       // over cM*cD/2 pairs
    int row = i / 384;                            // b*T + t
    int r = i - row * 384;
    int h = r >> 5;
    int hp = r & 31;
    int b = row >> 10, t = row & 1023;
    const float* base = qkv + (size_t)row * cD3 + h * cHD + hp * 2;
    size_t o = ((size_t)(b * cH + h) * cT + t) * 32 + hp;   // u32 index
    float2 q = *(const float2*)(base);
    float2 k = *(const float2*)(base + cD);
    float2 v = *(const float2*)(base + 2 * cD);
    uint32_t hpk, lpk;
    split2(q.x * 0.125f, q.y * 0.125f, hpk, lpk);
    ((uint32_t*)qh)[o] = hpk; ((uint32_t*)ql)[o] = lpk;
    split2(k.x, k.y, hpk, lpk);
    ((uint32_t*)kh)[o] = hpk; ((uint32_t*)kl)[o] = lpk;
    split2(v.x, v.y, hpk, lpk);
    ((uint32_t*)vh)[o] = hpk; ((uint32_t*)vl)[o] = lpk;
}

// causal softmax over S rows -> P hi/lo planes (zero-filled to diag block edge)
__global__ void __launch_bounds__(256) softmax_kernel(
    const float* __restrict__ S,
    __nv_bfloat16* __restrict__ Ph, __nv_bfloat16* __restrict__ Pl) {
    const int q = blockIdx.x;
    const int z = blockIdx.y;
    const float* sr = S + (size_t)z * cSH + (size_t)q * cT;
    const int n = q + 1;
    const int t = threadIdx.x;
    float mx = -INFINITY;
    for (int i = t; i < n; i += 256) mx = fmaxf(mx, sr[i]);
    mx = blockReduceMax(mx);
    float s = 0.0f;
    for (int i = t; i < n; i += 256) s += __expf(sr[i] - mx);
    s = blockReduceSum(s);
    float inv = 1.0f / s;
    const int jmax = ((q >> 7) + 1) << 7;          // PV read extent
    size_t pbase = ((size_t)z * cSH + (size_t)q * cT) >> 1;
    for (int j = t; j * 2 < jmax; j += 256) {
        int col = j * 2;
        float p0 = (col     <= q) ? __expf(sr[col]     - mx) * inv : 0.0f;
        float p1 = (col + 1 <= q) ? __expf(sr[col + 1] - mx) * inv : 0.0f;
        uint32_t hp, lp;
        split2(p0, p1, hp, lp);
        ((uint32_t*)Ph)[pbase + j] = hp;
        ((uint32_t*)Pl)[pbase + j] = lp;
    }
}

__global__ void __launch_bounds__(256) loss_row_kernel(const float* __restrict__ logits,
                                                       const int* __restrict__ tgt,
                                                       float* __restrict__ nll) {
    const int r = blockIdx.x;
    const float* lr = logits + (size_t)r * cV;
    float mx = -INFINITY;
    for (int i = threadIdx.x; i < cV; i += 256) mx = fmaxf(mx, lr[i]);
    mx = blockReduceMax(mx);
    float s = 0.0f;
    for (int i = threadIdx.x; i < cV; i += 256) s += __expf(lr[i] - mx);
    s = blockReduceSum(s);
    if (threadIdx.x == 0)
        nll[r] = -(lr[tgt[r]] - mx - logf(s));
}

__global__ void __launch_bounds__(256) loss_reduce_kernel(const float* __restrict__ nll,
                                                          float* __restrict__ out) {
    float s = 0.0f;
    for (int i = threadIdx.x; i < cM; i += 256) s += nll[i];
    s = blockReduceSum(s);
    if (threadIdx.x == 0) *out = s / (float)cM;
}

// ---------------------------------------------------------------------------
// Launch
// ---------------------------------------------------------------------------
template<typename T> static T* sym(const void* s) {
    void* p; cudaGetSymbolAddress(&p, s); return (T*)p;
}

using bf16 = __nv_bfloat16;

// instantiation aliases
#define GQKV  gemm_u<128,true ,false,false,false,true ,false,0,false,false>
#define GQK   gemm_u<128,false,false,false,false,true ,false,0,true ,false>
#define GPV   gemm_u<64 ,true ,false,false,false,false,true ,1,false,true >
#define GPROJ gemm_u<96 ,true ,false,true ,false,true ,false,0,false,false>
#define GFC   gemm_u<128,true ,true ,false,true ,false,true ,0,false,false>
#define GOUT  gemm_u<96 ,true ,true ,true ,false,true ,false,0,false,false>

extern "C" void kernel_launch(void* const* d_in, const int* in_sizes, int n_in,
                              void* d_out, int out_size) {
    const int*   idx    = (const int*)  d_in[0];
    const int*   tgt    = (const int*)  d_in[1];
    const float* wte    = (const float*)d_in[2];
    const float* wpe    = (const float*)d_in[3];
    const float* ln1_g  = (const float*)d_in[4];
    const float* ln1_b  = (const float*)d_in[5];
    const float* w_attn = (const float*)d_in[6];
    const float* w_proj = (const float*)d_in[7];
    const float* ln2_g  = (const float*)d_in[8];
    const float* ln2_b  = (const float*)d_in[9];
    const float* w_fc   = (const float*)d_in[10];
    const float* b_fc   = (const float*)d_in[11];
    const float* w_out  = (const float*)d_in[12];
    const float* b_out  = (const float*)d_in[13];
    const float* lnf_g  = (const float*)d_in[14];
    const float* lnf_b  = (const float*)d_in[15];
    const float* w_head = (const float*)d_in[16];
    float* logits = (float*)d_out;

    float* x   = sym<float>(g_x);
    float* qkv = sym<float>(g_qkv);
    float* nll = sym<float>(g_nll);
    float* S   = sym<float>(g_S);
    bf16 *lnh = sym<bf16>(g_ln_h), *lnl = sym<bf16>(g_ln_l);
    bf16 *yh  = sym<bf16>(g_y_h),  *yl  = sym<bf16>(g_y_l);
    bf16 *fch = sym<bf16>(g_fc_h), *fcl = sym<bf16>(g_fc_l);
    bf16 *Ph  = sym<bf16>(g_P_h),  *Pl  = sym<bf16>(g_P_l);
    bf16 *qh  = sym<bf16>(g_q_h),  *ql  = sym<bf16>(g_q_l);
    bf16 *kh  = sym<bf16>(g_k_h),  *kl  = sym<bf16>(g_k_l);
    bf16 *vh  = sym<bf16>(g_v_h),  *vl  = sym<bf16>(g_v_l);
    bf16 *wah = sym<bf16>(g_wa_h), *wal = sym<bf16>(g_wa_l);
    bf16 *wph = sym<bf16>(g_wp_h), *wpl = sym<bf16>(g_wp_l);
    bf16 *wfh = sym<bf16>(g_wf_h), *wfl = sym<bf16>(g_wf_l);
    bf16 *woh = sym<bf16>(g_wo_h), *wol = sym<bf16>(g_wo_l);
    bf16 *whh = sym<bf16>(g_wh_h), *whl = sym<bf16>(g_wh_l);

    constexpr int SM128T = Geom<128, true >::SMEM;   // 75776
    constexpr int SM128N = Geom<128, false>::SMEM;   // 81920
    constexpr int SM96T  = Geom<96,  true >::SMEM;   // 67584
    constexpr int SM64T  = Geom<64,  true >::SMEM;   // 59392

    cudaFuncSetAttribute((const void*)GQKV,  cudaFuncAttributeMaxDynamicSharedMemorySize, SM128T);
    cudaFuncSetAttribute((const void*)GQK,   cudaFuncAttributeMaxDynamicSharedMemorySize, SM128N);
    cudaFuncSetAttribute((const void*)GPV,   cudaFuncAttributeMaxDynamicSharedMemorySize, SM64T);
    cudaFuncSetAttribute((const void*)GPROJ, cudaFuncAttributeMaxDynamicSharedMemorySize, SM96T);
    cudaFuncSetAttribute((const void*)GFC,   cudaFuncAttributeMaxDynamicSharedMemorySize, SM128T);
    cudaFuncSetAttribute((const void*)GOUT,  cudaFuncAttributeMaxDynamicSharedMemorySize, SM96T);

    // weight splits
    split_kernel<<<cL * cD * cD3 / 512, 256>>>(w_attn, wah, wal, cL * cD * cD3 / 2);
    split_kernel<<<cL * cD * cD  / 512, 256>>>(w_proj, wph, wpl, cL * cD * cD  / 2);
    split_kernel<<<cL * cD * cDF / 512, 256>>>(w_fc,   wfh, wfl, cL * cD * cDF / 2);
    split_kernel<<<cL * cDF * cD / 512, 256>>>(w_out,  woh, wol, cL * cDF * cD / 2);
    split_kernel<<<cD * cV       / 512, 256>>>(w_head, whh, whl, cD * cV       / 2);

    embed_kernel<<<(cM * cD) / 256, 256>>>(idx, wte, wpe, x);

    for (int l = 0; l < cL; l++) {
        ln_kernel<<<cM, 256>>>(x, ln1_g + l * cD, ln1_b + l * cD, lnh, lnl);
        GQKV<<<dim3(cD3 / 128, cM / 128, 1), 256, SM128T>>>(
            lnh, lnl, wah + (size_t)l * cD * cD3, wal + (size_t)l * cD * cD3,
            nullptr, nullptr, qkv, nullptr, nullptr, cD3, cD, cD3, 0, 0, 0);
        repack_qkv<<<cM * cD / 512, 256>>>(qkv, qh, ql, kh, kl, vh, vl);
        // S = Q K^T  (batched over 48 heads, causal block skip)
        GQK<<<dim3(cT / 128, cT / 128, cZ), 256, SM128N>>>(
            qh, ql, kh, kl, nullptr, nullptr, S, nullptr, nullptr,
            cT, cHD, cT, cQH, cQH, cSH);
        softmax_kernel<<<dim3(cT, cZ), 256>>>(S, Ph, Pl);
        // y = P V (batched, causal K truncation, scatter to [B,T,D] planes)
        GPV<<<dim3(1, cT / 128, cZ), 256, SM64T>>>(
            Ph, Pl, vh, vl, nullptr, nullptr, nullptr, yh, yl,
            cHD, cT, cD, cSH, cQH, 0);
        GPROJ<<<dim3(cD / 96, cM / 128, 1), 256, SM96T>>>(
            yh, yl, wph + (size_t)l * cD * cD, wpl + (size_t)l * cD * cD,
            nullptr, x, x, nullptr, nullptr, cD, cD, cD, 0, 0, 0);
        ln_kernel<<<cM, 256>>>(x, ln2_g + l * cD, ln2_b + l * cD, lnh, lnl);
        GFC<<<dim3(cDF / 128, cM / 128, 1), 256, SM128T>>>(
            lnh, lnl, wfh + (size_t)l * cD * cDF, wfl + (size_t)l * cD * cDF,
            b_fc + l * cDF, nullptr, nullptr, fch, fcl, cDF, cD, cDF, 0, 0, 0);
        GOUT<<<dim3(cD / 96, cM / 128, 1), 256, SM96T>>>(
            fch, fcl, woh + (size_t)l * cDF * cD, wol + (size_t)l * cDF * cD,
            b_out + l * cD, x, x, nullptr, nullptr, cD, cDF, cD, 0, 0, 0);
    }

    ln_kernel<<<cM, 256>>>(x, lnf_g, lnf_b, lnh, lnl);
    GQKV<<<dim3(cV / 128, cM / 128, 1), 256, SM128T>>>(
        lnh, lnl, whh, whl, nullptr, nullptr, logits, nullptr, nullptr,
        cV, cD, cV, 0, 0, 0);

    if (out_size >= cM * cV + 1) {
        loss_row_kernel<<<cM, 256>>>(logits, tgt, nll);
        loss_reduce_kernel<<<1, 256>>>(nll, logits + (size_t)cM * cV);
    }
}

// round 6
// speedup vs baseline: 3.4719x; 1.1632x over previous
#include <cuda_runtime.h>
#include <cuda_bf16.h>
#include <math.h>
#include <stdint.h>

// ---------------------------------------------------------------------------
// Problem constants
// ---------------------------------------------------------------------------
constexpr int cV  = 32000;
constexpr int cD  = 768;
constexpr int cH  = 12;
constexpr int cL  = 8;
constexpr int cT  = 1024;
constexpr int cB  = 4;
constexpr int cHD = cD / cH;          // 64
constexpr int cM  = cB * cT;          // 4096
constexpr int cD3 = 3 * cD;           // 2304
constexpr int cDF = 4 * cD;           // 3072
constexpr int cZ  = cB * cH;          // 48 heads
constexpr size_t cQH = (size_t)cT * cHD;       // 65536 per head

// ---------------------------------------------------------------------------
// Scratch (device globals — no allocation allowed)
// ---------------------------------------------------------------------------
__device__ float g_x  [cM * cD];
__device__ float g_qkv[cM * cD3];
__device__ float g_nll[cM];

__device__ __nv_bfloat16 g_ln_h[cM * cD],  g_ln_l[cM * cD];
__device__ __nv_bfloat16 g_y_h [cM * cD],  g_y_l [cM * cD];
__device__ __nv_bfloat16 g_fc_h[cM * cDF], g_fc_l[cM * cDF];
__device__ __nv_bfloat16 g_q_h [cZ * cT * cHD], g_q_l [cZ * cT * cHD];
__device__ __nv_bfloat16 g_k_h [cZ * cT * cHD], g_k_l [cZ * cT * cHD];
__device__ __nv_bfloat16 g_v_h [cZ * cT * cHD], g_v_l [cZ * cT * cHD];
__device__ __nv_bfloat16 g_wa_h[cL * cD * cD3], g_wa_l[cL * cD * cD3];
__device__ __nv_bfloat16 g_wp_h[cL * cD * cD],  g_wp_l[cL * cD * cD];
__device__ __nv_bfloat16 g_wf_h[cL * cD * cDF], g_wf_l[cL * cD * cDF];
__device__ __nv_bfloat16 g_wo_h[cL * cDF * cD], g_wo_l[cL * cDF * cD];
__device__ __nv_bfloat16 g_wh_h[cD * cV],       g_wh_l[cD * cV];

// ---------------------------------------------------------------------------
// PTX helpers
// ---------------------------------------------------------------------------
__device__ __forceinline__ void cp_async16(uint32_t saddr, const void* gptr) {
    asm volatile("cp.async.cg.shared.global [%0], [%1], 16;"
                 :: "r"(saddr), "l"(gptr));
}
#define CP_COMMIT() asm volatile("cp.async.commit_group;" ::: "memory")
#define CP_WAIT0()  asm volatile("cp.async.wait_group 0;" ::: "memory")
#define CP_WAIT1()  asm volatile("cp.async.wait_group 1;" ::: "memory")

__device__ __forceinline__ void ldsm_x4(uint32_t* r, uint32_t addr) {
    asm volatile("ldmatrix.sync.aligned.m8n8.x4.shared.b16 {%0,%1,%2,%3}, [%4];"
        : "=r"(r[0]), "=r"(r[1]), "=r"(r[2]), "=r"(r[3]) : "r"(addr));
}
__device__ __forceinline__ void ldsm_x4_t(uint32_t* r, uint32_t addr) {
    asm volatile("ldmatrix.sync.aligned.m8n8.x4.trans.shared.b16 {%0,%1,%2,%3}, [%4];"
        : "=r"(r[0]), "=r"(r[1]), "=r"(r[2]), "=r"(r[3]) : "r"(addr));
}
__device__ __forceinline__ void mma_bf16(float* d, const uint32_t* a,
                                         uint32_t b0, uint32_t b1) {
    asm volatile(
        "mma.sync.aligned.m16n8k16.row.col.f32.bf16.bf16.f32 "
        "{%0,%1,%2,%3},{%4,%5,%6,%7},{%8,%9},{%0,%1,%2,%3};"
        : "+f"(d[0]), "+f"(d[1]), "+f"(d[2]), "+f"(d[3])
        : "r"(a[0]), "r"(a[1]), "r"(a[2]), "r"(a[3]), "r"(b0), "r"(b1));
}

__device__ __forceinline__ uint32_t pack_bf16x2(float lo, float hi) {
    uint32_t d;
    asm("cvt.rn.bf16x2.f32 %0, %1, %2;" : "=r"(d) : "f"(hi), "f"(lo));
    return d;
}
__device__ __forceinline__ void split2(float v0, float v1,
                                       uint32_t& hp, uint32_t& lp) {
    hp = pack_bf16x2(v0, v1);
    float h0 = __uint_as_float(hp << 16);
    float h1 = __uint_as_float(hp & 0xffff0000u);
    lp = pack_bf16x2(v0 - h0, v1 - h1);
}

__device__ __forceinline__ float gelu_exact(float x) {
    return 0.5f * x * (1.0f + erff(x * 0.70710678118654752f));
}

// ---------------------------------------------------------------------------
// Generalized split-bf16 GEMM (3-mma Markidis): C = A @ W(op)
// ---------------------------------------------------------------------------
template<int NT, bool BTRANS>
struct Geom {
    static constexpr int SBb = BTRANS ? (2 * NT + 16) : 80;
    static constexpr int BSZ = BTRANS ? 32 * SBb : NT * 80;
    static constexpr int AL  = 10240;
    static constexpr int BH  = 20480;
    static constexpr int BL  = BH + BSZ;
    static constexpr int BUF = BH + 2 * BSZ;
    static constexpr int SMEM = 2 * BUF;
};

template<int NT, bool BTRANS, bool BIAS, bool RES, bool GELU,
         bool WC, bool WPL, int ZMODE, bool CQK, bool CPV>
__global__ void __launch_bounds__(256, 2) gemm_u(
    const __nv_bfloat16* __restrict__ Ah, const __nv_bfloat16* __restrict__ Al,
    const __nv_bfloat16* __restrict__ Wh, const __nv_bfloat16* __restrict__ Wl,
    const float* __restrict__ bias, const float* __restrict__ Rres,
    float* __restrict__ C,
    __nv_bfloat16* __restrict__ Ch, __nv_bfloat16* __restrict__ Cl,
    int N, int K, int ldc, size_t sA, size_t sW, size_t sC) {

    using G = Geom<NT, BTRANS>;
    extern __shared__ char smem[];
    const uint32_t sb = (uint32_t)__cvta_generic_to_shared(smem);

    const int m0 = blockIdx.y * 128;
    const int n0 = blockIdx.x * NT;
    if (CQK && n0 > m0) return;

    const int z = blockIdx.z;
    Ah += z * sA; Al += z * sA;
    Wh += z * sW; Wl += z * sW;
    size_t cofs;
    if (ZMODE == 1) cofs = (size_t)(z / cH) * (cT * cD) + (size_t)(z % cH) * cHD;
    else            cofs = z * sC;

    const int tid  = threadIdx.x;
    const int lane = tid & 31;
    const int wid  = tid >> 5;
    const int gr   = lane >> 2;
    const int tg   = lane & 3;
    const int mw   = (wid & 3) * 32;
    const int nw   = (wid >> 2) * (NT / 2);
    const int lr   = lane & 7, lt = lane >> 3;

    const uint32_t aoff = (uint32_t)((mw + (lt & 1) * 8 + lr) * 80 + (lt >> 1) * 16);
    uint32_t boff;
    if (BTRANS) boff = (uint32_t)(((lt & 1) * 8 + lr) * G::SBb + (nw + (lt >> 1) * 8) * 2);
    else        boff = (uint32_t)((nw + (lt >> 1) * 8 + lr) * 80 + (lt & 1) * 16);

    constexpr int NTW = NT / 16;
    float acc[2][NTW][4];
    #pragma unroll
    for (int mi = 0; mi < 2; mi++)
        #pragma unroll
        for (int nt = 0; nt < NTW; nt++)
            #pragma unroll
            for (int q = 0; q < 4; q++) acc[mi][nt][q] = 0.0f;

    const int NK = CPV ? ((m0 + 128) >> 5) : (K >> 5);

    auto stage = [&](int ib, int buf) {
        const int k0 = ib << 5;
        const uint32_t bb = sb + buf * G::BUF;
        #pragma unroll
        for (int j = 0; j < 2; j++) {
            int c = tid + 256 * j;
            int row = c >> 2, seg = c & 3;
            uint32_t d = bb + (uint32_t)(row * 80 + seg * 16);
            size_t s = (size_t)(m0 + row) * K + k0 + seg * 8;
            cp_async16(d, Ah + s);
            cp_async16(d + G::AL, Al + s);
        }
        if (BTRANS) {
            constexpr int SEGS = NT / 8;
            constexpr int BCH = 32 * SEGS;
            #pragma unroll
            for (int j = 0; j < (BCH + 255) / 256; j++) {
                int c = tid + 256 * j;
                if ((BCH % 256 == 0) || c < BCH) {
                    int kr = c / SEGS, seg = c - kr * SEGS;
                    uint32_t d = bb + G::BH + (uint32_t)(kr * G::SBb + seg * 16);
                    size_t s = (size_t)(k0 + kr) * N + n0 + seg * 8;
                    cp_async16(d, Wh + s);
                    cp_async16(d + G::BSZ, Wl + s);
                }
            }
        } else {
            constexpr int BCH = NT * 4;
            #pragma unroll
            for (int j = 0; j < (BCH + 255) / 256; j++) {
                int c = tid + 256 * j;
                if ((BCH % 256 == 0) || c < BCH) {
                    int row = c >> 2, seg = c & 3;
                    uint32_t d = bb + G::BH + (uint32_t)(row * 80 + seg * 16);
                    size_t s = (size_t)(n0 + row) * K + k0 + seg * 8;
                    cp_async16(d, Wh + s);
                    cp_async16(d + G::BSZ, Wl + s);
                }
            }
        }
    };

    stage(0, 0); CP_COMMIT();
    stage(1, 1); CP_COMMIT();

    for (int ib = 0; ib < NK; ib++) {
        const int buf = ib & 1;
        CP_WAIT1();
        __syncthreads();

        const uint32_t base = sb + buf * G::BUF;
        const uint32_t aHb = base + aoff;
        const uint32_t aLb = base + G::AL + aoff;
        const uint32_t bHb = base + G::BH + boff;
        const uint32_t bLb = base + G::BL + boff;

        #pragma unroll
        for (int ks = 0; ks < 2; ks++) {
            uint32_t ahi[2][4], alo[2][4];
            ldsm_x4(ahi[0], aHb + ks * 32);
            ldsm_x4(ahi[1], aHb + 1280 + ks * 32);
            ldsm_x4(alo[0], aLb + ks * 32);
            ldsm_x4(alo[1], aLb + 1280 + ks * 32);
            #pragma unroll
            for (int g = 0; g < NT / 32; g++) {
                uint32_t bh[4], bl[4];
                if (BTRANS) {
                    ldsm_x4_t(bh, bHb + ks * (16 * G::SBb) + g * 32);
                    ldsm_x4_t(bl, bLb + ks * (16 * G::SBb) + g * 32);
                } else {
                    ldsm_x4(bh, bHb + ks * 32 + g * 1280);
                    ldsm_x4(bl, bLb + ks * 32 + g * 1280);
                }
                #pragma unroll
                for (int mi = 0; mi < 2; mi++) {
                    const int nt = g * 2;
                    mma_bf16(acc[mi][nt],     ahi[mi], bh[0], bh[1]);
                    mma_bf16(acc[mi][nt],     ahi[mi], bl[0], bl[1]);
                    mma_bf16(acc[mi][nt],     alo[mi], bh[0], bh[1]);
                    mma_bf16(acc[mi][nt + 1], ahi[mi], bh[2], bh[3]);
                    mma_bf16(acc[mi][nt + 1], ahi[mi], bl[2], bl[3]);
                    mma_bf16(acc[mi][nt + 1], alo[mi], bh[2], bh[3]);
                }
            }
        }
        __syncthreads();
        if (ib + 2 < NK) stage(ib + 2, buf);
        CP_COMMIT();
    }

    #pragma unroll
    for (int mi = 0; mi < 2; mi++) {
        const int r0 = m0 + mw + mi * 16 + gr;
        #pragma unroll
        for (int nt = 0; nt < NTW; nt++) {
            const int c0 = n0 + nw + nt * 8 + tg * 2;
            size_t o0 = cofs + (size_t)r0 * ldc + c0;
            size_t o1 = cofs + (size_t)(r0 + 8) * ldc + c0;
            float2 v0 = make_float2(acc[mi][nt][0], acc[mi][nt][1]);
            float2 v1 = make_float2(acc[mi][nt][2], acc[mi][nt][3]);
            if (BIAS) {
                float2 bv = *(const float2*)(bias + c0);
                v0.x += bv.x; v0.y += bv.y;
                v1.x += bv.x; v1.y += bv.y;
            }
            if (GELU) {
                v0.x = gelu_exact(v0.x); v0.y = gelu_exact(v0.y);
                v1.x = gelu_exact(v1.x); v1.y = gelu_exact(v1.y);
            }
            if (RES) {
                float2 a0 = *(const float2*)(Rres + o0);
                float2 a1 = *(const float2*)(Rres + o1);
                v0.x += a0.x; v0.y += a0.y;
                v1.x += a1.x; v1.y += a1.y;
            }
            if (WC) {
                *(float2*)(C + o0) = v0;
                *(float2*)(C + o1) = v1;
            }
            if (WPL) {
                uint32_t hp, lp;
                split2(v0.x, v0.y, hp, lp);
                ((uint32_t*)Ch)[o0 >> 1] = hp;
                ((uint32_t*)Cl)[o0 >> 1] = lp;
                split2(v1.x, v1.y, hp, lp);
                ((uint32_t*)Ch)[o1 >> 1] = hp;
                ((uint32_t*)Cl)[o1 >> 1] = lp;
            }
        }
    }
}

// ---------------------------------------------------------------------------
// Fused flash attention (split-bf16 mma, online softmax)
// Grid (cT/128, cZ); 256 threads; warp w owns q-rows w*16..w*16+15.
// SMEM: Q(2 planes) + double-buffered K,V (2 planes each); row stride 144B.
// ---------------------------------------------------------------------------
constexpr int F_SQ   = 144;                 // row stride bytes
constexpr int F_PL   = 128 * F_SQ;          // one plane: 18432
constexpr int F_QH   = 0;
constexpr int F_QL   = F_PL;
constexpr int F_KV0  = 2 * F_PL;            // K h/l + V h/l buffer 0
constexpr int F_KVSZ = 4 * F_PL;            // 73728 per buffer
constexpr int FLASH_SMEM = 2 * F_PL + 2 * F_KVSZ;  // 184320

__global__ void __launch_bounds__(256, 1) flash_kernel(
    const __nv_bfloat16* __restrict__ qh, const __nv_bfloat16* __restrict__ ql,
    const __nv_bfloat16* __restrict__ kh, const __nv_bfloat16* __restrict__ kl,
    const __nv_bfloat16* __restrict__ vh, const __nv_bfloat16* __restrict__ vl,
    __nv_bfloat16* __restrict__ yh, __nv_bfloat16* __restrict__ yl) {

    extern __shared__ char smem[];
    const uint32_t sb = (uint32_t)__cvta_generic_to_shared(smem);
    const int qb = blockIdx.x;                // q block 0..7
    const int z  = blockIdx.y;
    const int q0 = qb * 128;
    const int tid  = threadIdx.x;
    const int lane = tid & 31;
    const int wid  = tid >> 5;
    const int gr   = lane >> 2;
    const int tg   = lane & 3;
    const int wq   = wid * 16;                // warp's q-row base (local)
    const int lr   = lane & 7, lt = lane >> 3;

    const __nv_bfloat16* qhz = qh + (size_t)z * cQH;
    const __nv_bfloat16* qlz = ql + (size_t)z * cQH;
    const __nv_bfloat16* khz = kh + (size_t)z * cQH;
    const __nv_bfloat16* klz = kl + (size_t)z * cQH;
    const __nv_bfloat16* vhz = vh + (size_t)z * cQH;
    const __nv_bfloat16* vlz = vl + (size_t)z * cQH;

    // stage Q (1024 chunks per plane, 4 per thread per plane)
    #pragma unroll
    for (int j = 0; j < 4; j++) {
        int c = tid + 256 * j;
        int row = c >> 3, seg = c & 7;
        uint32_t d = sb + (uint32_t)(row * F_SQ + seg * 16);
        size_t s = (size_t)(q0 + row) * cHD + seg * 8;
        cp_async16(d, qhz + s);
        cp_async16(d + F_PL, qlz + s);
    }
    auto stageKV = [&](int kb, int buf) {
        const uint32_t bb = sb + F_KV0 + buf * F_KVSZ;
        #pragma unroll
        for (int j = 0; j < 4; j++) {
            int c = tid + 256 * j;
            int row = c >> 3, seg = c & 7;
            uint32_t d = bb + (uint32_t)(row * F_SQ + seg * 16);
            size_t s = (size_t)(kb * 128 + row) * cHD + seg * 8;
            cp_async16(d, khz + s);
            cp_async16(d + F_PL, klz + s);
            cp_async16(d + 2 * F_PL, vhz + s);
            cp_async16(d + 3 * F_PL, vlz + s);
        }
    };

    stageKV(0, 0);
    CP_COMMIT();
    if (qb >= 1) { stageKV(1, 1); CP_COMMIT(); }

    // per-thread state: rows (wq+gr) and (wq+gr+8)
    float mrow[2] = { -INFINITY, -INFINITY };
    float lrow[2] = { 0.0f, 0.0f };
    float oacc[8][4];
    #pragma unroll
    for (int nt = 0; nt < 8; nt++)
        #pragma unroll
        for (int q = 0; q < 4; q++) oacc[nt][q] = 0.0f;

    uint32_t qfh[4][4], qfl[4][4];
    bool qloaded = false;

    const uint32_t q_aoff = (uint32_t)((wq + (lt & 1) * 8 + lr) * F_SQ + (lt >> 1) * 16);
    const uint32_t k_boff = (uint32_t)(((lt >> 1) * 8 + lr) * F_SQ + (lt & 1) * 16);
    const uint32_t v_boff = (uint32_t)(((lt & 1) * 8 + lr) * F_SQ + (lt >> 1) * 16);

    for (int kb = 0; kb <= qb; kb++) {
        if (kb < qb) { CP_WAIT1(); } else { CP_WAIT0(); }
        __syncthreads();

        if (!qloaded) {
            #pragma unroll
            for (int ks = 0; ks < 4; ks++) {
                ldsm_x4(qfh[ks], sb + q_aoff + ks * 32);
                ldsm_x4(qfl[ks], sb + F_PL + q_aoff + ks * 32);
            }
            qloaded = true;
        }

        const uint32_t kvb = sb + F_KV0 + (kb & 1) * F_KVSZ;

        // ---- S = Q K^T : 16 n-tiles of 8 kv each ----
        float s[16][4];
        #pragma unroll
        for (int nt = 0; nt < 16; nt++)
            #pragma unroll
            for (int q = 0; q < 4; q++) s[nt][q] = 0.0f;

        #pragma unroll
        for (int ks = 0; ks < 4; ks++) {
            #pragma unroll
            for (int g = 0; g < 8; g++) {
                uint32_t bh[4], bl[4];
                uint32_t addr = kvb + k_boff + (uint32_t)(g * 16 * F_SQ) + ks * 32;
                ldsm_x4(bh, addr);
                ldsm_x4(bl, addr + F_PL);
                const int nt = g * 2;
                mma_bf16(s[nt],     qfh[ks], bh[0], bh[1]);
                mma_bf16(s[nt],     qfh[ks], bl[0], bl[1]);
                mma_bf16(s[nt],     qfl[ks], bh[0], bh[1]);
                mma_bf16(s[nt + 1], qfh[ks], bh[2], bh[3]);
                mma_bf16(s[nt + 1], qfh[ks], bl[2], bl[3]);
                mma_bf16(s[nt + 1], qfl[ks], bh[2], bh[3]);
            }
        }

        // ---- causal mask on diagonal block ----
        if (kb == qb) {
            const int r0 = wq + gr, r1 = wq + gr + 8;
            #pragma unroll
            for (int nt = 0; nt < 16; nt++) {
                const int c0 = nt * 8 + tg * 2;
                if (c0     > r0) s[nt][0] = -1e30f;
                if (c0 + 1 > r0) s[nt][1] = -1e30f;
                if (c0     > r1) s[nt][2] = -1e30f;
                if (c0 + 1 > r1) s[nt][3] = -1e30f;
            }
        }

        // ---- online softmax ----
        float mn0 = -INFINITY, mn1 = -INFINITY;
        #pragma unroll
        for (int nt = 0; nt < 16; nt++) {
            mn0 = fmaxf(mn0, fmaxf(s[nt][0], s[nt][1]));
            mn1 = fmaxf(mn1, fmaxf(s[nt][2], s[nt][3]));
        }
        mn0 = fmaxf(mn0, __shfl_xor_sync(0xffffffffu, mn0, 1));
        mn0 = fmaxf(mn0, __shfl_xor_sync(0xffffffffu, mn0, 2));
        mn1 = fmaxf(mn1, __shfl_xor_sync(0xffffffffu, mn1, 1));
        mn1 = fmaxf(mn1, __shfl_xor_sync(0xffffffffu, mn1, 2));
        float mnew0 = fmaxf(mrow[0], mn0);
        float mnew1 = fmaxf(mrow[1], mn1);
        float al0 = __expf(mrow[0] - mnew0);
        float al1 = __expf(mrow[1] - mnew1);
        mrow[0] = mnew0; mrow[1] = mnew1;

        float rs0 = 0.0f, rs1 = 0.0f;
        #pragma unroll
        for (int nt = 0; nt < 16; nt++) {
            s[nt][0] = __expf(s[nt][0] - mnew0);
            s[nt][1] = __expf(s[nt][1] - mnew0);
            s[nt][2] = __expf(s[nt][2] - mnew1);
            s[nt][3] = __expf(s[nt][3] - mnew1);
            rs0 += s[nt][0] + s[nt][1];
            rs1 += s[nt][2] + s[nt][3];
        }
        rs0 += __shfl_xor_sync(0xffffffffu, rs0, 1);
        rs0 += __shfl_xor_sync(0xffffffffu, rs0, 2);
        rs1 += __shfl_xor_sync(0xffffffffu, rs1, 1);
        rs1 += __shfl_xor_sync(0xffffffffu, rs1, 2);
        lrow[0] = lrow[0] * al0 + rs0;
        lrow[1] = lrow[1] * al1 + rs1;

        #pragma unroll
        for (int nt = 0; nt < 8; nt++) {
            oacc[nt][0] *= al0; oacc[nt][1] *= al0;
            oacc[nt][2] *= al1; oacc[nt][3] *= al1;
        }

        // ---- O += P V ----
        #pragma unroll
        for (int ks = 0; ks < 8; ks++) {        // kv chunks of 16
            uint32_t pah[4], pal[4];
            uint32_t h0, l0;
            split2(s[2*ks][0],   s[2*ks][1],   h0, l0); pah[0] = h0; pal[0] = l0;
            split2(s[2*ks][2],   s[2*ks][3],   h0, l0); pah[1] = h0; pal[1] = l0;
            split2(s[2*ks+1][0], s[2*ks+1][1], h0, l0); pah[2] = h0; pal[2] = l0;
            split2(s[2*ks+1][2], s[2*ks+1][3], h0, l0); pah[3] = h0; pal[3] = l0;
            #pragma unroll
            for (int g = 0; g < 4; g++) {
                uint32_t bvh[4], bvl[4];
                uint32_t addr = kvb + 2 * F_PL + v_boff
                              + (uint32_t)(ks * 16 * F_SQ) + g * 32;
                ldsm_x4_t(bvh, addr);
                ldsm_x4_t(bvl, addr + F_PL);
                const int nt = g * 2;
                mma_bf16(oacc[nt],     pah, bvh[0], bvh[1]);
                mma_bf16(oacc[nt],     pah, bvl[0], bvl[1]);
                mma_bf16(oacc[nt],     pal, bvh[0], bvh[1]);
                mma_bf16(oacc[nt + 1], pah, bvh[2], bvh[3]);
                mma_bf16(oacc[nt + 1], pah, bvl[2], bvl[3]);
                mma_bf16(oacc[nt + 1], pal, bvh[2], bvh[3]);
            }
        }

        __syncthreads();
        if (kb + 2 <= qb) { stageKV(kb + 2, kb & 1); CP_COMMIT(); }
    }

    // ---- epilogue: normalize and scatter to y planes ----
    const float inv0 = 1.0f / lrow[0];
    const float inv1 = 1.0f / lrow[1];
    const int b = z / cH, h = z % cH;
    const int r0 = b * cT + q0 + wq + gr;
    #pragma unroll
    for (int nt = 0; nt < 8; nt++) {
        const int c0 = h * cHD + nt * 8 + tg * 2;
        uint32_t hp, lp;
        split2(oacc[nt][0] * inv0, oacc[nt][1] * inv0, hp, lp);
        size_t o0 = ((size_t)r0 * cD + c0) >> 1;
        ((uint32_t*)yh)[o0] = hp; ((uint32_t*)yl)[o0] = lp;
        split2(oacc[nt][2] * inv1, oacc[nt][3] * inv1, hp, lp);
        size_t o1 = ((size_t)(r0 + 8) * cD + c0) >> 1;
        ((uint32_t*)yh)[o1] = hp; ((uint32_t*)yl)[o1] = lp;
    }
}

// ---------------------------------------------------------------------------
// Block reductions (blockDim.x == 256)
// ---------------------------------------------------------------------------
__device__ __forceinline__ float blockReduceSum(float v) {
    __shared__ float sh[8];
    #pragma unroll
    for (int o = 16; o; o >>= 1) v += __shfl_xor_sync(0xffffffffu, v, o);
    int w = threadIdx.x >> 5, l = threadIdx.x & 31;
    __syncthreads();
    if (l == 0) sh[w] = v;
    __syncthreads();
    if (w == 0) {
        v = (l < 8) ? sh[l] : 0.0f;
        #pragma unroll
        for (int o = 16; o; o >>= 1) v += __shfl_xor_sync(0xffffffffu, v, o);
        if (l == 0) sh[0] = v;
    }
    __syncthreads();
    return sh[0];
}

__device__ __forceinline__ float blockReduceMax(float v) {
    __shared__ float sh[8];
    #pragma unroll
    for (int o = 16; o; o >>= 1) v = fmaxf(v, __shfl_xor_sync(0xffffffffu, v, o));
    int w = threadIdx.x >> 5, l = threadIdx.x & 31;
    __syncthreads();
    if (l == 0) sh[w] = v;
    __syncthreads();
    if (w == 0) {
        v = (l < 8) ? sh[l] : -INFINITY;
        #pragma unroll
        for (int o = 16; o; o >>= 1) v = fmaxf(v, __shfl_xor_sync(0xffffffffu, v, o));
        if (l == 0) sh[0] = v;
    }
    __syncthreads();
    return sh[0];
}

// ---------------------------------------------------------------------------
// Small kernels
// ---------------------------------------------------------------------------
__global__ void __launch_bounds__(256) split_kernel(const float* __restrict__ src,
                                                    __nv_bfloat16* __restrict__ hi,
                                                    __nv_bfloat16* __restrict__ lo,
                                                    int npairs) {
    int i = blockIdx.x * blockDim.x + threadIdx.x;
    if (i >= npairs) return;
    float2 v = *(const float2*)(src + (size_t)i * 2);
    uint32_t hp, lp;
    split2(v.x, v.y, hp, lp);
    ((uint32_t*)hi)[i] = hp;
    ((uint32_t*)lo)[i] = lp;
}

__global__ void embed_kernel(const int* __restrict__ idx,
                             const float* __restrict__ wte,
                             const float* __restrict__ wpe,
                             float* __restrict__ x) {
    int i = blockIdx.x * blockDim.x + threadIdx.x;
    int row = i / cD;
    int d   = i - row * cD;
    int t   = row & (cT - 1);
    int tok = idx[row];
    x[i] = wte[(size_t)tok * cD + d] + wpe[(size_t)t * cD + d];
}

__global__ void __launch_bounds__(256) ln_kernel(const float* __restrict__ x,
                                                 const float* __restrict__ g,
                                                 const float* __restrict__ b,
                                                 __nv_bfloat16* __restrict__ oh,
                                                 __nv_bfloat16* __restrict__ ol) {
    const int row = blockIdx.x;
    const float* xr = x + (size_t)row * cD;
    const int t = threadIdx.x;
    float v0 = xr[t], v1 = xr[t + 256], v2 = xr[t + 512];
    float s  = blockReduceSum(v0 + v1 + v2);
    float s2 = blockReduceSum(v0 * v0 + v1 * v1 + v2 * v2);
    const float inv = 1.0f / cD;
    float mu  = s * inv;
    float var = s2 * inv - mu * mu;
    float rs  = rsqrtf(var + 1e-5f);
    #pragma unroll
    for (int j = 0; j < 3; j++) {
        int d = t + j * 256;
        float val = (((j == 0) ? v0 : (j == 1) ? v1 : v2) - mu) * rs * g[d] + b[d];
        __nv_bfloat16 h = __float2bfloat16_rn(val);
        oh[(size_t)row * cD + d] = h;
        ol[(size_t)row * cD + d] = __float2bfloat16_rn(val - __bfloat162float(h));
    }
}

__global__ void __launch_bounds__(256) repack_qkv(
    const float* __restrict__ qkv,
    __nv_bfloat16* __restrict__ qh, __nv_bfloat16* __restrict__ ql,
    __nv_bfloat16* __restrict__ kh, __nv_bfloat16* __restrict__ kl,
    __nv_bfloat16* __restrict__ vh, __nv_bfloat16* __restrict__ vl) {
    int i = blockIdx.x * 256 + threadIdx.x;
    int row = i / 384;
    int r = i - row * 384;
    int h = r >> 5;
    int hp = r & 31;
    int b = row >> 10, t = row & 1023;
    const float* base = qkv + (size_t)row * cD3 + h * cHD + hp * 2;
    size_t o = ((size_t)(b * cH + h) * cT + t) * 32 + hp;
    float2 q = *(const float2*)(base);
    float2 k = *(const float2*)(base + cD);
    float2 v = *(const float2*)(base + 2 * cD);
    uint32_t hpk, lpk;
    split2(q.x * 0.125f, q.y * 0.125f, hpk, lpk);
    ((uint32_t*)qh)[o] = hpk; ((uint32_t*)ql)[o] = lpk;
    split2(k.x, k.y, hpk, lpk);
    ((uint32_t*)kh)[o] = hpk; ((uint32_t*)kl)[o] = lpk;
    split2(v.x, v.y, hpk, lpk);
    ((uint32_t*)vh)[o] = hpk; ((uint32_t*)vl)[o] = lpk;
}

__global__ void __launch_bounds__(256) loss_row_kernel(const float* __restrict__ logits,
                                                       const int* __restrict__ tgt,
                                                       float* __restrict__ nll) {
    const int r = blockIdx.x;
    const float* lr = logits + (size_t)r * cV;
    float mx = -INFINITY;
    for (int i = threadIdx.x; i < cV; i += 256) mx = fmaxf(mx, lr[i]);
    mx = blockReduceMax(mx);
    float s = 0.0f;
    for (int i = threadIdx.x; i < cV; i += 256) s += __expf(lr[i] - mx);
    s = blockReduceSum(s);
    if (threadIdx.x == 0)
        nll[r] = -(lr[tgt[r]] - mx - logf(s));
}

__global__ void __launch_bounds__(256) loss_reduce_kernel(const float* __restrict__ nll,
                                                          float* __restrict__ out) {
    float s = 0.0f;
    for (int i = threadIdx.x; i < cM; i += 256) s += nll[i];
    s = blockReduceSum(s);
    if (threadIdx.x == 0) *out = s / (float)cM;
}

// ---------------------------------------------------------------------------
// Launch
// ---------------------------------------------------------------------------
template<typename T> static T* sym(const void* s) {
    void* p; cudaGetSymbolAddress(&p, s); return (T*)p;
}

using bf16 = __nv_bfloat16;

#define GQKV  gemm_u<128,true ,false,false,false,true ,false,0,false,false>
#define GPROJ gemm_u<96 ,true ,false,true ,false,true ,false,0,false,false>
#define GFC   gemm_u<128,true ,true ,false,true ,false,true ,0,false,false>
#define GOUT  gemm_u<96 ,true ,true ,true ,false,true ,false,0,false,false>

extern "C" void kernel_launch(void* const* d_in, const int* in_sizes, int n_in,
                              void* d_out, int out_size) {
    const int*   idx    = (const int*)  d_in[0];
    const int*   tgt    = (const int*)  d_in[1];
    const float* wte    = (const float*)d_in[2];
    const float* wpe    = (const float*)d_in[3];
    const float* ln1_g  = (const float*)d_in[4];
    const float* ln1_b  = (const float*)d_in[5];
    const float* w_attn = (const float*)d_in[6];
    const float* w_proj = (const float*)d_in[7];
    const float* ln2_g  = (const float*)d_in[8];
    const float* ln2_b  = (const float*)d_in[9];
    const float* w_fc   = (const float*)d_in[10];
    const float* b_fc   = (const float*)d_in[11];
    const float* w_out  = (const float*)d_in[12];
    const float* b_out  = (const float*)d_in[13];
    const float* lnf_g  = (const float*)d_in[14];
    const float* lnf_b  = (const float*)d_in[15];
    const float* w_head = (const float*)d_in[16];
    float* logits = (float*)d_out;

    float* x   = sym<float>(g_x);
    float* qkv = sym<float>(g_qkv);
    float* nll = sym<float>(g_nll);
    bf16 *lnh = sym<bf16>(g_ln_h), *lnl = sym<bf16>(g_ln_l);
    bf16 *yh  = sym<bf16>(g_y_h),  *yl  = sym<bf16>(g_y_l);
    bf16 *fch = sym<bf16>(g_fc_h), *fcl = sym<bf16>(g_fc_l);
    bf16 *qh  = sym<bf16>(g_q_h),  *ql  = sym<bf16>(g_q_l);
    bf16 *kh  = sym<bf16>(g_k_h),  *kl  = sym<bf16>(g_k_l);
    bf16 *vh  = sym<bf16>(g_v_h),  *vl  = sym<bf16>(g_v_l);
    bf16 *wah = sym<bf16>(g_wa_h), *wal = sym<bf16>(g_wa_l);
    bf16 *wph = sym<bf16>(g_wp_h), *wpl = sym<bf16>(g_wp_l);
    bf16 *wfh = sym<bf16>(g_wf_h), *wfl = sym<bf16>(g_wf_l);
    bf16 *woh = sym<bf16>(g_wo_h), *wol = sym<bf16>(g_wo_l);
    bf16 *whh = sym<bf16>(g_wh_h), *whl = sym<bf16>(g_wh_l);

    constexpr int SM128T = Geom<128, true>::SMEM;
    constexpr int SM96T  = Geom<96,  true>::SMEM;

    cudaFuncSetAttribute((const void*)GQKV,  cudaFuncAttributeMaxDynamicSharedMemorySize, SM128T);
    cudaFuncSetAttribute((const void*)GPROJ, cudaFuncAttributeMaxDynamicSharedMemorySize, SM96T);
    cudaFuncSetAttribute((const void*)GFC,   cudaFuncAttributeMaxDynamicSharedMemorySize, SM128T);
    cudaFuncSetAttribute((const void*)GOUT,  cudaFuncAttributeMaxDynamicSharedMemorySize, SM96T);
    cudaFuncSetAttribute((const void*)flash_kernel,
                         cudaFuncAttributeMaxDynamicSharedMemorySize, FLASH_SMEM);

    split_kernel<<<cL * cD * cD3 / 512, 256>>>(w_attn, wah, wal, cL * cD * cD3 / 2);
    split_kernel<<<cL * cD * cD  / 512, 256>>>(w_proj, wph, wpl, cL * cD * cD  / 2);
    split_kernel<<<cL * cD * cDF / 512, 256>>>(w_fc,   wfh, wfl, cL * cD * cDF / 2);
    split_kernel<<<cL * cDF * cD / 512, 256>>>(w_out,  woh, wol, cL * cDF * cD / 2);
    split_kernel<<<cD * cV       / 512, 256>>>(w_head, whh, whl, cD * cV       / 2);

    embed_kernel<<<(cM * cD) / 256, 256>>>(idx, wte, wpe, x);

    for (int l = 0; l < cL; l++) {
        ln_kernel<<<cM, 256>>>(x, ln1_g + l * cD, ln1_b + l * cD, lnh, lnl);
        GQKV<<<dim3(cD3 / 128, cM / 128, 1), 256, SM128T>>>(
            lnh, lnl, wah + (size_t)l * cD * cD3, wal + (size_t)l * cD * cD3,
            nullptr, nullptr, qkv, nullptr, nullptr, cD3, cD, cD3, 0, 0, 0);
        repack_qkv<<<cM * cD / 512, 256>>>(qkv, qh, ql, kh, kl, vh, vl);
        flash_kernel<<<dim3(cT / 128, cZ), 256, FLASH_SMEM>>>(
            qh, ql, kh, kl, vh, vl, yh, yl);
        GPROJ<<<dim3(cD / 96, cM / 128, 1), 256, SM96T>>>(
            yh, yl, wph + (size_t)l * cD * cD, wpl + (size_t)l * cD * cD,
            nullptr, x, x, nullptr, nullptr, cD, cD, cD, 0, 0, 0);
        ln_kernel<<<cM, 256>>>(x, ln2_g + l * cD, ln2_b + l * cD, lnh, lnl);
        GFC<<<dim3(cDF / 128, cM / 128, 1), 256, SM128T>>>(
            lnh, lnl, wfh + (size_t)l * cD * cDF, wfl + (size_t)l * cD * cDF,
            b_fc + l * cDF, nullptr, nullptr, fch, fcl, cDF, cD, cDF, 0, 0, 0);
        GOUT<<<dim3(cD / 96, cM / 128, 1), 256, SM96T>>>(
            fch, fcl, woh + (size_t)l * cDF * cD, wol + (size_t)l * cDF * cD,
            b_out + l * cD, x, x, nullptr, nullptr, cD, cDF, cD, 0, 0, 0);
    }

    ln_kernel<<<cM, 256>>>(x, lnf_g, lnf_b, lnh, lnl);
    GQKV<<<dim3(cV / 128, cM / 128, 1), 256, SM128T>>>(
        lnh, lnl, whh, whl, nullptr, nullptr, logits, nullptr, nullptr,
        cV, cD, cV, 0, 0, 0);

    if (out_size >= cM * cV + 1) {
        loss_row_kernel<<<cM, 256>>>(logits, tgt, nll);
        loss_reduce_kernel<<<1, 256>>>(nll, logits + (size_t)cM * cV);
    }
}

// round 7
// speedup vs baseline: 3.4945x; 1.0065x over previous
#include <cuda_runtime.h>
#include <cuda_bf16.h>
#include <math.h>
#include <stdint.h>

// ---------------------------------------------------------------------------
// Problem constants
// ---------------------------------------------------------------------------
constexpr int cV  = 32000;
constexpr int cD  = 768;
constexpr int cH  = 12;
constexpr int cL  = 8;
constexpr int cT  = 1024;
constexpr int cB  = 4;
constexpr int cHD = cD / cH;          // 64
constexpr int cM  = cB * cT;          // 4096
constexpr int cD3 = 3 * cD;           // 2304
constexpr int cDF = 4 * cD;           // 3072
constexpr int cZ  = cB * cH;          // 48 heads
constexpr size_t cQH = (size_t)cT * cHD;       // 65536 per head

// ---------------------------------------------------------------------------
// Scratch (device globals — no allocation allowed)
// ---------------------------------------------------------------------------
__device__ float g_x  [cM * cD];
__device__ float g_nll[cM];

__device__ __nv_bfloat16 g_ln_h[cM * cD],  g_ln_l[cM * cD];
__device__ __nv_bfloat16 g_y_h [cM * cD],  g_y_l [cM * cD];
__device__ __nv_bfloat16 g_fc_h[cM * cDF], g_fc_l[cM * cDF];
__device__ __nv_bfloat16 g_q_h [cZ * cT * cHD], g_q_l [cZ * cT * cHD];
__device__ __nv_bfloat16 g_k_h [cZ * cT * cHD], g_k_l [cZ * cT * cHD];
__device__ __nv_bfloat16 g_v_h [cZ * cT * cHD], g_v_l [cZ * cT * cHD];
__device__ __nv_bfloat16 g_wa_h[cL * cD * cD3], g_wa_l[cL * cD * cD3];
__device__ __nv_bfloat16 g_wp_h[cL * cD * cD],  g_wp_l[cL * cD * cD];
__device__ __nv_bfloat16 g_wf_h[cL * cD * cDF], g_wf_l[cL * cD * cDF];
__device__ __nv_bfloat16 g_wo_h[cL * cDF * cD], g_wo_l[cL * cDF * cD];
__device__ __nv_bfloat16 g_wh_h[cD * cV],       g_wh_l[cD * cV];

// ---------------------------------------------------------------------------
// PTX helpers
// ---------------------------------------------------------------------------
__device__ __forceinline__ void cp_async16(uint32_t saddr, const void* gptr) {
    asm volatile("cp.async.cg.shared.global [%0], [%1], 16;"
                 :: "r"(saddr), "l"(gptr));
}
#define CP_COMMIT() asm volatile("cp.async.commit_group;" ::: "memory")
#define CP_WAIT0()  asm volatile("cp.async.wait_group 0;" ::: "memory")
#define CP_WAIT1()  asm volatile("cp.async.wait_group 1;" ::: "memory")

__device__ __forceinline__ void ldsm_x4(uint32_t* r, uint32_t addr) {
    asm volatile("ldmatrix.sync.aligned.m8n8.x4.shared.b16 {%0,%1,%2,%3}, [%4];"
        : "=r"(r[0]), "=r"(r[1]), "=r"(r[2]), "=r"(r[3]) : "r"(addr));
}
__device__ __forceinline__ void ldsm_x4_t(uint32_t* r, uint32_t addr) {
    asm volatile("ldmatrix.sync.aligned.m8n8.x4.trans.shared.b16 {%0,%1,%2,%3}, [%4];"
        : "=r"(r[0]), "=r"(r[1]), "=r"(r[2]), "=r"(r[3]) : "r"(addr));
}
__device__ __forceinline__ void mma_bf16(float* d, const uint32_t* a,
                                         uint32_t b0, uint32_t b1) {
    asm volatile(
        "mma.sync.aligned.m16n8k16.row.col.f32.bf16.bf16.f32 "
        "{%0,%1,%2,%3},{%4,%5,%6,%7},{%8,%9},{%0,%1,%2,%3};"
        : "+f"(d[0]), "+f"(d[1]), "+f"(d[2]), "+f"(d[3])
        : "r"(a[0]), "r"(a[1]), "r"(a[2]), "r"(a[3]), "r"(b0), "r"(b1));
}

__device__ __forceinline__ uint32_t pack_bf16x2(float lo, float hi) {
    uint32_t d;
    asm("cvt.rn.bf16x2.f32 %0, %1, %2;" : "=r"(d) : "f"(hi), "f"(lo));
    return d;
}
__device__ __forceinline__ void split2(float v0, float v1,
                                       uint32_t& hp, uint32_t& lp) {
    hp = pack_bf16x2(v0, v1);
    float h0 = __uint_as_float(hp << 16);
    float h1 = __uint_as_float(hp & 0xffff0000u);
    lp = pack_bf16x2(v0 - h0, v1 - h1);
}

__device__ __forceinline__ float gelu_exact(float x) {
    return 0.5f * x * (1.0f + erff(x * 0.70710678118654752f));
}

// ---------------------------------------------------------------------------
// Generalized split-bf16 GEMM (3-mma Markidis): C = A @ W(op)
//   ZMODE 0: C offset z*sC   ZMODE 2: qkv scatter into per-head planes
//   SWAPXY : blockIdx.x indexes M (B-reuse-friendly wave order)
// ---------------------------------------------------------------------------
template<int NT, bool BTRANS>
struct Geom {
    static constexpr int SBb = BTRANS ? (2 * NT + 16) : 80;
    static constexpr int BSZ = BTRANS ? 32 * SBb : NT * 80;
    static constexpr int AL  = 10240;
    static constexpr int BH  = 20480;
    static constexpr int BL  = BH + BSZ;
    static constexpr int BUF = BH + 2 * BSZ;
    static constexpr int SMEM = 2 * BUF;
};

template<int NT, bool BTRANS, bool BIAS, bool RES, bool GELU,
         bool WC, bool WPL, int ZMODE, bool SWAPXY>
__global__ void __launch_bounds__(256, 2) gemm_u(
    const __nv_bfloat16* __restrict__ Ah, const __nv_bfloat16* __restrict__ Al,
    const __nv_bfloat16* __restrict__ Wh, const __nv_bfloat16* __restrict__ Wl,
    const float* __restrict__ bias, const float* __restrict__ Rres,
    float* __restrict__ C,
    __nv_bfloat16* __restrict__ Ch, __nv_bfloat16* __restrict__ Cl,
    __nv_bfloat16* __restrict__ Dh, __nv_bfloat16* __restrict__ Dl,
    __nv_bfloat16* __restrict__ Eh, __nv_bfloat16* __restrict__ El,
    int N, int K, int ldc, size_t sA, size_t sW, size_t sC) {

    using G = Geom<NT, BTRANS>;
    extern __shared__ char smem[];
    const uint32_t sb = (uint32_t)__cvta_generic_to_shared(smem);

    const int m0 = (SWAPXY ? blockIdx.x : blockIdx.y) * 128;
    const int n0 = (SWAPXY ? blockIdx.y : blockIdx.x) * NT;

    const int z = blockIdx.z;
    Ah += z * sA; Al += z * sA;
    Wh += z * sW; Wl += z * sW;
    const size_t cofs = z * sC;

    const int tid  = threadIdx.x;
    const int lane = tid & 31;
    const int wid  = tid >> 5;
    const int gr   = lane >> 2;
    const int tg   = lane & 3;
    const int mw   = (wid & 3) * 32;
    const int nw   = (wid >> 2) * (NT / 2);
    const int lr   = lane & 7, lt = lane >> 3;

    const uint32_t aoff = (uint32_t)((mw + (lt & 1) * 8 + lr) * 80 + (lt >> 1) * 16);
    uint32_t boff;
    if (BTRANS) boff = (uint32_t)(((lt & 1) * 8 + lr) * G::SBb + (nw + (lt >> 1) * 8) * 2);
    else        boff = (uint32_t)((nw + (lt >> 1) * 8 + lr) * 80 + (lt & 1) * 16);

    constexpr int NTW = NT / 16;
    float acc[2][NTW][4];
    #pragma unroll
    for (int mi = 0; mi < 2; mi++)
        #pragma unroll
        for (int nt = 0; nt < NTW; nt++)
            #pragma unroll
            for (int q = 0; q < 4; q++) acc[mi][nt][q] = 0.0f;

    const int NK = K >> 5;

    auto stage = [&](int ib, int buf) {
        const int k0 = ib << 5;
        const uint32_t bb = sb + buf * G::BUF;
        #pragma unroll
        for (int j = 0; j < 2; j++) {
            int c = tid + 256 * j;
            int row = c >> 2, seg = c & 3;
            uint32_t d = bb + (uint32_t)(row * 80 + seg * 16);
            size_t s = (size_t)(m0 + row) * K + k0 + seg * 8;
            cp_async16(d, Ah + s);
            cp_async16(d + G::AL, Al + s);
        }
        if (BTRANS) {
            constexpr int SEGS = NT / 8;
            constexpr int BCH = 32 * SEGS;
            #pragma unroll
            for (int j = 0; j < (BCH + 255) / 256; j++) {
                int c = tid + 256 * j;
                if ((BCH % 256 == 0) || c < BCH) {
                    int kr = c / SEGS, seg = c - kr * SEGS;
                    uint32_t d = bb + G::BH + (uint32_t)(kr * G::SBb + seg * 16);
                    size_t s = (size_t)(k0 + kr) * N + n0 + seg * 8;
                    cp_async16(d, Wh + s);
                    cp_async16(d + G::BSZ, Wl + s);
                }
            }
        } else {
            constexpr int BCH = NT * 4;
            #pragma unroll
            for (int j = 0; j < (BCH + 255) / 256; j++) {
                int c = tid + 256 * j;
                if ((BCH % 256 == 0) || c < BCH) {
                    int row = c >> 2, seg = c & 3;
                    uint32_t d = bb + G::BH + (uint32_t)(row * 80 + seg * 16);
                    size_t s = (size_t)(n0 + row) * K + k0 + seg * 8;
                    cp_async16(d, Wh + s);
                    cp_async16(d + G::BSZ, Wl + s);
                }
            }
        }
    };

    stage(0, 0); CP_COMMIT();
    stage(1, 1); CP_COMMIT();

    for (int ib = 0; ib < NK; ib++) {
        const int buf = ib & 1;
        CP_WAIT1();
        __syncthreads();

        const uint32_t base = sb + buf * G::BUF;
        const uint32_t aHb = base + aoff;
        const uint32_t aLb = base + G::AL + aoff;
        const uint32_t bHb = base + G::BH + boff;
        const uint32_t bLb = base + G::BL + boff;

        #pragma unroll
        for (int ks = 0; ks < 2; ks++) {
            uint32_t ahi[2][4], alo[2][4];
            ldsm_x4(ahi[0], aHb + ks * 32);
            ldsm_x4(ahi[1], aHb + 1280 + ks * 32);
            ldsm_x4(alo[0], aLb + ks * 32);
            ldsm_x4(alo[1], aLb + 1280 + ks * 32);
            #pragma unroll
            for (int g = 0; g < NT / 32; g++) {
                uint32_t bh[4], bl[4];
                if (BTRANS) {
                    ldsm_x4_t(bh, bHb + ks * (16 * G::SBb) + g * 32);
                    ldsm_x4_t(bl, bLb + ks * (16 * G::SBb) + g * 32);
                } else {
                    ldsm_x4(bh, bHb + ks * 32 + g * 1280);
                    ldsm_x4(bl, bLb + ks * 32 + g * 1280);
                }
                #pragma unroll
                for (int mi = 0; mi < 2; mi++) {
                    const int nt = g * 2;
                    mma_bf16(acc[mi][nt],     ahi[mi], bh[0], bh[1]);
                    mma_bf16(acc[mi][nt],     ahi[mi], bl[0], bl[1]);
                    mma_bf16(acc[mi][nt],     alo[mi], bh[0], bh[1]);
                    mma_bf16(acc[mi][nt + 1], ahi[mi], bh[2], bh[3]);
                    mma_bf16(acc[mi][nt + 1], ahi[mi], bl[2], bl[3]);
                    mma_bf16(acc[mi][nt + 1], alo[mi], bh[2], bh[3]);
                }
            }
        }
        __syncthreads();
        if (ib + 2 < NK) stage(ib + 2, buf);
        CP_COMMIT();
    }

    #pragma unroll
    for (int mi = 0; mi < 2; mi++) {
        const int r0 = m0 + mw + mi * 16 + gr;
        #pragma unroll
        for (int nt = 0; nt < NTW; nt++) {
            const int c0 = n0 + nw + nt * 8 + tg * 2;
            float2 v0 = make_float2(acc[mi][nt][0], acc[mi][nt][1]);
            float2 v1 = make_float2(acc[mi][nt][2], acc[mi][nt][3]);
            if (BIAS) {
                float2 bv = *(const float2*)(bias + c0);
                v0.x += bv.x; v0.y += bv.y;
                v1.x += bv.x; v1.y += bv.y;
            }
            if (GELU) {
                v0.x = gelu_exact(v0.x); v0.y = gelu_exact(v0.y);
                v1.x = gelu_exact(v1.x); v1.y = gelu_exact(v1.y);
            }
            if (ZMODE == 2) {
                // qkv scatter: section uniform per CTA (768 % 128 == 0)
                const int sec = n0 / cD;
                const int cc  = c0 - sec * cD;
                const int h   = cc >> 6, d = cc & 63;
                const float scale = (sec == 0) ? 0.125f : 1.0f;
                uint32_t* ph = (uint32_t*)(sec == 0 ? Ch : sec == 1 ? Dh : Eh);
                uint32_t* pl = (uint32_t*)(sec == 0 ? Cl : sec == 1 ? Dl : El);
                const int b = r0 >> 10, t0 = r0 & 1023;
                size_t zb = (size_t)(b * cH + h) * 1024;
                size_t oA = (zb + t0)     * 32 + (d >> 1);
                size_t oB = (zb + t0 + 8) * 32 + (d >> 1);
                uint32_t hp, lp;
                split2(v0.x * scale, v0.y * scale, hp, lp);
                ph[oA] = hp; pl[oA] = lp;
                split2(v1.x * scale, v1.y * scale, hp, lp);
                ph[oB] = hp; pl[oB] = lp;
            } else {
                size_t o0 = cofs + (size_t)r0 * ldc + c0;
                size_t o1 = cofs + (size_t)(r0 + 8) * ldc + c0;
                if (RES) {
                    float2 a0 = *(const float2*)(Rres + o0);
                    float2 a1 = *(const float2*)(Rres + o1);
                    v0.x += a0.x; v0.y += a0.y;
                    v1.x += a1.x; v1.y += a1.y;
                }
                if (WC) {
                    *(float2*)(C + o0) = v0;
                    *(float2*)(C + o1) = v1;
                }
                if (WPL) {
                    uint32_t hp, lp;
                    split2(v0.x, v0.y, hp, lp);
                    ((uint32_t*)Ch)[o0 >> 1] = hp;
                    ((uint32_t*)Cl)[o0 >> 1] = lp;
                    split2(v1.x, v1.y, hp, lp);
                    ((uint32_t*)Ch)[o1 >> 1] = hp;
                    ((uint32_t*)Cl)[o1 >> 1] = lp;
                }
            }
        }
    }
}

// ---------------------------------------------------------------------------
// Fused flash attention (split-bf16 mma, online softmax)
// ---------------------------------------------------------------------------
constexpr int F_SQ   = 144;
constexpr int F_PL   = 128 * F_SQ;
constexpr int F_KV0  = 2 * F_PL;
constexpr int F_KVSZ = 4 * F_PL;
constexpr int FLASH_SMEM = 2 * F_PL + 2 * F_KVSZ;  // 184320

__global__ void __launch_bounds__(256, 1) flash_kernel(
    const __nv_bfloat16* __restrict__ qh, const __nv_bfloat16* __restrict__ ql,
    const __nv_bfloat16* __restrict__ kh, const __nv_bfloat16* __restrict__ kl,
    const __nv_bfloat16* __restrict__ vh, const __nv_bfloat16* __restrict__ vl,
    __nv_bfloat16* __restrict__ yh, __nv_bfloat16* __restrict__ yl) {

    extern __shared__ char smem[];
    const uint32_t sb = (uint32_t)__cvta_generic_to_shared(smem);
    const int qb = blockIdx.x;
    const int z  = blockIdx.y;
    const int q0 = qb * 128;
    const int tid  = threadIdx.x;
    const int lane = tid & 31;
    const int wid  = tid >> 5;
    const int gr   = lane >> 2;
    const int tg   = lane & 3;
    const int wq   = wid * 16;
    const int lr   = lane & 7, lt = lane >> 3;

    const __nv_bfloat16* qhz = qh + (size_t)z * cQH;
    const __nv_bfloat16* qlz = ql + (size_t)z * cQH;
    const __nv_bfloat16* khz = kh + (size_t)z * cQH;
    const __nv_bfloat16* klz = kl + (size_t)z * cQH;
    const __nv_bfloat16* vhz = vh + (size_t)z * cQH;
    const __nv_bfloat16* vlz = vl + (size_t)z * cQH;

    #pragma unroll
    for (int j = 0; j < 4; j++) {
        int c = tid + 256 * j;
        int row = c >> 3, seg = c & 7;
        uint32_t d = sb + (uint32_t)(row * F_SQ + seg * 16);
        size_t s = (size_t)(q0 + row) * cHD + seg * 8;
        cp_async16(d, qhz + s);
        cp_async16(d + F_PL, qlz + s);
    }
    auto stageKV = [&](int kb, int buf) {
        const uint32_t bb = sb + F_KV0 + buf * F_KVSZ;
        #pragma unroll
        for (int j = 0; j < 4; j++) {
            int c = tid + 256 * j;
            int row = c >> 3, seg = c & 7;
            uint32_t d = bb + (uint32_t)(row * F_SQ + seg * 16);
            size_t s = (size_t)(kb * 128 + row) * cHD + seg * 8;
            cp_async16(d, khz + s);
            cp_async16(d + F_PL, klz + s);
            cp_async16(d + 2 * F_PL, vhz + s);
            cp_async16(d + 3 * F_PL, vlz + s);
        }
    };

    stageKV(0, 0);
    CP_COMMIT();
    if (qb >= 1) { stageKV(1, 1); CP_COMMIT(); }

    float mrow[2] = { -INFINITY, -INFINITY };
    float lrow[2] = { 0.0f, 0.0f };
    float oacc[8][4];
    #pragma unroll
    for (int nt = 0; nt < 8; nt++)
        #pragma unroll
        for (int q = 0; q < 4; q++) oacc[nt][q] = 0.0f;

    uint32_t qfh[4][4], qfl[4][4];
    bool qloaded = false;

    const uint32_t q_aoff = (uint32_t)((wq + (lt & 1) * 8 + lr) * F_SQ + (lt >> 1) * 16);
    const uint32_t k_boff = (uint32_t)(((lt >> 1) * 8 + lr) * F_SQ + (lt & 1) * 16);
    const uint32_t v_boff = (uint32_t)(((lt & 1) * 8 + lr) * F_SQ + (lt >> 1) * 16);

    for (int kb = 0; kb <= qb; kb++) {
        if (kb < qb) { CP_WAIT1(); } else { CP_WAIT0(); }
        __syncthreads();

        if (!qloaded) {
            #pragma unroll
            for (int ks = 0; ks < 4; ks++) {
                ldsm_x4(qfh[ks], sb + q_aoff + ks * 32);
                ldsm_x4(qfl[ks], sb + F_PL + q_aoff + ks * 32);
            }
            qloaded = true;
        }

        const uint32_t kvb = sb + F_KV0 + (kb & 1) * F_KVSZ;

        float s[16][4];
        #pragma unroll
        for (int nt = 0; nt < 16; nt++)
            #pragma unroll
            for (int q = 0; q < 4; q++) s[nt][q] = 0.0f;

        #pragma unroll
        for (int ks = 0; ks < 4; ks++) {
            #pragma unroll
            for (int g = 0; g < 8; g++) {
                uint32_t bh[4], bl[4];
                uint32_t addr = kvb + k_boff + (uint32_t)(g * 16 * F_SQ) + ks * 32;
                ldsm_x4(bh, addr);
                ldsm_x4(bl, addr + F_PL);
                const int nt = g * 2;
                mma_bf16(s[nt],     qfh[ks], bh[0], bh[1]);
                mma_bf16(s[nt],     qfh[ks], bl[0], bl[1]);
                mma_bf16(s[nt],     qfl[ks], bh[0], bh[1]);
                mma_bf16(s[nt + 1], qfh[ks], bh[2], bh[3]);
                mma_bf16(s[nt + 1], qfh[ks], bl[2], bl[3]);
                mma_bf16(s[nt + 1], qfl[ks], bh[2], bh[3]);
            }
        }

        if (kb == qb) {
            const int r0 = wq + gr, r1 = wq + gr + 8;
            #pragma unroll
            for (int nt = 0; nt < 16; nt++) {
                const int c0 = nt * 8 + tg * 2;
                if (c0     > r0) s[nt][0] = -1e30f;
                if (c0 + 1 > r0) s[nt][1] = -1e30f;
                if (c0     > r1) s[nt][2] = -1e30f;
                if (c0 + 1 > r1) s[nt][3] = -1e30f;
            }
        }

        float mn0 = -INFINITY, mn1 = -INFINITY;
        #pragma unroll
        for (int nt = 0; nt < 16; nt++) {
            mn0 = fmaxf(mn0, fmaxf(s[nt][0], s[nt][1]));
            mn1 = fmaxf(mn1, fmaxf(s[nt][2], s[nt][3]));
        }
        mn0 = fmaxf(mn0, __shfl_xor_sync(0xffffffffu, mn0, 1));
        mn0 = fmaxf(mn0, __shfl_xor_sync(0xffffffffu, mn0, 2));
        mn1 = fmaxf(mn1, __shfl_xor_sync(0xffffffffu, mn1, 1));
        mn1 = fmaxf(mn1, __shfl_xor_sync(0xffffffffu, mn1, 2));
        float mnew0 = fmaxf(mrow[0], mn0);
        float mnew1 = fmaxf(mrow[1], mn1);
        float al0 = __expf(mrow[0] - mnew0);
        float al1 = __expf(mrow[1] - mnew1);
        mrow[0] = mnew0; mrow[1] = mnew1;

        float rs0 = 0.0f, rs1 = 0.0f;
        #pragma unroll
        for (int nt = 0; nt < 16; nt++) {
            s[nt][0] = __expf(s[nt][0] - mnew0);
            s[nt][1] = __expf(s[nt][1] - mnew0);
            s[nt][2] = __expf(s[nt][2] - mnew1);
            s[nt][3] = __expf(s[nt][3] - mnew1);
            rs0 += s[nt][0] + s[nt][1];
            rs1 += s[nt][2] + s[nt][3];
        }
        rs0 += __shfl_xor_sync(0xffffffffu, rs0, 1);
        rs0 += __shfl_xor_sync(0xffffffffu, rs0, 2);
        rs1 += __shfl_xor_sync(0xffffffffu, rs1, 1);
        rs1 += __shfl_xor_sync(0xffffffffu, rs1, 2);
        lrow[0] = lrow[0] * al0 + rs0;
        lrow[1] = lrow[1] * al1 + rs1;

        #pragma unroll
        for (int nt = 0; nt < 8; nt++) {
            oacc[nt][0] *= al0; oacc[nt][1] *= al0;
            oacc[nt][2] *= al1; oacc[nt][3] *= al1;
        }

        #pragma unroll
        for (int ks = 0; ks < 8; ks++) {
            uint32_t pah[4], pal[4];
            uint32_t h0, l0;
            split2(s[2*ks][0],   s[2*ks][1],   h0, l0); pah[0] = h0; pal[0] = l0;
            split2(s[2*ks][2],   s[2*ks][3],   h0, l0); pah[1] = h0; pal[1] = l0;
            split2(s[2*ks+1][0], s[2*ks+1][1], h0, l0); pah[2] = h0; pal[2] = l0;
            split2(s[2*ks+1][2], s[2*ks+1][3], h0, l0); pah[3] = h0; pal[3] = l0;
            #pragma unroll
            for (int g = 0; g < 4; g++) {
                uint32_t bvh[4], bvl[4];
                uint32_t addr = kvb + 2 * F_PL + v_boff
                              + (uint32_t)(ks * 16 * F_SQ) + g * 32;
                ldsm_x4_t(bvh, addr);
                ldsm_x4_t(bvl, addr + F_PL);
                const int nt = g * 2;
                mma_bf16(oacc[nt],     pah, bvh[0], bvh[1]);
                mma_bf16(oacc[nt],     pah, bvl[0], bvl[1]);
                mma_bf16(oacc[nt],     pal, bvh[0], bvh[1]);
                mma_bf16(oacc[nt + 1], pah, bvh[2], bvh[3]);
                mma_bf16(oacc[nt + 1], pah, bvl[2], bvl[3]);
                mma_bf16(oacc[nt + 1], pal, bvh[2], bvh[3]);
            }
        }

        __syncthreads();
        if (kb + 2 <= qb) { stageKV(kb + 2, kb & 1); CP_COMMIT(); }
    }

    const float inv0 = 1.0f / lrow[0];
    const float inv1 = 1.0f / lrow[1];
    const int b = z / cH, h = z % cH;
    const int r0 = b * cT + q0 + wq + gr;
    #pragma unroll
    for (int nt = 0; nt < 8; nt++) {
        const int c0 = h * cHD + nt * 8 + tg * 2;
        uint32_t hp, lp;
        split2(oacc[nt][0] * inv0, oacc[nt][1] * inv0, hp, lp);
        size_t o0 = ((size_t)r0 * cD + c0) >> 1;
        ((uint32_t*)yh)[o0] = hp; ((uint32_t*)yl)[o0] = lp;
        split2(oacc[nt][2] * inv1, oacc[nt][3] * inv1, hp, lp);
        size_t o1 = ((size_t)(r0 + 8) * cD + c0) >> 1;
        ((uint32_t*)yh)[o1] = hp; ((uint32_t*)yl)[o1] = lp;
    }
}

// ---------------------------------------------------------------------------
// Block reductions (blockDim.x == 256)
// ---------------------------------------------------------------------------
__device__ __forceinline__ float blockReduceSum(float v) {
    __shared__ float sh[8];
    #pragma unroll
    for (int o = 16; o; o >>= 1) v += __shfl_xor_sync(0xffffffffu, v, o);
    int w = threadIdx.x >> 5, l = threadIdx.x & 31;
    __syncthreads();
    if (l == 0) sh[w] = v;
    __syncthreads();
    if (w == 0) {
        v = (l < 8) ? sh[l] : 0.0f;
        #pragma unroll
        for (int o = 16; o; o >>= 1) v += __shfl_xor_sync(0xffffffffu, v, o);
        if (l == 0) sh[0] = v;
    }
    __syncthreads();
    return sh[0];
}

__device__ __forceinline__ float blockReduceMax(float v) {
    __shared__ float sh[8];
    #pragma unroll
    for (int o = 16; o; o >>= 1) v = fmaxf(v, __shfl_xor_sync(0xffffffffu, v, o));
    int w = threadIdx.x >> 5, l = threadIdx.x & 31;
    __syncthreads();
    if (l == 0) sh[w] = v;
    __syncthreads();
    if (w == 0) {
        v = (l < 8) ? sh[l] : -INFINITY;
        #pragma unroll
        for (int o = 16; o; o >>= 1) v = fmaxf(v, __shfl_xor_sync(0xffffffffu, v, o));
        if (l == 0) sh[0] = v;
    }
    __syncthreads();
    return sh[0];
}

// ---------------------------------------------------------------------------
// Small kernels
// ---------------------------------------------------------------------------
__global__ void __launch_bounds__(256) split_kernel(const float* __restrict__ src,
                                                    __nv_bfloat16* __restrict__ hi,
                                                    __nv_bfloat16* __restrict__ lo,
                                                    int npairs) {
    int i = blockIdx.x * blockDim.x + threadIdx.x;
    if (i >= npairs) return;
    float2 v = *(const float2*)(src + (size_t)i * 2);
    uint32_t hp, lp;
    split2(v.x, v.y, hp, lp);
    ((uint32_t*)hi)[i] = hp;
    ((uint32_t*)lo)[i] = lp;
}

__global__ void embed_kernel(const int* __restrict__ idx,
                             const float* __restrict__ wte,
                             const float* __restrict__ wpe,
                             float* __restrict__ x) {
    int i = blockIdx.x * blockDim.x + threadIdx.x;
    int row = i / cD;
    int d   = i - row * cD;
    int t   = row & (cT - 1);
    int tok = idx[row];
    x[i] = wte[(size_t)tok * cD + d] + wpe[(size_t)t * cD + d];
}

__global__ void __launch_bounds__(256) ln_kernel(const float* __restrict__ x,
                                                 const float* __restrict__ g,
                                                 const float* __restrict__ b,
                                                 __nv_bfloat16* __restrict__ oh,
                                                 __nv_bfloat16* __restrict__ ol) {
    const int row = blockIdx.x;
    const float* xr = x + (size_t)row * cD;
    const int t = threadIdx.x;
    float v0 = xr[t], v1 = xr[t + 256], v2 = xr[t + 512];
    float s  = blockReduceSum(v0 + v1 + v2);
    float s2 = blockReduceSum(v0 * v0 + v1 * v1 + v2 * v2);
    const float inv = 1.0f / cD;
    float mu  = s * inv;
    float var = s2 * inv - mu * mu;
    float rs  = rsqrtf(var + 1e-5f);
    #pragma unroll
    for (int j = 0; j < 3; j++) {
        int d = t + j * 256;
        float val = (((j == 0) ? v0 : (j == 1) ? v1 : v2) - mu) * rs * g[d] + b[d];
        __nv_bfloat16 h = __float2bfloat16_rn(val);
        oh[(size_t)row * cD + d] = h;
        ol[(size_t)row * cD + d] = __float2bfloat16_rn(val - __bfloat162float(h));
    }
}

__global__ void __launch_bounds__(256) loss_row_kernel(const float* __restrict__ logits,
                                                       const int* __restrict__ tgt,
                                                       float* __restrict__ nll) {
    const int r = blockIdx.x;
    const float* lr = logits + (size_t)r * cV;
    float mx = -INFINITY;
    for (int i = threadIdx.x; i < cV; i += 256) mx = fmaxf(mx, lr[i]);
    mx = blockReduceMax(mx);
    float s = 0.0f;
    for (int i = threadIdx.x; i < cV; i += 256) s += __expf(lr[i] - mx);
    s = blockReduceSum(s);
    if (threadIdx.x == 0)
        nll[r] = -(lr[tgt[r]] - mx - logf(s));
}

__global__ void __launch_bounds__(256) loss_reduce_kernel(const float* __restrict__ nll,
                                                          float* __restrict__ out) {
    float s = 0.0f;
    for (int i = threadIdx.x; i < cM; i += 256) s += nll[i];
    s = blockReduceSum(s);
    if (threadIdx.x == 0) *out = s / (float)cM;
}

// ---------------------------------------------------------------------------
// Launch
// ---------------------------------------------------------------------------
template<typename T> static T* sym(const void* s) {
    void* p; cudaGetSymbolAddress(&p, s); return (T*)p;
}

using bf16 = __nv_bfloat16;

//               NT  BT    BIAS  RES   GELU  WC    WPL   ZM SWAP
#define GQKV  gemm_u<128,true ,false,false,false,false,false,2,false>
#define GHEAD gemm_u<128,true ,false,false,false,true ,false,0,true >
#define GPROJ gemm_u<96 ,true ,false,true ,false,true ,false,0,false>
#define GFC   gemm_u<128,true ,true ,false,true ,false,true ,0,false>
#define GOUT  gemm_u<96 ,true ,true ,true ,false,true ,false,0,false>

extern "C" void kernel_launch(void* const* d_in, const int* in_sizes, int n_in,
                              void* d_out, int out_size) {
    const int*   idx    = (const int*)  d_in[0];
    const int*   tgt    = (const int*)  d_in[1];
    const float* wte    = (const float*)d_in[2];
    const float* wpe    = (const float*)d_in[3];
    const float* ln1_g  = (const float*)d_in[4];
    const float* ln1_b  = (const float*)d_in[5];
    const float* w_attn = (const float*)d_in[6];
    const float* w_proj = (const float*)d_in[7];
    const float* ln2_g  = (const float*)d_in[8];
    const float* ln2_b  = (const float*)d_in[9];
    const float* w_fc   = (const float*)d_in[10];
    const float* b_fc   = (const float*)d_in[11];
    const float* w_out  = (const float*)d_in[12];
    const float* b_out  = (const float*)d_in[13];
    const float* lnf_g  = (const float*)d_in[14];
    const float* lnf_b  = (const float*)d_in[15];
    const float* w_head = (const float*)d_in[16];
    float* logits = (float*)d_out;

    float* x   = sym<float>(g_x);
    float* nll = sym<float>(g_nll);
    bf16 *lnh = sym<bf16>(g_ln_h), *lnl = sym<bf16>(g_ln_l);
    bf16 *yh  = sym<bf16>(g_y_h),  *yl  = sym<bf16>(g_y_l);
    bf16 *fch = sym<bf16>(g_fc_h), *fcl = sym<bf16>(g_fc_l);
    bf16 *qh  = sym<bf16>(g_q_h),  *ql  = sym<bf16>(g_q_l);
    bf16 *kh  = sym<bf16>(g_k_h),  *kl  = sym<bf16>(g_k_l);
    bf16 *vh  = sym<bf16>(g_v_h),  *vl  = sym<bf16>(g_v_l);
    bf16 *wah = sym<bf16>(g_wa_h), *wal = sym<bf16>(g_wa_l);
    bf16 *wph = sym<bf16>(g_wp_h), *wpl = sym<bf16>(g_wp_l);
    bf16 *wfh = sym<bf16>(g_wf_h), *wfl = sym<bf16>(g_wf_l);
    bf16 *woh = sym<bf16>(g_wo_h), *wol = sym<bf16>(g_wo_l);
    bf16 *whh = sym<bf16>(g_wh_h), *whl = sym<bf16>(g_wh_l);

    constexpr int SM128T = Geom<128, true>::SMEM;
    constexpr int SM96T  = Geom<96,  true>::SMEM;

    cudaFuncSetAttribute((const void*)GQKV,  cudaFuncAttributeMaxDynamicSharedMemorySize, SM128T);
    cudaFuncSetAttribute((const void*)GHEAD, cudaFuncAttributeMaxDynamicSharedMemorySize, SM128T);
    cudaFuncSetAttribute((const void*)GPROJ, cudaFuncAttributeMaxDynamicSharedMemorySize, SM96T);
    cudaFuncSetAttribute((const void*)GFC,   cudaFuncAttributeMaxDynamicSharedMemorySize, SM128T);
    cudaFuncSetAttribute((const void*)GOUT,  cudaFuncAttributeMaxDynamicSharedMemorySize, SM96T);
    cudaFuncSetAttribute((const void*)flash_kernel,
                         cudaFuncAttributeMaxDynamicSharedMemorySize, FLASH_SMEM);

    split_kernel<<<cL * cD * cD3 / 512, 256>>>(w_attn, wah, wal, cL * cD * cD3 / 2);
    split_kernel<<<cL * cD * cD  / 512, 256>>>(w_proj, wph, wpl, cL * cD * cD  / 2);
    split_kernel<<<cL * cD * cDF / 512, 256>>>(w_fc,   wfh, wfl, cL * cD * cDF / 2);
    split_kernel<<<cL * cDF * cD / 512, 256>>>(w_out,  woh, wol, cL * cDF * cD / 2);
    split_kernel<<<cD * cV       / 512, 256>>>(w_head, whh, whl, cD * cV       / 2);

    embed_kernel<<<(cM * cD) / 256, 256>>>(idx, wte, wpe, x);

    for (int l = 0; l < cL; l++) {
        ln_kernel<<<cM, 256>>>(x, ln1_g + l * cD, ln1_b + l * cD, lnh, lnl);
        // qkv GEMM scatters directly into per-head q/k/v hi/lo planes
        GQKV<<<dim3(cD3 / 128, cM / 128, 1), 256, SM128T>>>(
            lnh, lnl, wah + (size_t)l * cD * cD3, wal + (size_t)l * cD * cD3,
            nullptr, nullptr, nullptr, qh, ql, kh, kl, vh, vl, cD3, cD, cD3, 0, 0, 0);
        flash_kernel<<<dim3(cT / 128, cZ), 256, FLASH_SMEM>>>(
            qh, ql, kh, kl, vh, vl, yh, yl);
        GPROJ<<<dim3(cD / 96, cM / 128, 1), 256, SM96T>>>(
            yh, yl, wph + (size_t)l * cD * cD, wpl + (size_t)l * cD * cD,
            nullptr, x, x, nullptr, nullptr, nullptr, nullptr, nullptr, nullptr,
            cD, cD, cD, 0, 0, 0);
        ln_kernel<<<cM, 256>>>(x, ln2_g + l * cD, ln2_b + l * cD, lnh, lnl);
        GFC<<<dim3(cDF / 128, cM / 128, 1), 256, SM128T>>>(
            lnh, lnl, wfh + (size_t)l * cD * cDF, wfl + (size_t)l * cD * cDF,
            b_fc + l * cDF, nullptr, nullptr, fch, fcl, nullptr, nullptr, nullptr, nullptr,
            cDF, cD, cDF, 0, 0, 0);
        GOUT<<<dim3(cD / 96, cM / 128, 1), 256, SM96T>>>(
            fch, fcl, woh + (size_t)l * cDF * cD, wol + (size_t)l * cDF * cD,
            b_out + l * cD, x, x, nullptr, nullptr, nullptr, nullptr, nullptr, nullptr,
            cD, cDF, cD, 0, 0, 0);
    }

    ln_kernel<<<cM, 256>>>(x, lnf_g, lnf_b, lnh, lnl);
    // head GEMM: x = M-major so a wave reuses B slices out of L2
    GHEAD<<<dim3(cM / 128, cV / 128, 1), 256, SM128T>>>(
        lnh, lnl, whh, whl, nullptr, nullptr, logits, nullptr, nullptr,
        nullptr, nullptr, nullptr, nullptr, cV, cD, cV, 0, 0, 0);

    if (out_size >= cM * cV + 1) {
        loss_row_kernel<<<cM, 256>>>(logits, tgt, nll);
        loss_reduce_kernel<<<1, 256>>>(nll, logits + (size_t)cM * cV);
    }
}

// round 8
// speedup vs baseline: 3.8487x; 1.1014x over previous
#include <cuda_runtime.h>
#include <cuda_bf16.h>
#include <math.h>
#include <stdint.h>

// ---------------------------------------------------------------------------
// Problem constants
// ---------------------------------------------------------------------------
constexpr int cV  = 32000;
constexpr int cD  = 768;
constexpr int cH  = 12;
constexpr int cL  = 8;
constexpr int cT  = 1024;
constexpr int cB  = 4;
constexpr int cHD = cD / cH;          // 64
constexpr int cM  = cB * cT;          // 4096
constexpr int cD3 = 3 * cD;           // 2304
constexpr int cDF = 4 * cD;           // 3072
constexpr int cZ  = cB * cH;          // 48 heads
constexpr size_t cQH = (size_t)cT * cHD;       // 65536 per head

// ---------------------------------------------------------------------------
// Scratch (device globals — no allocation allowed)
// ---------------------------------------------------------------------------
__device__ float g_x  [cM * cD];
__device__ float g_nll[cM];

__device__ __nv_bfloat16 g_ln_h[cM * cD],  g_ln_l[cM * cD];
__device__ __nv_bfloat16 g_y_h [cM * cD],  g_y_l [cM * cD];
__device__ __nv_bfloat16 g_fc_h[cM * cDF], g_fc_l[cM * cDF];
__device__ __nv_bfloat16 g_q_h [cZ * cT * cHD], g_q_l [cZ * cT * cHD];
__device__ __nv_bfloat16 g_k_h [cZ * cT * cHD], g_k_l [cZ * cT * cHD];
__device__ __nv_bfloat16 g_v_h [cZ * cT * cHD], g_v_l [cZ * cT * cHD];
__device__ __nv_bfloat16 g_wa_h[cL * cD * cD3], g_wa_l[cL * cD * cD3];
__device__ __nv_bfloat16 g_wp_h[cL * cD * cD],  g_wp_l[cL * cD * cD];
__device__ __nv_bfloat16 g_wf_h[cL * cD * cDF], g_wf_l[cL * cD * cDF];
__device__ __nv_bfloat16 g_wo_h[cL * cDF * cD], g_wo_l[cL * cDF * cD];
__device__ __nv_bfloat16 g_wh_h[cD * cV],       g_wh_l[cD * cV];

// ---------------------------------------------------------------------------
// PTX helpers
// ---------------------------------------------------------------------------
__device__ __forceinline__ void cp_async16(uint32_t saddr, const void* gptr) {
    asm volatile("cp.async.cg.shared.global [%0], [%1], 16;"
                 :: "r"(saddr), "l"(gptr));
}
#define CP_COMMIT() asm volatile("cp.async.commit_group;" ::: "memory")
#define CP_WAIT0()  asm volatile("cp.async.wait_group 0;" ::: "memory")
#define CP_WAIT1()  asm volatile("cp.async.wait_group 1;" ::: "memory")

__device__ __forceinline__ void ldsm_x4(uint32_t* r, uint32_t addr) {
    asm volatile("ldmatrix.sync.aligned.m8n8.x4.shared.b16 {%0,%1,%2,%3}, [%4];"
        : "=r"(r[0]), "=r"(r[1]), "=r"(r[2]), "=r"(r[3]) : "r"(addr));
}
__device__ __forceinline__ void ldsm_x4_t(uint32_t* r, uint32_t addr) {
    asm volatile("ldmatrix.sync.aligned.m8n8.x4.trans.shared.b16 {%0,%1,%2,%3}, [%4];"
        : "=r"(r[0]), "=r"(r[1]), "=r"(r[2]), "=r"(r[3]) : "r"(addr));
}
__device__ __forceinline__ void mma_bf16(float* d, const uint32_t* a,
                                         uint32_t b0, uint32_t b1) {
    asm volatile(
        "mma.sync.aligned.m16n8k16.row.col.f32.bf16.bf16.f32 "
        "{%0,%1,%2,%3},{%4,%5,%6,%7},{%8,%9},{%0,%1,%2,%3};"
        : "+f"(d[0]), "+f"(d[1]), "+f"(d[2]), "+f"(d[3])
        : "r"(a[0]), "r"(a[1]), "r"(a[2]), "r"(a[3]), "r"(b0), "r"(b1));
}

__device__ __forceinline__ uint32_t pack_bf16x2(float lo, float hi) {
    uint32_t d;
    asm("cvt.rn.bf16x2.f32 %0, %1, %2;" : "=r"(d) : "f"(hi), "f"(lo));
    return d;
}
__device__ __forceinline__ void split2(float v0, float v1,
                                       uint32_t& hp, uint32_t& lp) {
    hp = pack_bf16x2(v0, v1);
    float h0 = __uint_as_float(hp << 16);
    float h1 = __uint_as_float(hp & 0xffff0000u);
    lp = pack_bf16x2(v0 - h0, v1 - h1);
}

__device__ __forceinline__ float gelu_exact(float x) {
    return 0.5f * x * (1.0f + erff(x * 0.70710678118654752f));
}

// ---------------------------------------------------------------------------
// Generalized split-bf16 GEMM (3-mma Markidis): C = A @ W(op)
// 3-stage cp.async pipeline, ONE __syncthreads per k-iteration.
// ---------------------------------------------------------------------------
template<int NT, bool BTRANS>
struct Geom {
    static constexpr int SBb = BTRANS ? (2 * NT + 16) : 80;
    static constexpr int BSZ = BTRANS ? 32 * SBb : NT * 80;
    static constexpr int AL  = 10240;
    static constexpr int BH  = 20480;
    static constexpr int BL  = BH + BSZ;
    static constexpr int BUF = BH + 2 * BSZ;
    static constexpr int SMEM = 3 * BUF;          // 3 stages
};

template<int NT, bool BTRANS, bool BIAS, bool RES, bool GELU,
         bool WC, bool WPL, int ZMODE, bool SWAPXY>
__global__ void __launch_bounds__(256, 2) gemm_u(
    const __nv_bfloat16* __restrict__ Ah, const __nv_bfloat16* __restrict__ Al,
    const __nv_bfloat16* __restrict__ Wh, const __nv_bfloat16* __restrict__ Wl,
    const float* __restrict__ bias, const float* __restrict__ Rres,
    float* __restrict__ C,
    __nv_bfloat16* __restrict__ Ch, __nv_bfloat16* __restrict__ Cl,
    __nv_bfloat16* __restrict__ Dh, __nv_bfloat16* __restrict__ Dl,
    __nv_bfloat16* __restrict__ Eh, __nv_bfloat16* __restrict__ El,
    int N, int K, int ldc, size_t sA, size_t sW, size_t sC) {

    using G = Geom<NT, BTRANS>;
    extern __shared__ char smem[];
    const uint32_t sb = (uint32_t)__cvta_generic_to_shared(smem);

    const int m0 = (SWAPXY ? blockIdx.x : blockIdx.y) * 128;
    const int n0 = (SWAPXY ? blockIdx.y : blockIdx.x) * NT;

    const int z = blockIdx.z;
    Ah += z * sA; Al += z * sA;
    Wh += z * sW; Wl += z * sW;
    const size_t cofs = z * sC;

    const int tid  = threadIdx.x;
    const int lane = tid & 31;
    const int wid  = tid >> 5;
    const int gr   = lane >> 2;
    const int tg   = lane & 3;
    const int mw   = (wid & 3) * 32;
    const int nw   = (wid >> 2) * (NT / 2);
    const int lr   = lane & 7, lt = lane >> 3;

    const uint32_t aoff = (uint32_t)((mw + (lt & 1) * 8 + lr) * 80 + (lt >> 1) * 16);
    uint32_t boff;
    if (BTRANS) boff = (uint32_t)(((lt & 1) * 8 + lr) * G::SBb + (nw + (lt >> 1) * 8) * 2);
    else        boff = (uint32_t)((nw + (lt >> 1) * 8 + lr) * 80 + (lt & 1) * 16);

    constexpr int NTW = NT / 16;
    float acc[2][NTW][4];
    #pragma unroll
    for (int mi = 0; mi < 2; mi++)
        #pragma unroll
        for (int nt = 0; nt < NTW; nt++)
            #pragma unroll
            for (int q = 0; q < 4; q++) acc[mi][nt][q] = 0.0f;

    const int NK = K >> 5;

    auto stage = [&](int ib, int buf) {
        const int k0 = ib << 5;
        const uint32_t bb = sb + buf * G::BUF;
        #pragma unroll
        for (int j = 0; j < 2; j++) {
            int c = tid + 256 * j;
            int row = c >> 2, seg = c & 3;
            uint32_t d = bb + (uint32_t)(row * 80 + seg * 16);
            size_t s = (size_t)(m0 + row) * K + k0 + seg * 8;
            cp_async16(d, Ah + s);
            cp_async16(d + G::AL, Al + s);
        }
        if (BTRANS) {
            constexpr int SEGS = NT / 8;
            constexpr int BCH = 32 * SEGS;
            #pragma unroll
            for (int j = 0; j < (BCH + 255) / 256; j++) {
                int c = tid + 256 * j;
                if ((BCH % 256 == 0) || c < BCH) {
                    int kr = c / SEGS, seg = c - kr * SEGS;
                    uint32_t d = bb + G::BH + (uint32_t)(kr * G::SBb + seg * 16);
                    size_t s = (size_t)(k0 + kr) * N + n0 + seg * 8;
                    cp_async16(d, Wh + s);
                    cp_async16(d + G::BSZ, Wl + s);
                }
            }
        } else {
            constexpr int BCH = NT * 4;
            #pragma unroll
            for (int j = 0; j < (BCH + 255) / 256; j++) {
                int c = tid + 256 * j;
                if ((BCH % 256 == 0) || c < BCH) {
                    int row = c >> 2, seg = c & 3;
                    uint32_t d = bb + G::BH + (uint32_t)(row * 80 + seg * 16);
                    size_t s = (size_t)(n0 + row) * K + k0 + seg * 8;
                    cp_async16(d, Wh + s);
                    cp_async16(d + G::BSZ, Wl + s);
                }
            }
        }
    };

    stage(0, 0); CP_COMMIT();
    stage(1, 1); CP_COMMIT();

    for (int ib = 0; ib < NK; ib++) {
        const int buf = ib % 3;
        CP_WAIT1();
        __syncthreads();

        const uint32_t base = sb + buf * G::BUF;
        const uint32_t aHb = base + aoff;
        const uint32_t aLb = base + G::AL + aoff;
        const uint32_t bHb = base + G::BH + boff;
        const uint32_t bLb = base + G::BL + boff;

        #pragma unroll
        for (int ks = 0; ks < 2; ks++) {
            uint32_t ahi[2][4], alo[2][4];
            ldsm_x4(ahi[0], aHb + ks * 32);
            ldsm_x4(ahi[1], aHb + 1280 + ks * 32);
            ldsm_x4(alo[0], aLb + ks * 32);
            ldsm_x4(alo[1], aLb + 1280 + ks * 32);
            #pragma unroll
            for (int g = 0; g < NT / 32; g++) {
                uint32_t bh[4], bl[4];
                if (BTRANS) {
                    ldsm_x4_t(bh, bHb + ks * (16 * G::SBb) + g * 32);
                    ldsm_x4_t(bl, bLb + ks * (16 * G::SBb) + g * 32);
                } else {
                    ldsm_x4(bh, bHb + ks * 32 + g * 1280);
                    ldsm_x4(bl, bLb + ks * 32 + g * 1280);
                }
                #pragma unroll
                for (int mi = 0; mi < 2; mi++) {
                    const int nt = g * 2;
                    mma_bf16(acc[mi][nt],     ahi[mi], bh[0], bh[1]);
                    mma_bf16(acc[mi][nt],     ahi[mi], bl[0], bl[1]);
                    mma_bf16(acc[mi][nt],     alo[mi], bh[0], bh[1]);
                    mma_bf16(acc[mi][nt + 1], ahi[mi], bh[2], bh[3]);
                    mma_bf16(acc[mi][nt + 1], ahi[mi], bl[2], bl[3]);
                    mma_bf16(acc[mi][nt + 1], alo[mi], bh[2], bh[3]);
                }
            }
        }
        // Safe without a second barrier: buffer (ib+2)%3 was consumed in
        // iteration ib-1; every warp passed this iteration's __syncthreads,
        // which happens-after all of iteration ib-1's compute.
        if (ib + 2 < NK) stage(ib + 2, (ib + 2) % 3);
        CP_COMMIT();
    }

    #pragma unroll
    for (int mi = 0; mi < 2; mi++) {
        const int r0 = m0 + mw + mi * 16 + gr;
        #pragma unroll
        for (int nt = 0; nt < NTW; nt++) {
            const int c0 = n0 + nw + nt * 8 + tg * 2;
            float2 v0 = make_float2(acc[mi][nt][0], acc[mi][nt][1]);
            float2 v1 = make_float2(acc[mi][nt][2], acc[mi][nt][3]);
            if (BIAS) {
                float2 bv = *(const float2*)(bias + c0);
                v0.x += bv.x; v0.y += bv.y;
                v1.x += bv.x; v1.y += bv.y;
            }
            if (GELU) {
                v0.x = gelu_exact(v0.x); v0.y = gelu_exact(v0.y);
                v1.x = gelu_exact(v1.x); v1.y = gelu_exact(v1.y);
            }
            if (ZMODE == 2) {
                const int sec = n0 / cD;
                const int cc  = c0 - sec * cD;
                const int h   = cc >> 6, d = cc & 63;
                const float scale = (sec == 0) ? 0.125f : 1.0f;
                uint32_t* ph = (uint32_t*)(sec == 0 ? Ch : sec == 1 ? Dh : Eh);
                uint32_t* pl = (uint32_t*)(sec == 0 ? Cl : sec == 1 ? Dl : El);
                const int b = r0 >> 10, t0 = r0 & 1023;
                size_t zb = (size_t)(b * cH + h) * 1024;
                size_t oA = (zb + t0)     * 32 + (d >> 1);
                size_t oB = (zb + t0 + 8) * 32 + (d >> 1);
                uint32_t hp, lp;
                split2(v0.x * scale, v0.y * scale, hp, lp);
                ph[oA] = hp; pl[oA] = lp;
                split2(v1.x * scale, v1.y * scale, hp, lp);
                ph[oB] = hp; pl[oB] = lp;
            } else {
                size_t o0 = cofs + (size_t)r0 * ldc + c0;
                size_t o1 = cofs + (size_t)(r0 + 8) * ldc + c0;
                if (RES) {
                    float2 a0 = *(const float2*)(Rres + o0);
                    float2 a1 = *(const float2*)(Rres + o1);
                    v0.x += a0.x; v0.y += a0.y;
                    v1.x += a1.x; v1.y += a1.y;
                }
                if (WC) {
                    *(float2*)(C + o0) = v0;
                    *(float2*)(C + o1) = v1;
                }
                if (WPL) {
                    uint32_t hp, lp;
                    split2(v0.x, v0.y, hp, lp);
                    ((uint32_t*)Ch)[o0 >> 1] = hp;
                    ((uint32_t*)Cl)[o0 >> 1] = lp;
                    split2(v1.x, v1.y, hp, lp);
                    ((uint32_t*)Ch)[o1 >> 1] = hp;
                    ((uint32_t*)Cl)[o1 >> 1] = lp;
                }
            }
        }
    }
}

// ---------------------------------------------------------------------------
// Fused flash attention (split-bf16 mma, online softmax)
// ---------------------------------------------------------------------------
constexpr int F_SQ   = 144;
constexpr int F_PL   = 128 * F_SQ;
constexpr int F_KV0  = 2 * F_PL;
constexpr int F_KVSZ = 4 * F_PL;
constexpr int FLASH_SMEM = 2 * F_PL + 2 * F_KVSZ;  // 184320

__global__ void __launch_bounds__(256, 1) flash_kernel(
    const __nv_bfloat16* __restrict__ qh, const __nv_bfloat16* __restrict__ ql,
    const __nv_bfloat16* __restrict__ kh, const __nv_bfloat16* __restrict__ kl,
    const __nv_bfloat16* __restrict__ vh, const __nv_bfloat16* __restrict__ vl,
    __nv_bfloat16* __restrict__ yh, __nv_bfloat16* __restrict__ yl) {

    extern __shared__ char smem[];
    const uint32_t sb = (uint32_t)__cvta_generic_to_shared(smem);
    const int qb = blockIdx.x;
    const int z  = blockIdx.y;
    const int q0 = qb * 128;
    const int tid  = threadIdx.x;
    const int lane = tid & 31;
    const int wid  = tid >> 5;
    const int gr   = lane >> 2;
    const int tg   = lane & 3;
    const int wq   = wid * 16;
    const int lr   = lane & 7, lt = lane >> 3;

    const __nv_bfloat16* qhz = qh + (size_t)z * cQH;
    const __nv_bfloat16* qlz = ql + (size_t)z * cQH;
    const __nv_bfloat16* khz = kh + (size_t)z * cQH;
    const __nv_bfloat16* klz = kl + (size_t)z * cQH;
    const __nv_bfloat16* vhz = vh + (size_t)z * cQH;
    const __nv_bfloat16* vlz = vl + (size_t)z * cQH;

    #pragma unroll
    for (int j = 0; j < 4; j++) {
        int c = tid + 256 * j;
        int row = c >> 3, seg = c & 7;
        uint32_t d = sb + (uint32_t)(row * F_SQ + seg * 16);
        size_t s = (size_t)(q0 + row) * cHD + seg * 8;
        cp_async16(d, qhz + s);
        cp_async16(d + F_PL, qlz + s);
    }
    auto stageKV = [&](int kb, int buf) {
        const uint32_t bb = sb + F_KV0 + buf * F_KVSZ;
        #pragma unroll
        for (int j = 0; j < 4; j++) {
            int c = tid + 256 * j;
            int row = c >> 3, seg = c & 7;
            uint32_t d = bb + (uint32_t)(row * F_SQ + seg * 16);
            size_t s = (size_t)(kb * 128 + row) * cHD + seg * 8;
            cp_async16(d, khz + s);
            cp_async16(d + F_PL, klz + s);
            cp_async16(d + 2 * F_PL, vhz + s);
            cp_async16(d + 3 * F_PL, vlz + s);
        }
    };

    stageKV(0, 0);
    CP_COMMIT();
    if (qb >= 1) { stageKV(1, 1); CP_COMMIT(); }

    float mrow[2] = { -INFINITY, -INFINITY };
    float lrow[2] = { 0.0f, 0.0f };
    float oacc[8][4];
    #pragma unroll
    for (int nt = 0; nt < 8; nt++)
        #pragma unroll
        for (int q = 0; q < 4; q++) oacc[nt][q] = 0.0f;

    uint32_t qfh[4][4], qfl[4][4];
    bool qloaded = false;

    const uint32_t q_aoff = (uint32_t)((wq + (lt & 1) * 8 + lr) * F_SQ + (lt >> 1) * 16);
    const uint32_t k_boff = (uint32_t)(((lt >> 1) * 8 + lr) * F_SQ + (lt & 1) * 16);
    const uint32_t v_boff = (uint32_t)(((lt & 1) * 8 + lr) * F_SQ + (lt >> 1) * 16);

    for (int kb = 0; kb <= qb; kb++) {
        if (kb < qb) { CP_WAIT1(); } else { CP_WAIT0(); }
        __syncthreads();

        if (!qloaded) {
            #pragma unroll
            for (int ks = 0; ks < 4; ks++) {
                ldsm_x4(qfh[ks], sb + q_aoff + ks * 32);
                ldsm_x4(qfl[ks], sb + F_PL + q_aoff + ks * 32);
            }
            qloaded = true;
        }

        const uint32_t kvb = sb + F_KV0 + (kb & 1) * F_KVSZ;

        float s[16][4];
        #pragma unroll
        for (int nt = 0; nt < 16; nt++)
            #pragma unroll
            for (int q = 0; q < 4; q++) s[nt][q] = 0.0f;

        #pragma unroll
        for (int ks = 0; ks < 4; ks++) {
            #pragma unroll
            for (int g = 0; g < 8; g++) {
                uint32_t bh[4], bl[4];
                uint32_t addr = kvb + k_boff + (uint32_t)(g * 16 * F_SQ) + ks * 32;
                ldsm_x4(bh, addr);
                ldsm_x4(bl, addr + F_PL);
                const int nt = g * 2;
                mma_bf16(s[nt],     qfh[ks], bh[0], bh[1]);
                mma_bf16(s[nt],     qfh[ks], bl[0], bl[1]);
                mma_bf16(s[nt],     qfl[ks], bh[0], bh[1]);
                mma_bf16(s[nt + 1], qfh[ks], bh[2], bh[3]);
                mma_bf16(s[nt + 1], qfh[ks], bl[2], bl[3]);
                mma_bf16(s[nt + 1], qfl[ks], bh[2], bh[3]);
            }
        }

        if (kb == qb) {
            const int r0 = wq + gr, r1 = wq + gr + 8;
            #pragma unroll
            for (int nt = 0; nt < 16; nt++) {
                const int c0 = nt * 8 + tg * 2;
                if (c0     > r0) s[nt][0] = -1e30f;
                if (c0 + 1 > r0) s[nt][1] = -1e30f;
                if (c0     > r1) s[nt][2] = -1e30f;
                if (c0 + 1 > r1) s[nt][3] = -1e30f;
            }
        }

        float mn0 = -INFINITY, mn1 = -INFINITY;
        #pragma unroll
        for (int nt = 0; nt < 16; nt++) {
            mn0 = fmaxf(mn0, fmaxf(s[nt][0], s[nt][1]));
            mn1 = fmaxf(mn1, fmaxf(s[nt][2], s[nt][3]));
        }
        mn0 = fmaxf(mn0, __shfl_xor_sync(0xffffffffu, mn0, 1));
        mn0 = fmaxf(mn0, __shfl_xor_sync(0xffffffffu, mn0, 2));
        mn1 = fmaxf(mn1, __shfl_xor_sync(0xffffffffu, mn1, 1));
        mn1 = fmaxf(mn1, __shfl_xor_sync(0xffffffffu, mn1, 2));
        float mnew0 = fmaxf(mrow[0], mn0);
        float mnew1 = fmaxf(mrow[1], mn1);
        float al0 = __expf(mrow[0] - mnew0);
        float al1 = __expf(mrow[1] - mnew1);
        mrow[0] = mnew0; mrow[1] = mnew1;

        float rs0 = 0.0f, rs1 = 0.0f;
        #pragma unroll
        for (int nt = 0; nt < 16; nt++) {
            s[nt][0] = __expf(s[nt][0] - mnew0);
            s[nt][1] = __expf(s[nt][1] - mnew0);
            s[nt][2] = __expf(s[nt][2] - mnew1);
            s[nt][3] = __expf(s[nt][3] - mnew1);
            rs0 += s[nt][0] + s[nt][1];
            rs1 += s[nt][2] + s[nt][3];
        }
        rs0 += __shfl_xor_sync(0xffffffffu, rs0, 1);
        rs0 += __shfl_xor_sync(0xffffffffu, rs0, 2);
        rs1 += __shfl_xor_sync(0xffffffffu, rs1, 1);
        rs1 += __shfl_xor_sync(0xffffffffu, rs1, 2);
        lrow[0] = lrow[0] * al0 + rs0;
        lrow[1] = lrow[1] * al1 + rs1;

        #pragma unroll
        for (int nt = 0; nt < 8; nt++) {
            oacc[nt][0] *= al0; oacc[nt][1] *= al0;
            oacc[nt][2] *= al1; oacc[nt][3] *= al1;
        }

        #pragma unroll
        for (int ks = 0; ks < 8; ks++) {
            uint32_t pah[4], pal[4];
            uint32_t h0, l0;
            split2(s[2*ks][0],   s[2*ks][1],   h0, l0); pah[0] = h0; pal[0] = l0;
            split2(s[2*ks][2],   s[2*ks][3],   h0, l0); pah[1] = h0; pal[1] = l0;
            split2(s[2*ks+1][0], s[2*ks+1][1], h0, l0); pah[2] = h0; pal[2] = l0;
            split2(s[2*ks+1][2], s[2*ks+1][3], h0, l0); pah[3] = h0; pal[3] = l0;
            #pragma unroll
            for (int g = 0; g < 4; g++) {
                uint32_t bvh[4], bvl[4];
                uint32_t addr = kvb + 2 * F_PL + v_boff
                              + (uint32_t)(ks * 16 * F_SQ) + g * 32;
                ldsm_x4_t(bvh, addr);
                ldsm_x4_t(bvl, addr + F_PL);
                const int nt = g * 2;
                mma_bf16(oacc[nt],     pah, bvh[0], bvh[1]);
                mma_bf16(oacc[nt],     pah, bvl[0], bvl[1]);
                mma_bf16(oacc[nt],     pal, bvh[0], bvh[1]);
                mma_bf16(oacc[nt + 1], pah, bvh[2], bvh[3]);
                mma_bf16(oacc[nt + 1], pah, bvl[2], bvl[3]);
                mma_bf16(oacc[nt + 1], pal, bvh[2], bvh[3]);
            }
        }

        __syncthreads();
        if (kb + 2 <= qb) { stageKV(kb + 2, kb & 1); CP_COMMIT(); }
    }

    const float inv0 = 1.0f / lrow[0];
    const float inv1 = 1.0f / lrow[1];
    const int b = z / cH, h = z % cH;
    const int r0 = b * cT + q0 + wq + gr;
    #pragma unroll
    for (int nt = 0; nt < 8; nt++) {
        const int c0 = h * cHD + nt * 8 + tg * 2;
        uint32_t hp, lp;
        split2(oacc[nt][0] * inv0, oacc[nt][1] * inv0, hp, lp);
        size_t o0 = ((size_t)r0 * cD + c0) >> 1;
        ((uint32_t*)yh)[o0] = hp; ((uint32_t*)yl)[o0] = lp;
        split2(oacc[nt][2] * inv1, oacc[nt][3] * inv1, hp, lp);
        size_t o1 = ((size_t)(r0 + 8) * cD + c0) >> 1;
        ((uint32_t*)yh)[o1] = hp; ((uint32_t*)yl)[o1] = lp;
    }
}

// ---------------------------------------------------------------------------
// Block reductions (blockDim.x == 256)
// ---------------------------------------------------------------------------
__device__ __forceinline__ float blockReduceSum(float v) {
    __shared__ float sh[8];
    #pragma unroll
    for (int o = 16; o; o >>= 1) v += __shfl_xor_sync(0xffffffffu, v, o);
    int w = threadIdx.x >> 5, l = threadIdx.x & 31;
    __syncthreads();
    if (l == 0) sh[w] = v;
    __syncthreads();
    if (w == 0) {
        v = (l < 8) ? sh[l] : 0.0f;
        #pragma unroll
        for (int o = 16; o; o >>= 1) v += __shfl_xor_sync(0xffffffffu, v, o);
        if (l == 0) sh[0] = v;
    }
    __syncthreads();
    return sh[0];
}

__device__ __forceinline__ float blockReduceMax(float v) {
    __shared__ float sh[8];
    #pragma unroll
    for (int o = 16; o; o >>= 1) v = fmaxf(v, __shfl_xor_sync(0xffffffffu, v, o));
    int w = threadIdx.x >> 5, l = threadIdx.x & 31;
    __syncthreads();
    if (l == 0) sh[w] = v;
    __syncthreads();
    if (w == 0) {
        v = (l < 8) ? sh[l] : -INFINITY;
        #pragma unroll
        for (int o = 16; o; o >>= 1) v = fmaxf(v, __shfl_xor_sync(0xffffffffu, v, o));
        if (l == 0) sh[0] = v;
    }
    __syncthreads();
    return sh[0];
}

// ---------------------------------------------------------------------------
// Small kernels
// ---------------------------------------------------------------------------
__global__ void __launch_bounds__(256) split_kernel(const float* __restrict__ src,
                                                    __nv_bfloat16* __restrict__ hi,
                                                    __nv_bfloat16* __restrict__ lo,
                                                    int nquads) {
    int i = blockIdx.x * blockDim.x + threadIdx.x;
    if (i >= nquads) return;
    float4 v = *(const float4*)(src + (size_t)i * 4);
    uint32_t h0, l0, h1, l1;
    split2(v.x, v.y, h0, l0);
    split2(v.z, v.w, h1, l1);
    ((uint2*)hi)[i] = make_uint2(h0, h1);
    ((uint2*)lo)[i] = make_uint2(l0, l1);
}

__global__ void embed_kernel(const int* __restrict__ idx,
                             const float* __restrict__ wte,
                             const float* __restrict__ wpe,
                             float* __restrict__ x) {
    int i = blockIdx.x * blockDim.x + threadIdx.x;
    int row = i / cD;
    int d   = i - row * cD;
    int t   = row & (cT - 1);
    int tok = idx[row];
    x[i] = wte[(size_t)tok * cD + d] + wpe[(size_t)t * cD + d];
}

__global__ void __launch_bounds__(256) ln_kernel(const float* __restrict__ x,
                                                 const float* __restrict__ g,
                                                 const float* __restrict__ b,
                                                 __nv_bfloat16* __restrict__ oh,
                                                 __nv_bfloat16* __restrict__ ol) {
    const int row = blockIdx.x;
    const float* xr = x + (size_t)row * cD;
    const int t = threadIdx.x;
    float v0 = xr[t], v1 = xr[t + 256], v2 = xr[t + 512];
    float s  = blockReduceSum(v0 + v1 + v2);
    float s2 = blockReduceSum(v0 * v0 + v1 * v1 + v2 * v2);
    const float inv = 1.0f / cD;
    float mu  = s * inv;
    float var = s2 * inv - mu * mu;
    float rs  = rsqrtf(var + 1e-5f);
    #pragma unroll
    for (int j = 0; j < 3; j++) {
        int d = t + j * 256;
        float val = (((j == 0) ? v0 : (j == 1) ? v1 : v2) - mu) * rs * g[d] + b[d];
        __nv_bfloat16 h = __float2bfloat16_rn(val);
        oh[(size_t)row * cD + d] = h;
        ol[(size_t)row * cD + d] = __float2bfloat16_rn(val - __bfloat162float(h));
    }
}

// single-pass online log-sum-exp loss per row
__global__ void __launch_bounds__(256) loss_row_kernel(const float* __restrict__ logits,
                                                       const int* __restrict__ tgt,
                                                       float* __restrict__ nll) {
    const int r = blockIdx.x;
    const float* lr = logits + (size_t)r * cV;
    float m = -INFINITY, s = 0.0f;
    for (int i = threadIdx.x; i < cV; i += 256) {
        float v = lr[i];
        float nm = fmaxf(m, v);
        s = s * __expf(m - nm) + __expf(v - nm);
        m = nm;
    }
    __shared__ float shm[8];
    float mx = blockReduceMax(m);
    float sadj = s * __expf(m - mx);
    float tot = blockReduceSum(sadj);
    (void)shm;
    if (threadIdx.x == 0)
        nll[r] = -(lr[tgt[r]] - mx - logf(tot));
}

__global__ void __launch_bounds__(256) loss_reduce_kernel(const float* __restrict__ nll,
                                                          float* __restrict__ out) {
    float s = 0.0f;
    for (int i = threadIdx.x; i < cM; i += 256) s += nll[i];
    s = blockReduceSum(s);
    if (threadIdx.x == 0) *out = s / (float)cM;
}

// ---------------------------------------------------------------------------
// Launch
// ---------------------------------------------------------------------------
template<typename T> static T* sym(const void* s) {
    void* p; cudaGetSymbolAddress(&p, s); return (T*)p;
}

using bf16 = __nv_bfloat16;

//               NT  BT    BIAS  RES   GELU  WC    WPL   ZM SWAP
#define GQKV  gemm_u<128,true ,false,false,false,false,false,2,false>
#define GHEAD gemm_u<128,true ,false,false,false,true ,false,0,true >
#define GPROJ gemm_u<96 ,true ,false,true ,false,true ,false,0,false>
#define GFC   gemm_u<128,true ,true ,false,true ,false,true ,0,false>
#define GOUT  gemm_u<96 ,true ,true ,true ,false,true ,false,0,false>

extern "C" void kernel_launch(void* const* d_in, const int* in_sizes, int n_in,
                              void* d_out, int out_size) {
    const int*   idx    = (const int*)  d_in[0];
    const int*   tgt    = (const int*)  d_in[1];
    const float* wte    = (const float*)d_in[2];
    const float* wpe    = (const float*)d_in[3];
    const float* ln1_g  = (const float*)d_in[4];
    const float* ln1_b  = (const float*)d_in[5];
    const float* w_attn = (const float*)d_in[6];
    const float* w_proj = (const float*)d_in[7];
    const float* ln2_g  = (const float*)d_in[8];
    const float* ln2_b  = (const float*)d_in[9];
    const float* w_fc   = (const float*)d_in[10];
    const float* b_fc   = (const float*)d_in[11];
    const float* w_out  = (const float*)d_in[12];
    const float* b_out  = (const float*)d_in[13];
    const float* lnf_g  = (const float*)d_in[14];
    const float* lnf_b  = (const float*)d_in[15];
    const float* w_head = (const float*)d_in[16];
    float* logits = (float*)d_out;

    float* x   = sym<float>(g_x);
    float* nll = sym<float>(g_nll);
    bf16 *lnh = sym<bf16>(g_ln_h), *lnl = sym<bf16>(g_ln_l);
    bf16 *yh  = sym<bf16>(g_y_h),  *yl  = sym<bf16>(g_y_l);
    bf16 *fch = sym<bf16>(g_fc_h), *fcl = sym<bf16>(g_fc_l);
    bf16 *qh  = sym<bf16>(g_q_h),  *ql  = sym<bf16>(g_q_l);
    bf16 *kh  = sym<bf16>(g_k_h),  *kl  = sym<bf16>(g_k_l);
    bf16 *vh  = sym<bf16>(g_v_h),  *vl  = sym<bf16>(g_v_l);
    bf16 *wah = sym<bf16>(g_wa_h), *wal = sym<bf16>(g_wa_l);
    bf16 *wph = sym<bf16>(g_wp_h), *wpl = sym<bf16>(g_wp_l);
    bf16 *wfh = sym<bf16>(g_wf_h), *wfl = sym<bf16>(g_wf_l);
    bf16 *woh = sym<bf16>(g_wo_h), *wol = sym<bf16>(g_wo_l);
    bf16 *whh = sym<bf16>(g_wh_h), *whl = sym<bf16>(g_wh_l);

    constexpr int SM128T = Geom<128, true>::SMEM;  // 113664
    constexpr int SM96T  = Geom<96,  true>::SMEM;  // 101376

    cudaFuncSetAttribute((const void*)GQKV,  cudaFuncAttributeMaxDynamicSharedMemorySize, SM128T);
    cudaFuncSetAttribute((const void*)GHEAD, cudaFuncAttributeMaxDynamicSharedMemorySize, SM128T);
    cudaFuncSetAttribute((const void*)GPROJ, cudaFuncAttributeMaxDynamicSharedMemorySize, SM96T);
    cudaFuncSetAttribute((const void*)GFC,   cudaFuncAttributeMaxDynamicSharedMemorySize, SM128T);
    cudaFuncSetAttribute((const void*)GOUT,  cudaFuncAttributeMaxDynamicSharedMemorySize, SM96T);
    cudaFuncSetAttribute((const void*)flash_kernel,
                         cudaFuncAttributeMaxDynamicSharedMemorySize, FLASH_SMEM);

    split_kernel<<<cL * cD * cD3 / 1024, 256>>>(w_attn, wah, wal, cL * cD * cD3 / 4);
    split_kernel<<<cL * cD * cD  / 1024, 256>>>(w_proj, wph, wpl, cL * cD * cD  / 4);
    split_kernel<<<cL * cD * cDF / 1024, 256>>>(w_fc,   wfh, wfl, cL * cD * cDF / 4);
    split_kernel<<<cL * cDF * cD / 1024, 256>>>(w_out,  woh, wol, cL * cDF * cD / 4);
    split_kernel<<<cD * cV       / 1024, 256>>>(w_head, whh, whl, cD * cV       / 4);

    embed_kernel<<<(cM * cD) / 256, 256>>>(idx, wte, wpe, x);

    for (int l = 0; l < cL; l++) {
        ln_kernel<<<cM, 256>>>(x, ln1_g + l * cD, ln1_b + l * cD, lnh, lnl);
        GQKV<<<dim3(cD3 / 128, cM / 128, 1), 256, SM128T>>>(
            lnh, lnl, wah + (size_t)l * cD * cD3, wal + (size_t)l * cD * cD3,
            nullptr, nullptr, nullptr, qh, ql, kh, kl, vh, vl, cD3, cD, cD3, 0, 0, 0);
        flash_kernel<<<dim3(cT / 128, cZ), 256, FLASH_SMEM>>>(
            qh, ql, kh, kl, vh, vl, yh, yl);
        GPROJ<<<dim3(cD / 96, cM / 128, 1), 256, SM96T>>>(
            yh, yl, wph + (size_t)l * cD * cD, wpl + (size_t)l * cD * cD,
            nullptr, x, x, nullptr, nullptr, nullptr, nullptr, nullptr, nullptr,
            cD, cD, cD, 0, 0, 0);
        ln_kernel<<<cM, 256>>>(x, ln2_g + l * cD, ln2_b + l * cD, lnh, lnl);
        GFC<<<dim3(cDF / 128, cM / 128, 1), 256, SM128T>>>(
            lnh, lnl, wfh + (size_t)l * cD * cDF, wfl + (size_t)l * cD * cDF,
            b_fc + l * cDF, nullptr, nullptr, fch, fcl, nullptr, nullptr, nullptr, nullptr,
            cDF, cD, cDF, 0, 0, 0);
        GOUT<<<dim3(cD / 96, cM / 128, 1), 256, SM96T>>>(
            fch, fcl, woh + (size_t)l * cDF * cD, wol + (size_t)l * cDF * cD,
            b_out + l * cD, x, x, nullptr, nullptr, nullptr, nullptr, nullptr, nullptr,
            cD, cDF, cD, 0, 0, 0);
    }

    ln_kernel<<<cM, 256>>>(x, lnf_g, lnf_b, lnh, lnl);
    GHEAD<<<dim3(cM / 128, cV / 128, 1), 256, SM128T>>>(
        lnh, lnl, whh, whl, nullptr, nullptr, logits, nullptr, nullptr,
        nullptr, nullptr, nullptr, nullptr, cV, cD, cV, 0, 0, 0);

    if (out_size >= cM * cV + 1) {
        loss_row_kernel<<<cM, 256>>>(logits, tgt, nll);
        loss_reduce_kernel<<<1, 256>>>(nll, logits + (size_t)cM * cV);
    }
}

// round 9
// speedup vs baseline: 3.8488x; 1.0000x over previous
#include <cuda_runtime.h>
#include <cuda_bf16.h>
#include <math.h>
#include <stdint.h>

// ---------------------------------------------------------------------------
// Problem constants
// ---------------------------------------------------------------------------
constexpr int cV  = 32000;
constexpr int cD  = 768;
constexpr int cH  = 12;
constexpr int cL  = 8;
constexpr int cT  = 1024;
constexpr int cB  = 4;
constexpr int cHD = cD / cH;          // 64
constexpr int cM  = cB * cT;          // 4096
constexpr int cD3 = 3 * cD;           // 2304
constexpr int cDF = 4 * cD;           // 3072
constexpr int cZ  = cB * cH;          // 48 heads
constexpr size_t cQH = (size_t)cT * cHD;       // 65536 per head

// ---------------------------------------------------------------------------
// Scratch (device globals — no allocation allowed)
// ---------------------------------------------------------------------------
__device__ float g_x  [cM * cD];
__device__ float g_nll[cM];

__device__ __nv_bfloat16 g_ln_h[cM * cD],  g_ln_l[cM * cD];
__device__ __nv_bfloat16 g_y_h [cM * cD],  g_y_l [cM * cD];
__device__ __nv_bfloat16 g_fc_h[cM * cDF], g_fc_l[cM * cDF];
__device__ __nv_bfloat16 g_q_h [cZ * cT * cHD], g_q_l [cZ * cT * cHD];
__device__ __nv_bfloat16 g_k_h [cZ * cT * cHD], g_k_l [cZ * cT * cHD];
__device__ __nv_bfloat16 g_v_h [cZ * cT * cHD], g_v_l [cZ * cT * cHD];
__device__ __nv_bfloat16 g_wa_h[cL * cD * cD3], g_wa_l[cL * cD * cD3];
__device__ __nv_bfloat16 g_wp_h[cL * cD * cD],  g_wp_l[cL * cD * cD];
__device__ __nv_bfloat16 g_wf_h[cL * cD * cDF], g_wf_l[cL * cD * cDF];
__device__ __nv_bfloat16 g_wo_h[cL * cDF * cD], g_wo_l[cL * cDF * cD];
__device__ __nv_bfloat16 g_wh_h[cD * cV],       g_wh_l[cD * cV];

// ---------------------------------------------------------------------------
// PTX helpers
// ---------------------------------------------------------------------------
__device__ __forceinline__ void cp_async16(uint32_t saddr, const void* gptr) {
    asm volatile("cp.async.cg.shared.global [%0], [%1], 16;"
                 :: "r"(saddr), "l"(gptr));
}
#define CP_COMMIT() asm volatile("cp.async.commit_group;" ::: "memory")
#define CP_WAIT0()  asm volatile("cp.async.wait_group 0;" ::: "memory")
#define CP_WAIT1()  asm volatile("cp.async.wait_group 1;" ::: "memory")

__device__ __forceinline__ void ldsm_x4(uint32_t* r, uint32_t addr) {
    asm volatile("ldmatrix.sync.aligned.m8n8.x4.shared.b16 {%0,%1,%2,%3}, [%4];"
        : "=r"(r[0]), "=r"(r[1]), "=r"(r[2]), "=r"(r[3]) : "r"(addr));
}
__device__ __forceinline__ void ldsm_x4_t(uint32_t* r, uint32_t addr) {
    asm volatile("ldmatrix.sync.aligned.m8n8.x4.trans.shared.b16 {%0,%1,%2,%3}, [%4];"
        : "=r"(r[0]), "=r"(r[1]), "=r"(r[2]), "=r"(r[3]) : "r"(addr));
}
__device__ __forceinline__ void mma_bf16(float* d, const uint32_t* a,
                                         uint32_t b0, uint32_t b1) {
    asm volatile(
        "mma.sync.aligned.m16n8k16.row.col.f32.bf16.bf16.f32 "
        "{%0,%1,%2,%3},{%4,%5,%6,%7},{%8,%9},{%0,%1,%2,%3};"
        : "+f"(d[0]), "+f"(d[1]), "+f"(d[2]), "+f"(d[3])
        : "r"(a[0]), "r"(a[1]), "r"(a[2]), "r"(a[3]), "r"(b0), "r"(b1));
}

__device__ __forceinline__ uint32_t pack_bf16x2(float lo, float hi) {
    uint32_t d;
    asm("cvt.rn.bf16x2.f32 %0, %1, %2;" : "=r"(d) : "f"(hi), "f"(lo));
    return d;
}
__device__ __forceinline__ void split2(float v0, float v1,
                                       uint32_t& hp, uint32_t& lp) {
    hp = pack_bf16x2(v0, v1);
    float h0 = __uint_as_float(hp << 16);
    float h1 = __uint_as_float(hp & 0xffff0000u);
    lp = pack_bf16x2(v0 - h0, v1 - h1);
}

__device__ __forceinline__ float gelu_exact(float x) {
    return 0.5f * x * (1.0f + erff(x * 0.70710678118654752f));
}

// ---------------------------------------------------------------------------
// Generalized split-bf16 GEMM (3-mma Markidis): C = A @ W(op)
// 3-stage cp.async pipeline, ONE __syncthreads per k-iteration.
// mma stream interleaved product-major across 4 accumulators (no RAW chains).
// ---------------------------------------------------------------------------
template<int NT, bool BTRANS>
struct Geom {
    static constexpr int SBb = BTRANS ? (2 * NT + 16) : 80;
    static constexpr int BSZ = BTRANS ? 32 * SBb : NT * 80;
    static constexpr int AL  = 10240;
    static constexpr int BH  = 20480;
    static constexpr int BL  = BH + BSZ;
    static constexpr int BUF = BH + 2 * BSZ;
    static constexpr int SMEM = 3 * BUF;          // 3 stages
};

template<int NT, bool BTRANS, bool BIAS, bool RES, bool GELU,
         bool WC, bool WPL, int ZMODE, bool SWAPXY>
__global__ void __launch_bounds__(256, 2) gemm_u(
    const __nv_bfloat16* __restrict__ Ah, const __nv_bfloat16* __restrict__ Al,
    const __nv_bfloat16* __restrict__ Wh, const __nv_bfloat16* __restrict__ Wl,
    const float* __restrict__ bias, const float* __restrict__ Rres,
    float* __restrict__ C,
    __nv_bfloat16* __restrict__ Ch, __nv_bfloat16* __restrict__ Cl,
    __nv_bfloat16* __restrict__ Dh, __nv_bfloat16* __restrict__ Dl,
    __nv_bfloat16* __restrict__ Eh, __nv_bfloat16* __restrict__ El,
    int N, int K, int ldc, size_t sA, size_t sW, size_t sC) {

    using G = Geom<NT, BTRANS>;
    extern __shared__ char smem[];
    const uint32_t sb = (uint32_t)__cvta_generic_to_shared(smem);

    const int m0 = (SWAPXY ? blockIdx.x : blockIdx.y) * 128;
    const int n0 = (SWAPXY ? blockIdx.y : blockIdx.x) * NT;

    const int z = blockIdx.z;
    Ah += z * sA; Al += z * sA;
    Wh += z * sW; Wl += z * sW;
    const size_t cofs = z * sC;

    const int tid  = threadIdx.x;
    const int lane = tid & 31;
    const int wid  = tid >> 5;
    const int gr   = lane >> 2;
    const int tg   = lane & 3;
    const int mw   = (wid & 3) * 32;
    const int nw   = (wid >> 2) * (NT / 2);
    const int lr   = lane & 7, lt = lane >> 3;

    const uint32_t aoff = (uint32_t)((mw + (lt & 1) * 8 + lr) * 80 + (lt >> 1) * 16);
    uint32_t boff;
    if (BTRANS) boff = (uint32_t)(((lt & 1) * 8 + lr) * G::SBb + (nw + (lt >> 1) * 8) * 2);
    else        boff = (uint32_t)((nw + (lt >> 1) * 8 + lr) * 80 + (lt & 1) * 16);

    constexpr int NTW = NT / 16;
    float acc[2][NTW][4];
    #pragma unroll
    for (int mi = 0; mi < 2; mi++)
        #pragma unroll
        for (int nt = 0; nt < NTW; nt++)
            #pragma unroll
            for (int q = 0; q < 4; q++) acc[mi][nt][q] = 0.0f;

    const int NK = K >> 5;

    auto stage = [&](int ib, int buf) {
        const int k0 = ib << 5;
        const uint32_t bb = sb + buf * G::BUF;
        #pragma unroll
        for (int j = 0; j < 2; j++) {
            int c = tid + 256 * j;
            int row = c >> 2, seg = c & 3;
            uint32_t d = bb + (uint32_t)(row * 80 + seg * 16);
            size_t s = (size_t)(m0 + row) * K + k0 + seg * 8;
            cp_async16(d, Ah + s);
            cp_async16(d + G::AL, Al + s);
        }
        if (BTRANS) {
            constexpr int SEGS = NT / 8;
            constexpr int BCH = 32 * SEGS;
            #pragma unroll
            for (int j = 0; j < (BCH + 255) / 256; j++) {
                int c = tid + 256 * j;
                if ((BCH % 256 == 0) || c < BCH) {
                    int kr = c / SEGS, seg = c - kr * SEGS;
                    uint32_t d = bb + G::BH + (uint32_t)(kr * G::SBb + seg * 16);
                    size_t s = (size_t)(k0 + kr) * N + n0 + seg * 8;
                    cp_async16(d, Wh + s);
                    cp_async16(d + G::BSZ, Wl + s);
                }
            }
        } else {
            constexpr int BCH = NT * 4;
            #pragma unroll
            for (int j = 0; j < (BCH + 255) / 256; j++) {
                int c = tid + 256 * j;
                if ((BCH % 256 == 0) || c < BCH) {
                    int row = c >> 2, seg = c & 3;
                    uint32_t d = bb + G::BH + (uint32_t)(row * 80 + seg * 16);
                    size_t s = (size_t)(n0 + row) * K + k0 + seg * 8;
                    cp_async16(d, Wh + s);
                    cp_async16(d + G::BSZ, Wl + s);
                }
            }
        }
    };

    stage(0, 0); CP_COMMIT();
    stage(1, 1); CP_COMMIT();

    for (int ib = 0; ib < NK; ib++) {
        const int buf = ib % 3;
        CP_WAIT1();
        __syncthreads();

        const uint32_t base = sb + buf * G::BUF;
        const uint32_t aHb = base + aoff;
        const uint32_t aLb = base + G::AL + aoff;
        const uint32_t bHb = base + G::BH + boff;
        const uint32_t bLb = base + G::BL + boff;

        #pragma unroll
        for (int ks = 0; ks < 2; ks++) {
            uint32_t ahi[2][4], alo[2][4];
            ldsm_x4(ahi[0], aHb + ks * 32);
            ldsm_x4(ahi[1], aHb + 1280 + ks * 32);
            ldsm_x4(alo[0], aLb + ks * 32);
            ldsm_x4(alo[1], aLb + 1280 + ks * 32);
            #pragma unroll
            for (int g = 0; g < NT / 32; g++) {
                uint32_t bh[4], bl[4];
                if (BTRANS) {
                    ldsm_x4_t(bh, bHb + ks * (16 * G::SBb) + g * 32);
                    ldsm_x4_t(bl, bLb + ks * (16 * G::SBb) + g * 32);
                } else {
                    ldsm_x4(bh, bHb + ks * 32 + g * 1280);
                    ldsm_x4(bl, bLb + ks * 32 + g * 1280);
                }
                const int nt = g * 2;
                // product-major interleave: same-acc reuse distance = 4 mmas.
                // Per-acc FP order unchanged: (ahi,bh) then (ahi,bl) then (alo,bh).
                mma_bf16(acc[0][nt],     ahi[0], bh[0], bh[1]);
                mma_bf16(acc[1][nt],     ahi[1], bh[0], bh[1]);
                mma_bf16(acc[0][nt + 1], ahi[0], bh[2], bh[3]);
                mma_bf16(acc[1][nt + 1], ahi[1], bh[2], bh[3]);
                mma_bf16(acc[0][nt],     ahi[0], bl[0], bl[1]);
                mma_bf16(acc[1][nt],     ahi[1], bl[0], bl[1]);
                mma_bf16(acc[0][nt + 1], ahi[0], bl[2], bl[3]);
                mma_bf16(acc[1][nt + 1], ahi[1], bl[2], bl[3]);
                mma_bf16(acc[0][nt],     alo[0], bh[0], bh[1]);
                mma_bf16(acc[1][nt],     alo[1], bh[0], bh[1]);
                mma_bf16(acc[0][nt + 1], alo[0], bh[2], bh[3]);
                mma_bf16(acc[1][nt + 1], alo[1], bh[2], bh[3]);
            }
        }
        // Safe without a second barrier: buffer (ib+2)%3 was consumed in
        // iteration ib-1; every warp passed this iteration's __syncthreads.
        if (ib + 2 < NK) stage(ib + 2, (ib + 2) % 3);
        CP_COMMIT();
    }

    #pragma unroll
    for (int mi = 0; mi < 2; mi++) {
        const int r0 = m0 + mw + mi * 16 + gr;
        #pragma unroll
        for (int nt = 0; nt < NTW; nt++) {
            const int c0 = n0 + nw + nt * 8 + tg * 2;
            float2 v0 = make_float2(acc[mi][nt][0], acc[mi][nt][1]);
            float2 v1 = make_float2(acc[mi][nt][2], acc[mi][nt][3]);
            if (BIAS) {
                float2 bv = *(const float2*)(bias + c0);
                v0.x += bv.x; v0.y += bv.y;
                v1.x += bv.x; v1.y += bv.y;
            }
            if (GELU) {
                v0.x = gelu_exact(v0.x); v0.y = gelu_exact(v0.y);
                v1.x = gelu_exact(v1.x); v1.y = gelu_exact(v1.y);
            }
            if (ZMODE == 2) {
                const int sec = n0 / cD;
                const int cc  = c0 - sec * cD;
                const int h   = cc >> 6, d = cc & 63;
                const float scale = (sec == 0) ? 0.125f : 1.0f;
                uint32_t* ph = (uint32_t*)(sec == 0 ? Ch : sec == 1 ? Dh : Eh);
                uint32_t* pl = (uint32_t*)(sec == 0 ? Cl : sec == 1 ? Dl : El);
                const int b = r0 >> 10, t0 = r0 & 1023;
                size_t zb = (size_t)(b * cH + h) * 1024;
                size_t oA = (zb + t0)     * 32 + (d >> 1);
                size_t oB = (zb + t0 + 8) * 32 + (d >> 1);
                uint32_t hp, lp;
                split2(v0.x * scale, v0.y * scale, hp, lp);
                ph[oA] = hp; pl[oA] = lp;
                split2(v1.x * scale, v1.y * scale, hp, lp);
                ph[oB] = hp; pl[oB] = lp;
            } else {
                size_t o0 = cofs + (size_t)r0 * ldc + c0;
                size_t o1 = cofs + (size_t)(r0 + 8) * ldc + c0;
                if (RES) {
                    float2 a0 = *(const float2*)(Rres + o0);
                    float2 a1 = *(const float2*)(Rres + o1);
                    v0.x += a0.x; v0.y += a0.y;
                    v1.x += a1.x; v1.y += a1.y;
                }
                if (WC) {
                    *(float2*)(C + o0) = v0;
                    *(float2*)(C + o1) = v1;
                }
                if (WPL) {
                    uint32_t hp, lp;
                    split2(v0.x, v0.y, hp, lp);
                    ((uint32_t*)Ch)[o0 >> 1] = hp;
                    ((uint32_t*)Cl)[o0 >> 1] = lp;
                    split2(v1.x, v1.y, hp, lp);
                    ((uint32_t*)Ch)[o1 >> 1] = hp;
                    ((uint32_t*)Cl)[o1 >> 1] = lp;
                }
            }
        }
    }
}

// ---------------------------------------------------------------------------
// Fused flash attention (split-bf16 mma, online softmax)
// ---------------------------------------------------------------------------
constexpr int F_SQ   = 144;
constexpr int F_PL   = 128 * F_SQ;
constexpr int F_KV0  = 2 * F_PL;
constexpr int F_KVSZ = 4 * F_PL;
constexpr int FLASH_SMEM = 2 * F_PL + 2 * F_KVSZ;  // 184320

__global__ void __launch_bounds__(256, 1) flash_kernel(
    const __nv_bfloat16* __restrict__ qh, const __nv_bfloat16* __restrict__ ql,
    const __nv_bfloat16* __restrict__ kh, const __nv_bfloat16* __restrict__ kl,
    const __nv_bfloat16* __restrict__ vh, const __nv_bfloat16* __restrict__ vl,
    __nv_bfloat16* __restrict__ yh, __nv_bfloat16* __restrict__ yl) {

    extern __shared__ char smem[];
    const uint32_t sb = (uint32_t)__cvta_generic_to_shared(smem);
    const int qb = blockIdx.x;
    const int z  = blockIdx.y;
    const int q0 = qb * 128;
    const int tid  = threadIdx.x;
    const int lane = tid & 31;
    const int wid  = tid >> 5;
    const int gr   = lane >> 2;
    const int tg   = lane & 3;
    const int wq   = wid * 16;
    const int lr   = lane & 7, lt = lane >> 3;

    const __nv_bfloat16* qhz = qh + (size_t)z * cQH;
    const __nv_bfloat16* qlz = ql + (size_t)z * cQH;
    const __nv_bfloat16* khz = kh + (size_t)z * cQH;
    const __nv_bfloat16* klz = kl + (size_t)z * cQH;
    const __nv_bfloat16* vhz = vh + (size_t)z * cQH;
    const __nv_bfloat16* vlz = vl + (size_t)z * cQH;

    #pragma unroll
    for (int j = 0; j < 4; j++) {
        int c = tid + 256 * j;
        int row = c >> 3, seg = c & 7;
        uint32_t d = sb + (uint32_t)(row * F_SQ + seg * 16);
        size_t s = (size_t)(q0 + row) * cHD + seg * 8;
        cp_async16(d, qhz + s);
        cp_async16(d + F_PL, qlz + s);
    }
    auto stageKV = [&](int kb, int buf) {
        const uint32_t bb = sb + F_KV0 + buf * F_KVSZ;
        #pragma unroll
        for (int j = 0; j < 4; j++) {
            int c = tid + 256 * j;
            int row = c >> 3, seg = c & 7;
            uint32_t d = bb + (uint32_t)(row * F_SQ + seg * 16);
            size_t s = (size_t)(kb * 128 + row) * cHD + seg * 8;
            cp_async16(d, khz + s);
            cp_async16(d + F_PL, klz + s);
            cp_async16(d + 2 * F_PL, vhz + s);
            cp_async16(d + 3 * F_PL, vlz + s);
        }
    };

    stageKV(0, 0);
    CP_COMMIT();
    if (qb >= 1) { stageKV(1, 1); CP_COMMIT(); }

    float mrow[2] = { -INFINITY, -INFINITY };
    float lrow[2] = { 0.0f, 0.0f };
    float oacc[8][4];
    #pragma unroll
    for (int nt = 0; nt < 8; nt++)
        #pragma unroll
        for (int q = 0; q < 4; q++) oacc[nt][q] = 0.0f;

    uint32_t qfh[4][4], qfl[4][4];
    bool qloaded = false;

    const uint32_t q_aoff = (uint32_t)((wq + (lt & 1) * 8 + lr) * F_SQ + (lt >> 1) * 16);
    const uint32_t k_boff = (uint32_t)(((lt >> 1) * 8 + lr) * F_SQ + (lt & 1) * 16);
    const uint32_t v_boff = (uint32_t)(((lt & 1) * 8 + lr) * F_SQ + (lt >> 1) * 16);

    for (int kb = 0; kb <= qb; kb++) {
        if (kb < qb) { CP_WAIT1(); } else { CP_WAIT0(); }
        __syncthreads();

        if (!qloaded) {
            #pragma unroll
            for (int ks = 0; ks < 4; ks++) {
                ldsm_x4(qfh[ks], sb + q_aoff + ks * 32);
                ldsm_x4(qfl[ks], sb + F_PL + q_aoff + ks * 32);
            }
            qloaded = true;
        }

        const uint32_t kvb = sb + F_KV0 + (kb & 1) * F_KVSZ;

        float s[16][4];
        #pragma unroll
        for (int nt = 0; nt < 16; nt++)
            #pragma unroll
            for (int q = 0; q < 4; q++) s[nt][q] = 0.0f;

        #pragma unroll
        for (int ks = 0; ks < 4; ks++) {
            #pragma unroll
            for (int g = 0; g < 8; g++) {
                uint32_t bh[4], bl[4];
                uint32_t addr = kvb + k_boff + (uint32_t)(g * 16 * F_SQ) + ks * 32;
                ldsm_x4(bh, addr);
                ldsm_x4(bl, addr + F_PL);
                const int nt = g * 2;
                // interleaved: same-acc spacing 2
                mma_bf16(s[nt],     qfh[ks], bh[0], bh[1]);
                mma_bf16(s[nt + 1], qfh[ks], bh[2], bh[3]);
                mma_bf16(s[nt],     qfh[ks], bl[0], bl[1]);
                mma_bf16(s[nt + 1], qfh[ks], bl[2], bl[3]);
                mma_bf16(s[nt],     qfl[ks], bh[0], bh[1]);
                mma_bf16(s[nt + 1], qfl[ks], bh[2], bh[3]);
            }
        }

        if (kb == qb) {
            const int r0 = wq + gr, r1 = wq + gr + 8;
            #pragma unroll
            for (int nt = 0; nt < 16; nt++) {
                const int c0 = nt * 8 + tg * 2;
                if (c0     > r0) s[nt][0] = -1e30f;
                if (c0 + 1 > r0) s[nt][1] = -1e30f;
                if (c0     > r1) s[nt][2] = -1e30f;
                if (c0 + 1 > r1) s[nt][3] = -1e30f;
            }
        }

        float mn0 = -INFINITY, mn1 = -INFINITY;
        #pragma unroll
        for (int nt = 0; nt < 16; nt++) {
            mn0 = fmaxf(mn0, fmaxf(s[nt][0], s[nt][1]));
            mn1 = fmaxf(mn1, fmaxf(s[nt][2], s[nt][3]));
        }
        mn0 = fmaxf(mn0, __shfl_xor_sync(0xffffffffu, mn0, 1));
        mn0 = fmaxf(mn0, __shfl_xor_sync(0xffffffffu, mn0, 2));
        mn1 = fmaxf(mn1, __shfl_xor_sync(0xffffffffu, mn1, 1));
        mn1 = fmaxf(mn1, __shfl_xor_sync(0xffffffffu, mn1, 2));
        float mnew0 = fmaxf(mrow[0], mn0);
        float mnew1 = fmaxf(mrow[1], mn1);
        float al0 = __expf(mrow[0] - mnew0);
        float al1 = __expf(mrow[1] - mnew1);
        mrow[0] = mnew0; mrow[1] = mnew1;

        float rs0 = 0.0f, rs1 = 0.0f;
        #pragma unroll
        for (int nt = 0; nt < 16; nt++) {
            s[nt][0] = __expf(s[nt][0] - mnew0);
            s[nt][1] = __expf(s[nt][1] - mnew0);
            s[nt][2] = __expf(s[nt][2] - mnew1);
            s[nt][3] = __expf(s[nt][3] - mnew1);
            rs0 += s[nt][0] + s[nt][1];
            rs1 += s[nt][2] + s[nt][3];
        }
        rs0 += __shfl_xor_sync(0xffffffffu, rs0, 1);
        rs0 += __shfl_xor_sync(0xffffffffu, rs0, 2);
        rs1 += __shfl_xor_sync(0xffffffffu, rs1, 1);
        rs1 += __shfl_xor_sync(0xffffffffu, rs1, 2);
        lrow[0] = lrow[0] * al0 + rs0;
        lrow[1] = lrow[1] * al1 + rs1;

        #pragma unroll
        for (int nt = 0; nt < 8; nt++) {
            oacc[nt][0] *= al0; oacc[nt][1] *= al0;
            oacc[nt][2] *= al1; oacc[nt][3] *= al1;
        }

        #pragma unroll
        for (int ks = 0; ks < 8; ks++) {
            uint32_t pah[4], pal[4];
            uint32_t h0, l0;
            split2(s[2*ks][0],   s[2*ks][1],   h0, l0); pah[0] = h0; pal[0] = l0;
            split2(s[2*ks][2],   s[2*ks][3],   h0, l0); pah[1] = h0; pal[1] = l0;
            split2(s[2*ks+1][0], s[2*ks+1][1], h0, l0); pah[2] = h0; pal[2] = l0;
            split2(s[2*ks+1][2], s[2*ks+1][3], h0, l0); pah[3] = h0; pal[3] = l0;
            #pragma unroll
            for (int g = 0; g < 4; g++) {
                uint32_t bvh[4], bvl[4];
                uint32_t addr = kvb + 2 * F_PL + v_boff
                              + (uint32_t)(ks * 16 * F_SQ) + g * 32;
                ldsm_x4_t(bvh, addr);
                ldsm_x4_t(bvl, addr + F_PL);
                const int nt = g * 2;
                // interleaved: same-acc spacing 2
                mma_bf16(oacc[nt],     pah, bvh[0], bvh[1]);
                mma_bf16(oacc[nt + 1], pah, bvh[2], bvh[3]);
                mma_bf16(oacc[nt],     pah, bvl[0], bvl[1]);
                mma_bf16(oacc[nt + 1], pah, bvl[2], bvl[3]);
                mma_bf16(oacc[nt],     pal, bvh[0], bvh[1]);
                mma_bf16(oacc[nt + 1], pal, bvh[2], bvh[3]);
            }
        }

        __syncthreads();
        if (kb + 2 <= qb) { stageKV(kb + 2, kb & 1); CP_COMMIT(); }
    }

    const float inv0 = 1.0f / lrow[0];
    const float inv1 = 1.0f / lrow[1];
    const int b = z / cH, h = z % cH;
    const int r0 = b * cT + q0 + wq + gr;
    #pragma unroll
    for (int nt = 0; nt < 8; nt++) {
        const int c0 = h * cHD + nt * 8 + tg * 2;
        uint32_t hp, lp;
        split2(oacc[nt][0] * inv0, oacc[nt][1] * inv0, hp, lp);
        size_t o0 = ((size_t)r0 * cD + c0) >> 1;
        ((uint32_t*)yh)[o0] = hp; ((uint32_t*)yl)[o0] = lp;
        split2(oacc[nt][2] * inv1, oacc[nt][3] * inv1, hp, lp);
        size_t o1 = ((size_t)(r0 + 8) * cD + c0) >> 1;
        ((uint32_t*)yh)[o1] = hp; ((uint32_t*)yl)[o1] = lp;
    }
}

// ---------------------------------------------------------------------------
// Block reductions (blockDim.x == 256)
// ---------------------------------------------------------------------------
__device__ __forceinline__ float blockReduceSum(float v) {
    __shared__ float sh[8];
    #pragma unroll
    for (int o = 16; o; o >>= 1) v += __shfl_xor_sync(0xffffffffu, v, o);
    int w = threadIdx.x >> 5, l = threadIdx.x & 31;
    __syncthreads();
    if (l == 0) sh[w] = v;
    __syncthreads();
    if (w == 0) {
        v = (l < 8) ? sh[l] : 0.0f;
        #pragma unroll
        for (int o = 16; o; o >>= 1) v += __shfl_xor_sync(0xffffffffu, v, o);
        if (l == 0) sh[0] = v;
    }
    __syncthreads();
    return sh[0];
}

__device__ __forceinline__ float blockReduceMax(float v) {
    __shared__ float sh[8];
    #pragma unroll
    for (int o = 16; o; o >>= 1) v = fmaxf(v, __shfl_xor_sync(0xffffffffu, v, o));
    int w = threadIdx.x >> 5, l = threadIdx.x & 31;
    __syncthreads();
    if (l == 0) sh[w] = v;
    __syncthreads();
    if (w == 0) {
        v = (l < 8) ? sh[l] : -INFINITY;
        #pragma unroll
        for (int o = 16; o; o >>= 1) v = fmaxf(v, __shfl_xor_sync(0xffffffffu, v, o));
        if (l == 0) sh[0] = v;
    }
    __syncthreads();
    return sh[0];
}

// ---------------------------------------------------------------------------
// Small kernels
// ---------------------------------------------------------------------------
__global__ void __launch_bounds__(256) split_kernel(const float* __restrict__ src,
                                                    __nv_bfloat16* __restrict__ hi,
                                                    __nv_bfloat16* __restrict__ lo,
                                                    int nquads) {
    int i = blockIdx.x * blockDim.x + threadIdx.x;
    if (i >= nquads) return;
    float4 v = *(const float4*)(src + (size_t)i * 4);
    uint32_t h0, l0, h1, l1;
    split2(v.x, v.y, h0, l0);
    split2(v.z, v.w, h1, l1);
    ((uint2*)hi)[i] = make_uint2(h0, h1);
    ((uint2*)lo)[i] = make_uint2(l0, l1);
}

__global__ void embed_kernel(const int* __restrict__ idx,
                             const float* __restrict__ wte,
                             const float* __restrict__ wpe,
                             float* __restrict__ x) {
    int i = blockIdx.x * blockDim.x + threadIdx.x;
    int row = i / cD;
    int d   = i - row * cD;
    int t   = row & (cT - 1);
    int tok = idx[row];
    x[i] = wte[(size_t)tok * cD + d] + wpe[(size_t)t * cD + d];
}

__global__ void __launch_bounds__(256) ln_kernel(const float* __restrict__ x,
                                                 const float* __restrict__ g,
                                                 const float* __restrict__ b,
                                                 __nv_bfloat16* __restrict__ oh,
                                                 __nv_bfloat16* __restrict__ ol) {
    const int row = blockIdx.x;
    const float* xr = x + (size_t)row * cD;
    const int t = threadIdx.x;
    float v0 = xr[t], v1 = xr[t + 256], v2 = xr[t + 512];
    float s  = blockReduceSum(v0 + v1 + v2);
    float s2 = blockReduceSum(v0 * v0 + v1 * v1 + v2 * v2);
    const float inv = 1.0f / cD;
    float mu  = s * inv;
    float var = s2 * inv - mu * mu;
    float rs  = rsqrtf(var + 1e-5f);
    #pragma unroll
    for (int j = 0; j < 3; j++) {
        int d = t + j * 256;
        float val = (((j == 0) ? v0 : (j == 1) ? v1 : v2) - mu) * rs * g[d] + b[d];
        __nv_bfloat16 h = __float2bfloat16_rn(val);
        oh[(size_t)row * cD + d] = h;
        ol[(size_t)row * cD + d] = __float2bfloat16_rn(val - __bfloat162float(h));
    }
}

// single-pass online log-sum-exp loss per row
__global__ void __launch_bounds__(256) loss_row_kernel(const float* __restrict__ logits,
                                                       const int* __restrict__ tgt,
                                                       float* __restrict__ nll) {
    const int r = blockIdx.x;
    const float* lr = logits + (size_t)r * cV;
    float m = -INFINITY, s = 0.0f;
    for (int i = threadIdx.x; i < cV; i += 256) {
        float v = lr[i];
        float nm = fmaxf(m, v);
        s = s * __expf(m - nm) + __expf(v - nm);
        m = nm;
    }
    float mx = blockReduceMax(m);
    float sadj = s * __expf(m - mx);
    float tot = blockReduceSum(sadj);
    if (threadIdx.x == 0)
        nll[r] = -(lr[tgt[r]] - mx - logf(tot));
}

__global__ void __launch_bounds__(256) loss_reduce_kernel(const float* __restrict__ nll,
                                                          float* __restrict__ out) {
    float s = 0.0f;
    for (int i = threadIdx.x; i < cM; i += 256) s += nll[i];
    s = blockReduceSum(s);
    if (threadIdx.x == 0) *out = s / (float)cM;
}

// ---------------------------------------------------------------------------
// Launch
// ---------------------------------------------------------------------------
template<typename T> static T* sym(const void* s) {
    void* p; cudaGetSymbolAddress(&p, s); return (T*)p;
}

using bf16 = __nv_bfloat16;

//               NT  BT    BIAS  RES   GELU  WC    WPL   ZM SWAP
#define GQKV  gemm_u<128,true ,false,false,false,false,false,2,false>
#define GHEAD gemm_u<128,true ,false,false,false,true ,false,0,true >
#define GPROJ gemm_u<96 ,true ,false,true ,false,true ,false,0,false>
#define GFC   gemm_u<128,true ,true ,false,true ,false,true ,0,false>
#define GOUT  gemm_u<96 ,true ,true ,true ,false,true ,false,0,false>

extern "C" void kernel_launch(void* const* d_in, const int* in_sizes, int n_in,
                              void* d_out, int out_size) {
    const int*   idx    = (const int*)  d_in[0];
    const int*   tgt    = (const int*)  d_in[1];
    const float* wte    = (const float*)d_in[2];
    const float* wpe    = (const float*)d_in[3];
    const float* ln1_g  = (const float*)d_in[4];
    const float* ln1_b  = (const float*)d_in[5];
    const float* w_attn = (const float*)d_in[6];
    const float* w_proj = (const float*)d_in[7];
    const float* ln2_g  = (const float*)d_in[8];
    const float* ln2_b  = (const float*)d_in[9];
    const float* w_fc   = (const float*)d_in[10];
    const float* b_fc   = (const float*)d_in[11];
    const float* w_out  = (const float*)d_in[12];
    const float* b_out  = (const float*)d_in[13];
    const float* lnf_g  = (const float*)d_in[14];
    const float* lnf_b  = (const float*)d_in[15];
    const float* w_head = (const float*)d_in[16];
    float* logits = (float*)d_out;

    float* x   = sym<float>(g_x);
    float* nll = sym<float>(g_nll);
    bf16 *lnh = sym<bf16>(g_ln_h), *lnl = sym<bf16>(g_ln_l);
    bf16 *yh  = sym<bf16>(g_y_h),  *yl  = sym<bf16>(g_y_l);
    bf16 *fch = sym<bf16>(g_fc_h), *fcl = sym<bf16>(g_fc_l);
    bf16 *qh  = sym<bf16>(g_q_h),  *ql  = sym<bf16>(g_q_l);
    bf16 *kh  = sym<bf16>(g_k_h),  *kl  = sym<bf16>(g_k_l);
    bf16 *vh  = sym<bf16>(g_v_h),  *vl  = sym<bf16>(g_v_l);
    bf16 *wah = sym<bf16>(g_wa_h), *wal = sym<bf16>(g_wa_l);
    bf16 *wph = sym<bf16>(g_wp_h), *wpl = sym<bf16>(g_wp_l);
    bf16 *wfh = sym<bf16>(g_wf_h), *wfl = sym<bf16>(g_wf_l);
    bf16 *woh = sym<bf16>(g_wo_h), *wol = sym<bf16>(g_wo_l);
    bf16 *whh = sym<bf16>(g_wh_h), *whl = sym<bf16>(g_wh_l);

    constexpr int SM128T = Geom<128, true>::SMEM;  // 113664
    constexpr int SM96T  = Geom<96,  true>::SMEM;  // 101376

    cudaFuncSetAttribute((const void*)GQKV,  cudaFuncAttributeMaxDynamicSharedMemorySize, SM128T);
    cudaFuncSetAttribute((const void*)GHEAD, cudaFuncAttributeMaxDynamicSharedMemorySize, SM128T);
    cudaFuncSetAttribute((const void*)GPROJ, cudaFuncAttributeMaxDynamicSharedMemorySize, SM96T);
    cudaFuncSetAttribute((const void*)GFC,   cudaFuncAttributeMaxDynamicSharedMemorySize, SM128T);
    cudaFuncSetAttribute((const void*)GOUT,  cudaFuncAttributeMaxDynamicSharedMemorySize, SM96T);
    cudaFuncSetAttribute((const void*)flash_kernel,
                         cudaFuncAttributeMaxDynamicSharedMemorySize, FLASH_SMEM);

    split_kernel<<<cL * cD * cD3 / 1024, 256>>>(w_attn, wah, wal, cL * cD * cD3 / 4);
    split_kernel<<<cL * cD * cD  / 1024, 256>>>(w_proj, wph, wpl, cL * cD * cD  / 4);
    split_kernel<<<cL * cD * cDF / 1024, 256>>>(w_fc,   wfh, wfl, cL * cD * cDF / 4);
    split_kernel<<<cL * cDF * cD / 1024, 256>>>(w_out,  woh, wol, cL * cDF * cD / 4);
    split_kernel<<<cD * cV       / 1024, 256>>>(w_head, whh, whl, cD * cV       / 4);

    embed_kernel<<<(cM * cD) / 256, 256>>>(idx, wte, wpe, x);

    for (int l = 0; l < cL; l++) {
        ln_kernel<<<cM, 256>>>(x, ln1_g + l * cD, ln1_b + l * cD, lnh, lnl);
        GQKV<<<dim3(cD3 / 128, cM / 128, 1), 256, SM128T>>>(
            lnh, lnl, wah + (size_t)l * cD * cD3, wal + (size_t)l * cD * cD3,
            nullptr, nullptr, nullptr, qh, ql, kh, kl, vh, vl, cD3, cD, cD3, 0, 0, 0);
        flash_kernel<<<dim3(cT / 128, cZ), 256, FLASH_SMEM>>>(
            qh, ql, kh, kl, vh, vl, yh, yl);
        GPROJ<<<dim3(cD / 96, cM / 128, 1), 256, SM96T>>>(
            yh, yl, wph + (size_t)l * cD * cD, wpl + (size_t)l * cD * cD,
            nullptr, x, x, nullptr, nullptr, nullptr, nullptr, nullptr, nullptr,
            cD, cD, cD, 0, 0, 0);
        ln_kernel<<<cM, 256>>>(x, ln2_g + l * cD, ln2_b + l * cD, lnh, lnl);
        GFC<<<dim3(cDF / 128, cM / 128, 1), 256, SM128T>>>(
            lnh, lnl, wfh + (size_t)l * cD * cDF, wfl + (size_t)l * cD * cDF,
            b_fc + l * cDF, nullptr, nullptr, fch, fcl, nullptr, nullptr, nullptr, nullptr,
            cDF, cD, cDF, 0, 0, 0);
        GOUT<<<dim3(cD / 96, cM / 128, 1), 256, SM96T>>>(
            fch, fcl, woh + (size_t)l * cDF * cD, wol + (size_t)l * cDF * cD,
            b_out + l * cD, x, x, nullptr, nullptr, nullptr, nullptr, nullptr, nullptr,
            cD, cDF, cD, 0, 0, 0);
    }

    ln_kernel<<<cM, 256>>>(x, lnf_g, lnf_b, lnh, lnl);
    GHEAD<<<dim3(cM / 128, cV / 128, 1), 256, SM128T>>>(
        lnh, lnl, whh, whl, nullptr, nullptr, logits, nullptr, nullptr,
        nullptr, nullptr, nullptr, nullptr, cV, cD, cV, 0, 0, 0);

    if (out_size >= cM * cV + 1) {
        loss_row_kernel<<<cM, 256>>>(logits, tgt, nll);
        loss_reduce_kernel<<<1, 256>>>(nll, logits + (size_t)cM * cV);
    }
}